// round 10
// baseline (speedup 1.0000x reference)
#include <cuda_runtime.h>
#include <cuda_fp16.h>
#include <math.h>
#include <cstdint>

// Problem constants
#define BB    32
#define CC    12
#define HH_   64
#define WW_   64
#define HW_   4096
#define HID   128
#define CONDC 4
#define OUTS  276          // 12 * 23
#define NB    8
#define TAILF 3.0f
#define MBWF  0.001f
#define MBHF  0.001f
#define MDF   0.001f
#define NTOT  (BB*CC*HW_)  // 1572864
#define PERB  (CC*HW_)     // 49152
#define PAREA (66*64)      // padded channel area (66 rows x 64 cols)
#define PBLK  192          // rqs partial-sum blocks per batch (PERB/256)

// ---------------- scratch (no cudaMalloc allowed) ----------------
__device__ __half g_pad1[(size_t)3*BB*16*PAREA];     // 13 MB
__device__ __half g_h1h[(size_t)BB*HID*HW_];          // 33 MB
__device__ __half g_pad3[(size_t)3*BB*HID*PAREA];    // 104 MB
__device__ __half g_w1h[128 * 192];
__device__ __half g_w2h[128 * 128];
__device__ __half g_w3h[384 * 1152];
__device__ float  g_params[(size_t)BB*OUTS*HW_];      // 144 MB
__device__ double g_psum[BB * PBLK];

// ---------------- helpers ----------------
__device__ __forceinline__ uint32_t smem_u32(const void* p) {
    uint32_t a;
    asm("{ .reg .u64 t; cvta.to.shared.u64 t, %1; cvt.u32.u64 %0, t; }" : "=r"(a) : "l"(p));
    return a;
}
__device__ __forceinline__ void cp_async16(uint32_t dst, const void* src) {
    asm volatile("cp.async.cg.shared.global [%0], [%1], 16;"
                 :: "r"(dst), "l"(src) : "memory");
}
__device__ __forceinline__ void cp_commit() {
    asm volatile("cp.async.commit_group;" ::: "memory");
}
template<int N>
__device__ __forceinline__ void cp_wait() {
    asm volatile("cp.async.wait_group %0;" :: "n"(N) : "memory");
}
__device__ __forceinline__ void ldsm_x4(uint32_t r[4], uint32_t addr) {
    asm volatile("ldmatrix.sync.aligned.m8n8.x4.shared.b16 {%0,%1,%2,%3}, [%4];"
        : "=r"(r[0]), "=r"(r[1]), "=r"(r[2]), "=r"(r[3]) : "r"(addr));
}
__device__ __forceinline__ void ldsm_x4t(uint32_t r[4], uint32_t addr) {
    asm volatile("ldmatrix.sync.aligned.m8n8.x4.trans.shared.b16 {%0,%1,%2,%3}, [%4];"
        : "=r"(r[0]), "=r"(r[1]), "=r"(r[2]), "=r"(r[3]) : "r"(addr));
}
__device__ __forceinline__ void mma_f16(float c[4], const uint32_t a[4],
                                        uint32_t b0, uint32_t b1) {
    asm volatile(
        "mma.sync.aligned.m16n8k16.row.col.f32.f16.f16.f32 "
        "{%0,%1,%2,%3}, {%4,%5,%6,%7}, {%8,%9}, {%0,%1,%2,%3};"
        : "+f"(c[0]), "+f"(c[1]), "+f"(c[2]), "+f"(c[3])
        : "r"(a[0]), "r"(a[1]), "r"(a[2]), "r"(a[3]), "r"(b0), "r"(b1));
}

// A tile: 128 rows x 64 k halves (128B rows, 8 granules), granule XORed by (row&7)
// -> each 8-row ldmatrix phase touches 8 distinct granules = all 32 banks.
__device__ __forceinline__ uint32_t a_addr(uint32_t base, int row, int kg) {
    return base + row * 128 + ((kg ^ (row & 7)) << 4);
}
// B tile: 64 k-rows x 128 n halves (256B rows, 16 granules), granule XORed by (krow&7)
__device__ __forceinline__ uint32_t b_addr(uint32_t base, int krow, int g) {
    return base + krow * 256 + ((g ^ (krow & 7)) << 4);
}

#define A_BYTES     (128 * 128)           // 16 KB
#define B_BYTES     (64 * 256)            // 16 KB
#define STAGE_BYTES (A_BYTES + B_BYTES)   // 32 KB
#define NSTG        3
#define CONV_SMEM   (NSTG * STAGE_BYTES)  // 96 KB -> 2 CTAs/SM

// ---------------- weight reorder (tap-major, zero-padded, fp16) ----------------
__global__ void prep_weights(const float* __restrict__ w1, const float* __restrict__ w2,
                             const float* __restrict__ w3) {
    const int N1 = 128 * 192, N2 = 128 * 128, N3 = 384 * 1152;
    int i = blockIdx.x * blockDim.x + threadIdx.x;
    if (i < N1) {
        int oc = i / 192, k = i - oc * 192;
        int t = k >> 4, ch = k & 15;
        g_w1h[i] = __float2half((t < 9) ? w1[oc * 144 + ch * 9 + t] : 0.f);
    } else if (i < N1 + N2) {
        int j = i - N1;
        g_w2h[j] = __float2half(w2[j]);
    } else if (i < N1 + N2 + N3) {
        int j = i - N1 - N2;
        int oc = j / 1152, k = j - oc * 1152;
        int t = k >> 7, ch = k & 127;
        g_w3h[j] = __float2half((oc < OUTS) ? w3[oc * 1152 + ch * 9 + t] : 0.f);
    }
}

// ---------------- padded dw-replicated input builders ----------------
// P[dw][b][ch][r 0..65][w 0..63] = in[ch][r-1][w+dw-1] (0 if OOB)
__global__ void pad1_kernel(const float* __restrict__ x, const float* __restrict__ cond) {
    const int N = 3 * BB * 16 * 66 * 32;
    int i = blockIdx.x * blockDim.x + threadIdx.x;
    if (i >= N) return;
    int w2 = i & 31;           int tmp = i >> 5;
    int r  = tmp % 66;         tmp /= 66;
    int ch = tmp & 15;         tmp >>= 4;
    int b  = tmp & 31;         int dw = tmp >> 5;
    int rr = r - 1;
    const float* src = (ch < CC) ? (x    + ((size_t)b * CC    + ch)        * HW_)
                                 : (cond + ((size_t)b * CONDC + (ch - CC)) * HW_);
    float v0 = 0.f, v1 = 0.f;
    if ((unsigned)rr < 64u) {
        int w = w2 * 2;
        int ww0 = w + dw - 1, ww1 = ww0 + 1;
        if ((unsigned)ww0 < 64u) v0 = src[rr * 64 + ww0];
        if ((unsigned)ww1 < 64u) v1 = src[rr * 64 + ww1];
    }
    __half2* dst = reinterpret_cast<__half2*>(
        g_pad1 + (((size_t)(dw * BB + b) * 16 + ch) * PAREA) + r * 64);
    dst[w2] = __floats2half2_rn(v0, v1);
}

__global__ void pad3_kernel(const __half* __restrict__ h2) {
    const int N = 3 * BB * HID * 66 * 32;
    int i = blockIdx.x * blockDim.x + threadIdx.x;
    if (i >= N) return;
    int w2 = i & 31;           int tmp = i >> 5;
    int r  = tmp % 66;         tmp /= 66;
    int ch = tmp & 127;        tmp >>= 7;
    int b  = tmp & 31;         int dw = tmp >> 5;
    int rr = r - 1;
    const __half* src = h2 + ((size_t)b * HID + ch) * HW_;
    __half z = __ushort_as_half(0);
    __half v0 = z, v1 = z;
    if ((unsigned)rr < 64u) {
        int w = w2 * 2;
        int ww0 = w + dw - 1, ww1 = ww0 + 1;
        if ((unsigned)ww0 < 64u) v0 = src[rr * 64 + ww0];
        if ((unsigned)ww1 < 64u) v1 = src[rr * 64 + ww1];
    }
    __half2* dst = reinterpret_cast<__half2*>(
        g_pad3 + (((size_t)(dw * BB + b) * HID + ch) * PAREA) + r * 64);
    dst[w2] = __halves2half2(v0, v1);
}

// ---------------- fp16 multistage GEMM conv (BK=64, 2 CTAs/SM) ----------------
// CTA: 256 threads (8 warps, 4(M) x 2(N)); tile M=128 x N=128 pixels (2 rows); BK=64.
template<bool PAD3, bool RELU, int COUT, int CIN, int CLOG, int KPAD, bool HALF_OUT>
__global__ __launch_bounds__(256, 2)
void conv_gemm(const __half* __restrict__ in, const __half* __restrict__ wgt,
               const float* __restrict__ bias, void* __restrict__ outp)
{
    constexpr int NC = KPAD / 64;
    extern __shared__ char smemc[];
    const uint32_t stg = smem_u32(smemc);

    const int tid  = threadIdx.x;
    const int lane = tid & 31;
    const int wid  = tid >> 5;
    const int wm   = (wid & 3) * 32;
    const int wn   = (wid >> 2) * 64;

    const int b     = blockIdx.z;
    const int mbase = blockIdx.y * 128;
    const int h0    = blockIdx.x * 2;
    const int pix0  = blockIdx.x * 128;

    // A-loader: 1024 granules, 4/thread (64B contiguous per thread)
    const int a_row0 = tid >> 1;            // 0..127
    const int a_kg0  = (tid & 1) * 4;       // 0 or 4
    // B-loader: krow = tid>>2 (0..63); quarter = tid&3 -> granules q*4..q*4+3 (64B)
    const int b_krow = tid >> 2;
    const int b_q    = tid & 3;
    const int b_orow = b_q >> 1;            // 0 or 1 (image row within tile)

    auto issue_stage = [&](int c) {
        if (c < NC) {
            const uint32_t sA = stg + (c % NSTG) * STAGE_BYTES;
            const uint32_t sB = sA + A_BYTES;
            const __half* asrc = wgt + (size_t)(mbase + a_row0) * KPAD + c * 64 + a_kg0 * 8;
            #pragma unroll
            for (int q = 0; q < 4; ++q)
                cp_async16(a_addr(sA, a_row0, a_kg0 + q), asrc + q * 8);
            const int kk = c * 64 + b_krow;
            const __half* bsrc;
            if (PAD3) {
                int t9 = kk >> CLOG;
                if (t9 > 8) t9 = 8;                 // pad region: weights are zero
                const int ch = kk & (CIN - 1);
                const int dh = t9 / 3, dw = t9 - dh * 3;
                bsrc = in + (((size_t)(dw * BB + b) * CIN + ch) * PAREA)
                          + (size_t)(h0 + b_orow + dh) * 64 + (b_q & 1) * 32;
            } else {
                bsrc = in + ((size_t)b * CIN + kk) * HW_ + pix0 + b_q * 32;
            }
            #pragma unroll
            for (int q = 0; q < 4; ++q)
                cp_async16(b_addr(sB, b_krow, b_q * 4 + q), bsrc + q * 8);
        }
        cp_commit();
    };

    float acc[2][8][4];
    #pragma unroll
    for (int mt = 0; mt < 2; ++mt)
        #pragma unroll
        for (int nt = 0; nt < 8; ++nt)
            #pragma unroll
            for (int q = 0; q < 4; ++q) acc[mt][nt][q] = 0.f;

    issue_stage(0);
    issue_stage(1);

    // ldmatrix lane bases
    const int a_m  = (lane & 7) + ((lane >> 3) & 1) * 8;
    const int a_kg = lane >> 4;                            // 0/1, + 2*ks
    const int bl_k = ((lane >> 3) & 1) * 8 + (lane & 7);   // + 16*ks
    const int bl_g = lane >> 4;                            // + nt2*2

    for (int c = 0; c < NC; ++c) {
        cp_wait<NSTG - 2>();
        __syncthreads();
        issue_stage(c + NSTG - 1);

        const uint32_t sA = stg + (c % NSTG) * STAGE_BYTES;
        const uint32_t sB = sA + A_BYTES;

        #pragma unroll
        for (int ks = 0; ks < 4; ++ks) {
            uint32_t af[2][4];
            uint32_t bf[4][4];
            #pragma unroll
            for (int mt = 0; mt < 2; ++mt)
                ldsm_x4(af[mt], a_addr(sA, wm + mt * 16 + a_m, 2 * ks + a_kg));
            #pragma unroll
            for (int nt2 = 0; nt2 < 4; ++nt2)
                ldsm_x4t(bf[nt2], b_addr(sB, 16 * ks + bl_k, (wn >> 3) + nt2 * 2 + bl_g));
            #pragma unroll
            for (int nt2 = 0; nt2 < 4; ++nt2) {
                #pragma unroll
                for (int mt = 0; mt < 2; ++mt) {
                    mma_f16(acc[mt][nt2 * 2 + 0], af[mt], bf[nt2][0], bf[nt2][1]);
                    mma_f16(acc[mt][nt2 * 2 + 1], af[mt], bf[nt2][2], bf[nt2][3]);
                }
            }
        }
        // no trailing barrier: next iteration's leading barrier (after cp_wait)
        // orders all reads of this stage before any overwrite.
    }

    // ---- epilogue ----
    const int g  = lane >> 2;
    const int tq = lane & 3;
    #pragma unroll
    for (int mt = 0; mt < 2; ++mt) {
        const int ocl = mbase + wm + mt * 16 + g;
        const int och = ocl + 8;
        const float bl = (ocl < COUT) ? bias[ocl] : 0.f;
        const float bh = (och < COUT) ? bias[och] : 0.f;
        #pragma unroll
        for (int nt = 0; nt < 8; ++nt) {
            const int col = wn + nt * 8 + 2 * tq;
            float v0 = acc[mt][nt][0] + bl, v1 = acc[mt][nt][1] + bl;
            float v2 = acc[mt][nt][2] + bh, v3 = acc[mt][nt][3] + bh;
            if (RELU) {
                v0 = fmaxf(v0, 0.f); v1 = fmaxf(v1, 0.f);
                v2 = fmaxf(v2, 0.f); v3 = fmaxf(v3, 0.f);
            }
            if constexpr (HALF_OUT) {
                __half* o = (__half*)outp;
                if (ocl < COUT)
                    *reinterpret_cast<__half2*>(o + ((size_t)b * COUT + ocl) * HW_ + pix0 + col) =
                        __floats2half2_rn(v0, v1);
                if (och < COUT)
                    *reinterpret_cast<__half2*>(o + ((size_t)b * COUT + och) * HW_ + pix0 + col) =
                        __floats2half2_rn(v2, v3);
            } else {
                float* o = (float*)outp;
                if (ocl < COUT)
                    *reinterpret_cast<float2*>(o + ((size_t)b * COUT + ocl) * HW_ + pix0 + col) =
                        make_float2(v0, v1);
                if (och < COUT)
                    *reinterpret_cast<float2*>(o + ((size_t)b * COUT + och) * HW_ + pix0 + col) =
                        make_float2(v2, v3);
            }
        }
    }
}

// ---------------- RQS pointwise transform + fused partial logdet ----------------
__device__ __forceinline__ float softplusf(float v) {
    return (v > 20.f) ? v : __logf(1.f + __expf(v));
}

__global__ void rqs_kernel(const float* __restrict__ x, float* __restrict__ y)
{
    const int b   = blockIdx.y;
    const int blk = blockIdx.x;                       // 0..PBLK-1
    const int i   = b * PERB + blk * 256 + threadIdx.x;
    const int hw  = i & (HW_ - 1);
    const int c   = (i >> 12) % CC;
    const float* pp = g_params + (((size_t)b * OUTS + c * 23) * HW_) + hw;

    float xv = x[i];
    bool inside = (xv >= -TAILF) && (xv <= TAILF);
    float xin = fminf(fmaxf(xv, -TAILF), TAILF);

    float u[NB];
    float mx = -1e30f;
    #pragma unroll
    for (int j = 0; j < NB; ++j) { u[j] = pp[(size_t)j * HW_]; mx = fmaxf(mx, u[j]); }
    float se = 0.f;
    #pragma unroll
    for (int j = 0; j < NB; ++j) { u[j] = __expf(u[j] - mx); se += u[j]; }
    float inv = 1.f / se;
    float cw[NB + 1];
    cw[0] = -TAILF;
    float cs = 0.f;
    #pragma unroll
    for (int k = 0; k < NB; ++k) {
        cs += MBWF + (1.f - MBWF * NB) * (u[k] * inv);
        cw[k + 1] = 2.f * TAILF * cs - TAILF;
    }
    cw[NB] = TAILF;

    int t = 0;
    #pragma unroll
    for (int k = 1; k < NB; ++k) t += (xin >= cw[k]) ? 1 : 0;
    float in_cw = cw[t];
    float in_w  = cw[t + 1] - cw[t];

    mx = -1e30f;
    #pragma unroll
    for (int j = 0; j < NB; ++j) { u[j] = pp[(size_t)(NB + j) * HW_]; mx = fmaxf(mx, u[j]); }
    se = 0.f;
    #pragma unroll
    for (int j = 0; j < NB; ++j) { u[j] = __expf(u[j] - mx); se += u[j]; }
    inv = 1.f / se;
    float ch[NB + 1];
    ch[0] = -TAILF;
    cs = 0.f;
    #pragma unroll
    for (int k = 0; k < NB; ++k) {
        cs += MBHF + (1.f - MBHF * NB) * (u[k] * inv);
        ch[k + 1] = 2.f * TAILF * cs - TAILF;
    }
    ch[NB] = TAILF;
    float in_ch = ch[t];
    float in_h  = ch[t + 1] - ch[t];

    float d0 = 1.0f, d1 = 1.0f;
    if (t > 0)      d0 = MDF + softplusf(pp[(size_t)(2*NB + t - 1) * HW_]);
    if (t < NB - 1) d1 = MDF + softplusf(pp[(size_t)(2*NB + t) * HW_]);

    float delta = in_h / in_w;
    float th  = (xin - in_cw) / in_w;
    float tom = th * (1.f - th);
    float numer = in_h * (delta * th * th + d0 * tom);
    float denom = delta + (d0 + d1 - 2.f * delta) * tom;
    float yv = in_ch + numer / denom;
    float omt = 1.f - th;
    float dnum = delta * delta * (d1 * th * th + 2.f * delta * tom + d0 * omt * omt);
    float lad = __logf(dnum) - 2.f * __logf(denom);

    y[i] = inside ? yv : xv;

    // fused deterministic block partial sum of lad
    __shared__ double sm[256];
    sm[threadIdx.x] = inside ? (double)lad : 0.0;
    __syncthreads();
    for (int st = 128; st > 0; st >>= 1) {
        if (threadIdx.x < st) sm[threadIdx.x] += sm[threadIdx.x + st];
        __syncthreads();
    }
    if (threadIdx.x == 0) g_psum[b * PBLK + blk] = sm[0];
}

__global__ void logdet_reduce(const float* __restrict__ logdet, float* __restrict__ out)
{
    int b = blockIdx.x;
    double s = (threadIdx.x < PBLK) ? g_psum[b * PBLK + threadIdx.x] : 0.0;
    __shared__ double sm[256];
    sm[threadIdx.x] = s;
    __syncthreads();
    for (int st = 128; st > 0; st >>= 1) {
        if (threadIdx.x < st) sm[threadIdx.x] += sm[threadIdx.x + st];
        __syncthreads();
    }
    if (threadIdx.x == 0) out[b] = logdet[b] + (float)sm[0];
}

// ---------------- launch ----------------
extern "C" void kernel_launch(void* const* d_in, const int* in_sizes, int n_in,
                              void* d_out, int out_size)
{
    const float* x    = (const float*)d_in[0];
    const float* ld   = (const float*)d_in[1];
    const float* cond = (const float*)d_in[2];
    const float* w1   = (const float*)d_in[3];
    const float* b1   = (const float*)d_in[4];
    const float* w2   = (const float*)d_in[5];
    const float* b2   = (const float*)d_in[6];
    const float* w3   = (const float*)d_in[7];
    const float* b3   = (const float*)d_in[8];
    float* out = (float*)d_out;

    __half *p_pad1, *p_pad3, *p_h1, *p_w1, *p_w2, *p_w3;
    float *p_params;
    cudaGetSymbolAddress((void**)&p_pad1, g_pad1);
    cudaGetSymbolAddress((void**)&p_pad3, g_pad3);
    cudaGetSymbolAddress((void**)&p_h1, g_h1h);
    cudaGetSymbolAddress((void**)&p_w1, g_w1h);
    cudaGetSymbolAddress((void**)&p_w2, g_w2h);
    cudaGetSymbolAddress((void**)&p_w3, g_w3h);
    cudaGetSymbolAddress((void**)&p_params, g_params);

    // h2 (fp16, 33MB) aliases the head of g_params (144MB): consumed by pad3
    // strictly before conv3 writes params. Safe ordering on one stream.
    __half* p_h2 = reinterpret_cast<__half*>(p_params);

    cudaFuncSetAttribute((const void*)conv_gemm<true,  true,  HID,  16,  4, 192,  true >,
                         cudaFuncAttributeMaxDynamicSharedMemorySize, CONV_SMEM);
    cudaFuncSetAttribute((const void*)conv_gemm<false, true,  HID,  128, 7, 128,  true >,
                         cudaFuncAttributeMaxDynamicSharedMemorySize, CONV_SMEM);
    cudaFuncSetAttribute((const void*)conv_gemm<true,  false, OUTS, 128, 7, 1152, false>,
                         cudaFuncAttributeMaxDynamicSharedMemorySize, CONV_SMEM);

    {
        const int NW = 128*192 + 128*128 + 384*1152;
        prep_weights<<<(NW + 255) / 256, 256>>>(w1, w2, w3);
    }
    {
        const int N = 3 * BB * 16 * 66 * 32;
        pad1_kernel<<<(N + 255) / 256, 256>>>(x, cond);
    }
    conv_gemm<true,  true,  HID, 16,  4, 192, true ><<<dim3(32, 1, BB), 256, CONV_SMEM>>>(p_pad1, p_w1, b1, p_h1);
    conv_gemm<false, true,  HID, 128, 7, 128, true ><<<dim3(32, 1, BB), 256, CONV_SMEM>>>(p_h1,   p_w2, b2, p_h2);
    {
        const int N = 3 * BB * HID * 66 * 32;
        pad3_kernel<<<(N + 255) / 256, 256>>>(p_h2);
    }
    conv_gemm<true,  false, OUTS, 128, 7, 1152, false><<<dim3(32, 3, BB), 256, CONV_SMEM>>>(p_pad3, p_w3, b3, p_params);
    rqs_kernel<<<dim3(PBLK, BB), 256>>>(x, out);
    logdet_reduce<<<BB, 256>>>(ld, out + NTOT);
}

// round 11
// speedup vs baseline: 1.1020x; 1.1020x over previous
#include <cuda_runtime.h>
#include <cuda_fp16.h>
#include <math.h>
#include <cstdint>

// Problem constants
#define BB    32
#define CC    12
#define HH_   64
#define WW_   64
#define HW_   4096
#define HID   128
#define CONDC 4
#define OUTS  276          // 12 * 23
#define NB    8
#define TAILF 3.0f
#define MBWF  0.001f
#define MBHF  0.001f
#define MDF   0.001f
#define NTOT  (BB*CC*HW_)  // 1572864
#define PERB  (CC*HW_)     // 49152
#define PAREA (66*64)      // padded channel area (66 rows x 64 cols)
#define PBLK  192          // rqs partial-sum blocks per batch (PERB/256)

// ---------------- scratch (no cudaMalloc allowed) ----------------
__device__ __half g_pad1[(size_t)3*BB*16*PAREA];     // 13 MB
__device__ __half g_h1h[(size_t)BB*HID*HW_];          // 33 MB
__device__ __half g_pad3[(size_t)3*BB*HID*PAREA];    // 104 MB
__device__ __half g_w1h[128 * 192];
__device__ __half g_w2h[128 * 128];
__device__ __half g_w3h[384 * 1152];
__device__ float  g_params[(size_t)BB*OUTS*HW_];      // 144 MB
__device__ double g_psum[BB * PBLK];

// ---------------- helpers ----------------
__device__ __forceinline__ uint32_t smem_u32(const void* p) {
    uint32_t a;
    asm("{ .reg .u64 t; cvta.to.shared.u64 t, %1; cvt.u32.u64 %0, t; }" : "=r"(a) : "l"(p));
    return a;
}
__device__ __forceinline__ void cp_async16(uint32_t dst, const void* src) {
    asm volatile("cp.async.cg.shared.global [%0], [%1], 16;"
                 :: "r"(dst), "l"(src) : "memory");
}
__device__ __forceinline__ void cp_commit() {
    asm volatile("cp.async.commit_group;" ::: "memory");
}
template<int N>
__device__ __forceinline__ void cp_wait() {
    asm volatile("cp.async.wait_group %0;" :: "n"(N) : "memory");
}
__device__ __forceinline__ void ldsm_x4(uint32_t r[4], uint32_t addr) {
    asm volatile("ldmatrix.sync.aligned.m8n8.x4.shared.b16 {%0,%1,%2,%3}, [%4];"
        : "=r"(r[0]), "=r"(r[1]), "=r"(r[2]), "=r"(r[3]) : "r"(addr));
}
__device__ __forceinline__ void ldsm_x4t(uint32_t r[4], uint32_t addr) {
    asm volatile("ldmatrix.sync.aligned.m8n8.x4.trans.shared.b16 {%0,%1,%2,%3}, [%4];"
        : "=r"(r[0]), "=r"(r[1]), "=r"(r[2]), "=r"(r[3]) : "r"(addr));
}
__device__ __forceinline__ void mma_f16(float c[4], const uint32_t a[4],
                                        uint32_t b0, uint32_t b1) {
    asm volatile(
        "mma.sync.aligned.m16n8k16.row.col.f32.f16.f16.f32 "
        "{%0,%1,%2,%3}, {%4,%5,%6,%7}, {%8,%9}, {%0,%1,%2,%3};"
        : "+f"(c[0]), "+f"(c[1]), "+f"(c[2]), "+f"(c[3])
        : "r"(a[0]), "r"(a[1]), "r"(a[2]), "r"(a[3]), "r"(b0), "r"(b1));
}

// A tile: 128 rows x 32 k halves (64B rows), 16B granules XORed by (row>>1)&3
__device__ __forceinline__ uint32_t a_addr(uint32_t base, int row, int kg) {
    return base + row * 64 + ((kg ^ ((row >> 1) & 3)) << 4);
}
// B tile: 32 k-rows x 128 n halves (256B rows, 16 granules), granule XORed by (krow&7)
__device__ __forceinline__ uint32_t b_addr(uint32_t base, int krow, int g) {
    return base + krow * 256 + ((g ^ (krow & 7)) << 4);
}

#define A_BYTES     (128 * 64)            // 8 KB
#define B_BYTES     (32 * 256)            // 8 KB
#define STAGE_BYTES (A_BYTES + B_BYTES)   // 16 KB
#define NSTG        6
#define CONV_SMEM   (NSTG * STAGE_BYTES)  // 96 KB -> 2 CTAs/SM

// ---------------- weight reorder (tap-major, zero-padded, fp16) ----------------
__global__ void prep_weights(const float* __restrict__ w1, const float* __restrict__ w2,
                             const float* __restrict__ w3) {
    const int N1 = 128 * 192, N2 = 128 * 128, N3 = 384 * 1152;
    int i = blockIdx.x * blockDim.x + threadIdx.x;
    if (i < N1) {
        int oc = i / 192, k = i - oc * 192;
        int t = k >> 4, ch = k & 15;
        g_w1h[i] = __float2half((t < 9) ? w1[oc * 144 + ch * 9 + t] : 0.f);
    } else if (i < N1 + N2) {
        int j = i - N1;
        g_w2h[j] = __float2half(w2[j]);
    } else if (i < N1 + N2 + N3) {
        int j = i - N1 - N2;
        int oc = j / 1152, k = j - oc * 1152;
        int t = k >> 7, ch = k & 127;
        g_w3h[j] = __float2half((oc < OUTS) ? w3[oc * 1152 + ch * 9 + t] : 0.f);
    }
}

// ---------------- padded dw-replicated input builders ----------------
// P[dw][b][ch][r 0..65][w 0..63] = in[ch][r-1][w+dw-1] (0 if OOB)
__global__ void pad1_kernel(const float* __restrict__ x, const float* __restrict__ cond) {
    const int N = 3 * BB * 16 * 66 * 32;
    int i = blockIdx.x * blockDim.x + threadIdx.x;
    if (i >= N) return;
    int w2 = i & 31;           int tmp = i >> 5;
    int r  = tmp % 66;         tmp /= 66;
    int ch = tmp & 15;         tmp >>= 4;
    int b  = tmp & 31;         int dw = tmp >> 5;
    int rr = r - 1;
    const float* src = (ch < CC) ? (x    + ((size_t)b * CC    + ch)        * HW_)
                                 : (cond + ((size_t)b * CONDC + (ch - CC)) * HW_);
    float v0 = 0.f, v1 = 0.f;
    if ((unsigned)rr < 64u) {
        int w = w2 * 2;
        int ww0 = w + dw - 1, ww1 = ww0 + 1;
        if ((unsigned)ww0 < 64u) v0 = src[rr * 64 + ww0];
        if ((unsigned)ww1 < 64u) v1 = src[rr * 64 + ww1];
    }
    __half2* dst = reinterpret_cast<__half2*>(
        g_pad1 + (((size_t)(dw * BB + b) * 16 + ch) * PAREA) + r * 64);
    dst[w2] = __floats2half2_rn(v0, v1);
}

__global__ void pad3_kernel(const __half* __restrict__ h2) {
    const int N = 3 * BB * HID * 66 * 32;
    int i = blockIdx.x * blockDim.x + threadIdx.x;
    if (i >= N) return;
    int w2 = i & 31;           int tmp = i >> 5;
    int r  = tmp % 66;         tmp /= 66;
    int ch = tmp & 127;        tmp >>= 7;
    int b  = tmp & 31;         int dw = tmp >> 5;
    int rr = r - 1;
    const __half* src = h2 + ((size_t)b * HID + ch) * HW_;
    __half z = __ushort_as_half(0);
    __half v0 = z, v1 = z;
    if ((unsigned)rr < 64u) {
        int w = w2 * 2;
        int ww0 = w + dw - 1, ww1 = ww0 + 1;
        if ((unsigned)ww0 < 64u) v0 = src[rr * 64 + ww0];
        if ((unsigned)ww1 < 64u) v1 = src[rr * 64 + ww1];
    }
    __half2* dst = reinterpret_cast<__half2*>(
        g_pad3 + (((size_t)(dw * BB + b) * HID + ch) * PAREA) + r * 64);
    dst[w2] = __halves2half2(v0, v1);
}

// ---------------- fp16 multistage GEMM conv (BK=32, dual-chunk barriers) ----------------
// CTA: 256 threads (8 warps, 4(M) x 2(N)); tile M=128 x N=128 pixels (2 rows); BK=32.
// 6-stage ring, per-stage commit; one barrier retires TWO chunks.
template<bool PAD3, bool RELU, int COUT, int CIN, int CLOG, int KPAD, bool HALF_OUT>
__global__ __launch_bounds__(256, 2)
void conv_gemm(const __half* __restrict__ in, const __half* __restrict__ wgt,
               const float* __restrict__ bias, void* __restrict__ outp)
{
    constexpr int NC = KPAD / 32;     // even for all instantiations
    extern __shared__ char smemc[];
    const uint32_t stg = smem_u32(smemc);

    const int tid  = threadIdx.x;
    const int lane = tid & 31;
    const int wid  = tid >> 5;
    const int wm   = (wid & 3) * 32;
    const int wn   = (wid >> 2) * 64;

    const int b     = blockIdx.z;
    const int mbase = blockIdx.y * 128;
    const int h0    = blockIdx.x * 2;
    const int pix0  = blockIdx.x * 128;

    // A-loader: 512 granules, 2/thread (32B contiguous)
    const int a_row0 = tid >> 1;
    const int a_kg0  = (tid & 1) * 2;
    // B-loader: krow = tid>>3, granules g0, g0+1 (32B contiguous)
    const int b_krow = tid >> 3;
    const int b_g0   = (tid & 7) * 2;
    const int b_orow = b_g0 >> 3;       // 0 or 1 (image row within tile)

    auto issue_stage = [&](int c) {
        if (c < NC) {
            const uint32_t sA = stg + (c % NSTG) * STAGE_BYTES;
            const uint32_t sB = sA + A_BYTES;
            const __half* asrc = wgt + (size_t)(mbase + a_row0) * KPAD + c * 32 + a_kg0 * 8;
            cp_async16(a_addr(sA, a_row0, a_kg0), asrc);
            cp_async16(a_addr(sA, a_row0, a_kg0 + 1), asrc + 8);
            const int kk = c * 32 + b_krow;
            const __half* bsrc;
            if (PAD3) {
                int t9 = kk >> CLOG;
                if (t9 > 8) t9 = 8;                 // pad region: weights are zero
                const int ch = kk & (CIN - 1);
                const int dh = t9 / 3, dw = t9 - dh * 3;
                bsrc = in + (((size_t)(dw * BB + b) * CIN + ch) * PAREA)
                          + (size_t)(h0 + b_orow + dh) * 64 + (b_g0 & 7) * 8;
            } else {
                bsrc = in + ((size_t)b * CIN + kk) * HW_ + pix0 + b_g0 * 8;
            }
            cp_async16(b_addr(sB, b_krow, b_g0), bsrc);
            cp_async16(b_addr(sB, b_krow, b_g0 + 1), bsrc + 8);
        }
        cp_commit();
    };

    float acc[2][8][4];
    #pragma unroll
    for (int mt = 0; mt < 2; ++mt)
        #pragma unroll
        for (int nt = 0; nt < 8; ++nt)
            #pragma unroll
            for (int q = 0; q < 4; ++q) acc[mt][nt][q] = 0.f;

    issue_stage(0);
    issue_stage(1);
    issue_stage(2);
    issue_stage(3);

    // ldmatrix lane bases
    const int a_m  = (lane & 7) + ((lane >> 3) & 1) * 8;
    const int a_kg = lane >> 4;
    const int bl_k = ((lane >> 3) & 1) * 8 + (lane & 7);
    const int bl_g = lane >> 4;

    auto compute_chunk = [&](int c) {
        const uint32_t sA = stg + (c % NSTG) * STAGE_BYTES;
        const uint32_t sB = sA + A_BYTES;
        #pragma unroll
        for (int ks = 0; ks < 2; ++ks) {
            uint32_t af[2][4];
            uint32_t bf[4][4];
            #pragma unroll
            for (int mt = 0; mt < 2; ++mt)
                ldsm_x4(af[mt], a_addr(sA, wm + mt * 16 + a_m, 2 * ks + a_kg));
            #pragma unroll
            for (int nt2 = 0; nt2 < 4; ++nt2)
                ldsm_x4t(bf[nt2], b_addr(sB, 16 * ks + bl_k, (wn >> 3) + nt2 * 2 + bl_g));
            #pragma unroll
            for (int nt2 = 0; nt2 < 4; ++nt2) {
                #pragma unroll
                for (int mt = 0; mt < 2; ++mt) {
                    mma_f16(acc[mt][nt2 * 2 + 0], af[mt], bf[nt2][0], bf[nt2][1]);
                    mma_f16(acc[mt][nt2 * 2 + 1], af[mt], bf[nt2][2], bf[nt2][3]);
                }
            }
        }
    };

    for (int c = 0; c < NC; c += 2) {
        cp_wait<2>();            // chunks c, c+1 arrived (c+2, c+3 may be in flight)
        __syncthreads();         // all warps done reading stages freed last iter
        issue_stage(c + 4);      // into stage (c+4)%6 — free
        issue_stage(c + 5);      // into stage (c+5)%6 — free
        compute_chunk(c);
        compute_chunk(c + 1);
        // next iteration's barrier orders these reads before stage reuse
    }

    // ---- epilogue ----
    const int g  = lane >> 2;
    const int tq = lane & 3;
    #pragma unroll
    for (int mt = 0; mt < 2; ++mt) {
        const int ocl = mbase + wm + mt * 16 + g;
        const int och = ocl + 8;
        const float bl = (ocl < COUT) ? bias[ocl] : 0.f;
        const float bh = (och < COUT) ? bias[och] : 0.f;
        #pragma unroll
        for (int nt = 0; nt < 8; ++nt) {
            const int col = wn + nt * 8 + 2 * tq;
            float v0 = acc[mt][nt][0] + bl, v1 = acc[mt][nt][1] + bl;
            float v2 = acc[mt][nt][2] + bh, v3 = acc[mt][nt][3] + bh;
            if (RELU) {
                v0 = fmaxf(v0, 0.f); v1 = fmaxf(v1, 0.f);
                v2 = fmaxf(v2, 0.f); v3 = fmaxf(v3, 0.f);
            }
            if constexpr (HALF_OUT) {
                __half* o = (__half*)outp;
                if (ocl < COUT)
                    *reinterpret_cast<__half2*>(o + ((size_t)b * COUT + ocl) * HW_ + pix0 + col) =
                        __floats2half2_rn(v0, v1);
                if (och < COUT)
                    *reinterpret_cast<__half2*>(o + ((size_t)b * COUT + och) * HW_ + pix0 + col) =
                        __floats2half2_rn(v2, v3);
            } else {
                float* o = (float*)outp;
                if (ocl < COUT)
                    *reinterpret_cast<float2*>(o + ((size_t)b * COUT + ocl) * HW_ + pix0 + col) =
                        make_float2(v0, v1);
                if (och < COUT)
                    *reinterpret_cast<float2*>(o + ((size_t)b * COUT + och) * HW_ + pix0 + col) =
                        make_float2(v2, v3);
            }
        }
    }
}

// ---------------- RQS pointwise transform + fused partial logdet ----------------
__device__ __forceinline__ float softplusf(float v) {
    return (v > 20.f) ? v : __logf(1.f + __expf(v));
}

__global__ void rqs_kernel(const float* __restrict__ x, float* __restrict__ y)
{
    const int b   = blockIdx.y;
    const int blk = blockIdx.x;                       // 0..PBLK-1
    const int i   = b * PERB + blk * 256 + threadIdx.x;
    const int hw  = i & (HW_ - 1);
    const int c   = (i >> 12) % CC;
    const float* pp = g_params + (((size_t)b * OUTS + c * 23) * HW_) + hw;

    float xv = x[i];
    bool inside = (xv >= -TAILF) && (xv <= TAILF);
    float xin = fminf(fmaxf(xv, -TAILF), TAILF);

    float u[NB];
    float mx = -1e30f;
    #pragma unroll
    for (int j = 0; j < NB; ++j) { u[j] = pp[(size_t)j * HW_]; mx = fmaxf(mx, u[j]); }
    float se = 0.f;
    #pragma unroll
    for (int j = 0; j < NB; ++j) { u[j] = __expf(u[j] - mx); se += u[j]; }
    float inv = 1.f / se;
    float cw[NB + 1];
    cw[0] = -TAILF;
    float cs = 0.f;
    #pragma unroll
    for (int k = 0; k < NB; ++k) {
        cs += MBWF + (1.f - MBWF * NB) * (u[k] * inv);
        cw[k + 1] = 2.f * TAILF * cs - TAILF;
    }
    cw[NB] = TAILF;

    int t = 0;
    #pragma unroll
    for (int k = 1; k < NB; ++k) t += (xin >= cw[k]) ? 1 : 0;
    float in_cw = cw[t];
    float in_w  = cw[t + 1] - cw[t];

    mx = -1e30f;
    #pragma unroll
    for (int j = 0; j < NB; ++j) { u[j] = pp[(size_t)(NB + j) * HW_]; mx = fmaxf(mx, u[j]); }
    se = 0.f;
    #pragma unroll
    for (int j = 0; j < NB; ++j) { u[j] = __expf(u[j] - mx); se += u[j]; }
    inv = 1.f / se;
    float ch[NB + 1];
    ch[0] = -TAILF;
    cs = 0.f;
    #pragma unroll
    for (int k = 0; k < NB; ++k) {
        cs += MBHF + (1.f - MBHF * NB) * (u[k] * inv);
        ch[k + 1] = 2.f * TAILF * cs - TAILF;
    }
    ch[NB] = TAILF;
    float in_ch = ch[t];
    float in_h  = ch[t + 1] - ch[t];

    float d0 = 1.0f, d1 = 1.0f;
    if (t > 0)      d0 = MDF + softplusf(pp[(size_t)(2*NB + t - 1) * HW_]);
    if (t < NB - 1) d1 = MDF + softplusf(pp[(size_t)(2*NB + t) * HW_]);

    float delta = in_h / in_w;
    float th  = (xin - in_cw) / in_w;
    float tom = th * (1.f - th);
    float numer = in_h * (delta * th * th + d0 * tom);
    float denom = delta + (d0 + d1 - 2.f * delta) * tom;
    float yv = in_ch + numer / denom;
    float omt = 1.f - th;
    float dnum = delta * delta * (d1 * th * th + 2.f * delta * tom + d0 * omt * omt);
    float lad = __logf(dnum) - 2.f * __logf(denom);

    y[i] = inside ? yv : xv;

    // fused deterministic block partial sum of lad
    __shared__ double sm[256];
    sm[threadIdx.x] = inside ? (double)lad : 0.0;
    __syncthreads();
    for (int st = 128; st > 0; st >>= 1) {
        if (threadIdx.x < st) sm[threadIdx.x] += sm[threadIdx.x + st];
        __syncthreads();
    }
    if (threadIdx.x == 0) g_psum[b * PBLK + blk] = sm[0];
}

__global__ void logdet_reduce(const float* __restrict__ logdet, float* __restrict__ out)
{
    int b = blockIdx.x;
    double s = (threadIdx.x < PBLK) ? g_psum[b * PBLK + threadIdx.x] : 0.0;
    __shared__ double sm[256];
    sm[threadIdx.x] = s;
    __syncthreads();
    for (int st = 128; st > 0; st >>= 1) {
        if (threadIdx.x < st) sm[threadIdx.x] += sm[threadIdx.x + st];
        __syncthreads();
    }
    if (threadIdx.x == 0) out[b] = logdet[b] + (float)sm[0];
}

// ---------------- launch ----------------
extern "C" void kernel_launch(void* const* d_in, const int* in_sizes, int n_in,
                              void* d_out, int out_size)
{
    const float* x    = (const float*)d_in[0];
    const float* ld   = (const float*)d_in[1];
    const float* cond = (const float*)d_in[2];
    const float* w1   = (const float*)d_in[3];
    const float* b1   = (const float*)d_in[4];
    const float* w2   = (const float*)d_in[5];
    const float* b2   = (const float*)d_in[6];
    const float* w3   = (const float*)d_in[7];
    const float* b3   = (const float*)d_in[8];
    float* out = (float*)d_out;

    __half *p_pad1, *p_pad3, *p_h1, *p_w1, *p_w2, *p_w3;
    float *p_params;
    cudaGetSymbolAddress((void**)&p_pad1, g_pad1);
    cudaGetSymbolAddress((void**)&p_pad3, g_pad3);
    cudaGetSymbolAddress((void**)&p_h1, g_h1h);
    cudaGetSymbolAddress((void**)&p_w1, g_w1h);
    cudaGetSymbolAddress((void**)&p_w2, g_w2h);
    cudaGetSymbolAddress((void**)&p_w3, g_w3h);
    cudaGetSymbolAddress((void**)&p_params, g_params);

    // h2 (fp16, 33MB) aliases the head of g_params (144MB): consumed by pad3
    // strictly before conv3 writes params. Safe ordering on one stream.
    __half* p_h2 = reinterpret_cast<__half*>(p_params);

    cudaFuncSetAttribute((const void*)conv_gemm<true,  true,  HID,  16,  4, 192,  true >,
                         cudaFuncAttributeMaxDynamicSharedMemorySize, CONV_SMEM);
    cudaFuncSetAttribute((const void*)conv_gemm<false, true,  HID,  128, 7, 128,  true >,
                         cudaFuncAttributeMaxDynamicSharedMemorySize, CONV_SMEM);
    cudaFuncSetAttribute((const void*)conv_gemm<true,  false, OUTS, 128, 7, 1152, false>,
                         cudaFuncAttributeMaxDynamicSharedMemorySize, CONV_SMEM);

    {
        const int NW = 128*192 + 128*128 + 384*1152;
        prep_weights<<<(NW + 255) / 256, 256>>>(w1, w2, w3);
    }
    {
        const int N = 3 * BB * 16 * 66 * 32;
        pad1_kernel<<<(N + 255) / 256, 256>>>(x, cond);
    }
    conv_gemm<true,  true,  HID, 16,  4, 192, true ><<<dim3(32, 1, BB), 256, CONV_SMEM>>>(p_pad1, p_w1, b1, p_h1);
    conv_gemm<false, true,  HID, 128, 7, 128, true ><<<dim3(32, 1, BB), 256, CONV_SMEM>>>(p_h1,   p_w2, b2, p_h2);
    {
        const int N = 3 * BB * HID * 66 * 32;
        pad3_kernel<<<(N + 255) / 256, 256>>>(p_h2);
    }
    conv_gemm<true,  false, OUTS, 128, 7, 1152, false><<<dim3(32, 3, BB), 256, CONV_SMEM>>>(p_pad3, p_w3, b3, p_params);
    rqs_kernel<<<dim3(PBLK, BB), 256>>>(x, out);
    logdet_reduce<<<BB, 256>>>(ld, out + NTOT);
}

// round 13
// speedup vs baseline: 1.1179x; 1.0144x over previous
#include <cuda_runtime.h>
#include <cuda_fp16.h>
#include <math.h>
#include <cstdint>

// Problem constants
#define BB    32
#define CC    12
#define HH_   64
#define WW_   64
#define HW_   4096
#define HID   128
#define CONDC 4
#define OUTS  276          // 12 * 23
#define NB    8
#define TAILF 3.0f
#define MBWF  0.001f
#define MBHF  0.001f
#define MDF   0.001f
#define NTOT  (BB*CC*HW_)  // 1572864
#define PERB  (CC*HW_)     // 49152
#define PAREA (66*64)      // padded channel area (66 rows x 64 cols)
#define PBLK  192          // rqs partial-sum blocks per batch (PERB/256)

// ---------------- scratch (no cudaMalloc allowed) ----------------
__device__ __half g_pad1[(size_t)3*BB*16*PAREA];     // 13 MB
__device__ __half g_pad3[(size_t)3*BB*HID*PAREA];    // 104 MB
__device__ __half g_w1h[128 * 192];
__device__ __half g_w2h[128 * 128];
__device__ __half g_w3h[384 * 1152];
__device__ float  g_params[(size_t)BB*OUTS*HW_];      // 144 MB
__device__ double g_psum[BB * PBLK];

// ---------------- helpers ----------------
__device__ __forceinline__ uint32_t smem_u32(const void* p) {
    uint32_t a;
    asm("{ .reg .u64 t; cvta.to.shared.u64 t, %1; cvt.u32.u64 %0, t; }" : "=r"(a) : "l"(p));
    return a;
}
__device__ __forceinline__ uint32_t h2_bits(__half2 h) {
    uint32_t u;
    memcpy(&u, &h, 4);
    return u;
}
__device__ __forceinline__ void cp_async16(uint32_t dst, const void* src) {
    asm volatile("cp.async.cg.shared.global [%0], [%1], 16;"
                 :: "r"(dst), "l"(src) : "memory");
}
__device__ __forceinline__ void cp_commit() {
    asm volatile("cp.async.commit_group;" ::: "memory");
}
template<int N>
__device__ __forceinline__ void cp_wait() {
    asm volatile("cp.async.wait_group %0;" :: "n"(N) : "memory");
}
__device__ __forceinline__ void ldsm_x4(uint32_t r[4], uint32_t addr) {
    asm volatile("ldmatrix.sync.aligned.m8n8.x4.shared.b16 {%0,%1,%2,%3}, [%4];"
        : "=r"(r[0]), "=r"(r[1]), "=r"(r[2]), "=r"(r[3]) : "r"(addr));
}
__device__ __forceinline__ void ldsm_x4t(uint32_t r[4], uint32_t addr) {
    asm volatile("ldmatrix.sync.aligned.m8n8.x4.trans.shared.b16 {%0,%1,%2,%3}, [%4];"
        : "=r"(r[0]), "=r"(r[1]), "=r"(r[2]), "=r"(r[3]) : "r"(addr));
}
__device__ __forceinline__ void sts32(uint32_t addr, uint32_t v) {
    asm volatile("st.shared.u32 [%0], %1;" :: "r"(addr), "r"(v) : "memory");
}
__device__ __forceinline__ void mma_f16(float c[4], const uint32_t a[4],
                                        uint32_t b0, uint32_t b1) {
    asm volatile(
        "mma.sync.aligned.m16n8k16.row.col.f32.f16.f16.f32 "
        "{%0,%1,%2,%3}, {%4,%5,%6,%7}, {%8,%9}, {%0,%1,%2,%3};"
        : "+f"(c[0]), "+f"(c[1]), "+f"(c[2]), "+f"(c[3])
        : "r"(a[0]), "r"(a[1]), "r"(a[2]), "r"(a[3]), "r"(b0), "r"(b1));
}

// A tile: 128 rows x 32 k halves (64B rows), 16B granules XORed by (row>>1)&3
__device__ __forceinline__ uint32_t a_addr(uint32_t base, int row, int kg) {
    return base + row * 64 + ((kg ^ ((row >> 1) & 3)) << 4);
}
// B tile: 32 k-rows x 128 n halves (256B rows, 16 granules), granule XORed by (krow&7)
__device__ __forceinline__ uint32_t b_addr(uint32_t base, int krow, int g) {
    return base + krow * 256 + ((g ^ (krow & 7)) << 4);
}

#define A_BYTES     (128 * 64)            // 8 KB
#define B_BYTES     (32 * 256)            // 8 KB
#define STAGE_BYTES (A_BYTES + B_BYTES)   // 16 KB
#define NSTG        6
#define CONV_SMEM   (NSTG * STAGE_BYTES)  // 96 KB -> 2 CTAs/SM

// fused conv1+conv2 smem: 4-stage ring (64 KB) + h1 B-layout area (32 KB)
#define F_NSTG      4
#define F_RING      (F_NSTG * STAGE_BYTES)     // 64 KB
#define FUSED_SMEM  (F_RING + 4 * B_BYTES)     // 96 KB -> 2 CTAs/SM

// ---------------- weight reorder (tap-major, zero-padded, fp16) ----------------
__global__ void prep_weights(const float* __restrict__ w1, const float* __restrict__ w2,
                             const float* __restrict__ w3) {
    const int N1 = 128 * 192, N2 = 128 * 128, N3 = 384 * 1152;
    int i = blockIdx.x * blockDim.x + threadIdx.x;
    if (i < N1) {
        int oc = i / 192, k = i - oc * 192;
        int t = k >> 4, ch = k & 15;
        g_w1h[i] = __float2half((t < 9) ? w1[oc * 144 + ch * 9 + t] : 0.f);
    } else if (i < N1 + N2) {
        int j = i - N1;
        g_w2h[j] = __float2half(w2[j]);
    } else if (i < N1 + N2 + N3) {
        int j = i - N1 - N2;
        int oc = j / 1152, k = j - oc * 1152;
        int t = k >> 7, ch = k & 127;
        g_w3h[j] = __float2half((oc < OUTS) ? w3[oc * 1152 + ch * 9 + t] : 0.f);
    }
}

// ---------------- padded dw-replicated input builders ----------------
// P[dw][b][ch][r 0..65][w 0..63] = in[ch][r-1][w+dw-1] (0 if OOB)
__global__ void pad1_kernel(const float* __restrict__ x, const float* __restrict__ cond) {
    const int N = 3 * BB * 16 * 66 * 32;
    int i = blockIdx.x * blockDim.x + threadIdx.x;
    if (i >= N) return;
    int w2 = i & 31;           int tmp = i >> 5;
    int r  = tmp % 66;         tmp /= 66;
    int ch = tmp & 15;         tmp >>= 4;
    int b  = tmp & 31;         int dw = tmp >> 5;
    int rr = r - 1;
    const float* src = (ch < CC) ? (x    + ((size_t)b * CC    + ch)        * HW_)
                                 : (cond + ((size_t)b * CONDC + (ch - CC)) * HW_);
    float v0 = 0.f, v1 = 0.f;
    if ((unsigned)rr < 64u) {
        int w = w2 * 2;
        int ww0 = w + dw - 1, ww1 = ww0 + 1;
        if ((unsigned)ww0 < 64u) v0 = src[rr * 64 + ww0];
        if ((unsigned)ww1 < 64u) v1 = src[rr * 64 + ww1];
    }
    __half2* dst = reinterpret_cast<__half2*>(
        g_pad1 + (((size_t)(dw * BB + b) * 16 + ch) * PAREA) + r * 64);
    dst[w2] = __floats2half2_rn(v0, v1);
}

__global__ void pad3_kernel(const __half* __restrict__ h2) {
    const int N = 3 * BB * HID * 66 * 32;
    int i = blockIdx.x * blockDim.x + threadIdx.x;
    if (i >= N) return;
    int w2 = i & 31;           int tmp = i >> 5;
    int r  = tmp % 66;         tmp /= 66;
    int ch = tmp & 127;        tmp >>= 7;
    int b  = tmp & 31;         int dw = tmp >> 5;
    int rr = r - 1;
    const __half* src = h2 + ((size_t)b * HID + ch) * HW_;
    __half z = __ushort_as_half(0);
    __half v0 = z, v1 = z;
    if ((unsigned)rr < 64u) {
        int w = w2 * 2;
        int ww0 = w + dw - 1, ww1 = ww0 + 1;
        if ((unsigned)ww0 < 64u) v0 = src[rr * 64 + ww0];
        if ((unsigned)ww1 < 64u) v1 = src[rr * 64 + ww1];
    }
    __half2* dst = reinterpret_cast<__half2*>(
        g_pad3 + (((size_t)(dw * BB + b) * HID + ch) * PAREA) + r * 64);
    dst[w2] = __halves2half2(v0, v1);
}

// ---------------- fused conv1 (3x3, 16->128) + conv2 (1x1, 128->128) ----------------
// CTA: 256 threads (8 warps, 4(M) x 2(N)); M=128 (= all HID channels), N=128 pixels.
// Phase 1: K=192 (padded) over pad1 -> h1 in regs -> bias1+relu -> fp16 -> smem B-layout.
// Phase 2: K=128 over smem h1 with w2 A-tiles via cp.async -> bias2+relu -> h2 (fp16 gmem).
__global__ __launch_bounds__(256, 2)
void fused_conv12(const __half* __restrict__ in, const __half* __restrict__ w1,
                  const __half* __restrict__ w2, const float* __restrict__ bias1,
                  const float* __restrict__ bias2, __half* __restrict__ h2out)
{
    constexpr int NC1 = 6;      // K=192 / 32
    extern __shared__ char smemc[];
    const uint32_t stg  = smem_u32(smemc);
    const uint32_t h1b  = stg + F_RING;

    const int tid  = threadIdx.x;
    const int lane = tid & 31;
    const int wid  = tid >> 5;
    const int wm   = (wid & 3) * 32;
    const int wn   = (wid >> 2) * 64;

    const int b    = blockIdx.z;
    const int h0   = blockIdx.x * 2;
    const int pix0 = blockIdx.x * 128;

    const int a_row0 = tid >> 1;
    const int a_kg0  = (tid & 1) * 2;
    const int b_krow = tid >> 3;
    const int b_g0   = (tid & 7) * 2;
    const int b_orow = b_g0 >> 3;

    auto issue_stage1 = [&](int c) {
        if (c < NC1) {
            const uint32_t sA = stg + (c % F_NSTG) * STAGE_BYTES;
            const uint32_t sB = sA + A_BYTES;
            const __half* asrc = w1 + (size_t)a_row0 * 192 + c * 32 + a_kg0 * 8;
            cp_async16(a_addr(sA, a_row0, a_kg0), asrc);
            cp_async16(a_addr(sA, a_row0, a_kg0 + 1), asrc + 8);
            const int kk = c * 32 + b_krow;
            int t9 = kk >> 4;
            if (t9 > 8) t9 = 8;                  // pad region: weights are zero
            const int ch = kk & 15;
            const int dh = t9 / 3, dw = t9 - dh * 3;
            const __half* bsrc = in + (((size_t)(dw * BB + b) * 16 + ch) * PAREA)
                                    + (size_t)(h0 + b_orow + dh) * 64 + (b_g0 & 7) * 8;
            cp_async16(b_addr(sB, b_krow, b_g0), bsrc);
            cp_async16(b_addr(sB, b_krow, b_g0 + 1), bsrc + 8);
        }
        cp_commit();
    };

    float acc[2][8][4];
    #pragma unroll
    for (int mt = 0; mt < 2; ++mt)
        #pragma unroll
        for (int nt = 0; nt < 8; ++nt)
            #pragma unroll
            for (int q = 0; q < 4; ++q) acc[mt][nt][q] = 0.f;

    issue_stage1(0);
    issue_stage1(1);
    issue_stage1(2);

    const int a_m  = (lane & 7) + ((lane >> 3) & 1) * 8;
    const int a_kg = lane >> 4;
    const int bl_k = ((lane >> 3) & 1) * 8 + (lane & 7);
    const int bl_g = lane >> 4;

    auto compute_chunk = [&](uint32_t sA, uint32_t sB) {
        #pragma unroll
        for (int ks = 0; ks < 2; ++ks) {
            uint32_t af[2][4];
            uint32_t bf[4][4];
            #pragma unroll
            for (int mt = 0; mt < 2; ++mt)
                ldsm_x4(af[mt], a_addr(sA, wm + mt * 16 + a_m, 2 * ks + a_kg));
            #pragma unroll
            for (int nt2 = 0; nt2 < 4; ++nt2)
                ldsm_x4t(bf[nt2], b_addr(sB, 16 * ks + bl_k, (wn >> 3) + nt2 * 2 + bl_g));
            #pragma unroll
            for (int nt2 = 0; nt2 < 4; ++nt2) {
                #pragma unroll
                for (int mt = 0; mt < 2; ++mt) {
                    mma_f16(acc[mt][nt2 * 2 + 0], af[mt], bf[nt2][0], bf[nt2][1]);
                    mma_f16(acc[mt][nt2 * 2 + 1], af[mt], bf[nt2][2], bf[nt2][3]);
                }
            }
        }
    };

    // ---- phase 1: conv1 K-loop ----
    for (int c = 0; c < NC1; ++c) {
        cp_wait<F_NSTG - 2>();
        __syncthreads();
        issue_stage1(c + F_NSTG - 1);
        const uint32_t sA = stg + (c % F_NSTG) * STAGE_BYTES;
        compute_chunk(sA, sA + A_BYTES);
    }
    __syncthreads();    // all warps done reading ring before it is reused

    // ---- h1 = relu(acc + b1) -> fp16 -> smem (B-tile layout, 4 k-chunks) ----
    const int g  = lane >> 2;
    const int tq = lane & 3;
    #pragma unroll
    for (int mt = 0; mt < 2; ++mt) {
        const int chl = wm + mt * 16 + g;
        const int chh = chl + 8;
        const float bl = bias1[chl];
        const float bh = bias1[chh];
        #pragma unroll
        for (int nt = 0; nt < 8; ++nt) {
            const int col = wn + nt * 8 + 2 * tq;
            float v0 = fmaxf(acc[mt][nt][0] + bl, 0.f);
            float v1 = fmaxf(acc[mt][nt][1] + bl, 0.f);
            float v2 = fmaxf(acc[mt][nt][2] + bh, 0.f);
            float v3 = fmaxf(acc[mt][nt][3] + bh, 0.f);
            // addr(ch, col) in h1b: chunk = ch>>5, krow = ch&31, granule = col>>3
            uint32_t al = h1b + ((chl >> 5) << 13) + ((chl & 31) * 256)
                        + ((((col >> 3) ^ (chl & 7)) ) << 4) + ((col & 7) << 1);
            uint32_t ah = h1b + ((chh >> 5) << 13) + ((chh & 31) * 256)
                        + ((((col >> 3) ^ (chh & 7)) ) << 4) + ((col & 7) << 1);
            sts32(al, h2_bits(__floats2half2_rn(v0, v1)));
            sts32(ah, h2_bits(__floats2half2_rn(v2, v3)));
            acc[mt][nt][0] = 0.f; acc[mt][nt][1] = 0.f;
            acc[mt][nt][2] = 0.f; acc[mt][nt][3] = 0.f;
        }
    }

    // ---- phase 2: A = w2 tiles via cp.async into ring; B = h1 in smem ----
    #pragma unroll
    for (int s = 0; s < 4; ++s) {
        const uint32_t sA = stg + s * STAGE_BYTES;
        const __half* asrc = w2 + (size_t)a_row0 * 128 + s * 32 + a_kg0 * 8;
        cp_async16(a_addr(sA, a_row0, a_kg0), asrc);
        cp_async16(a_addr(sA, a_row0, a_kg0 + 1), asrc + 8);
        cp_commit();
    }
    cp_wait<0>();
    __syncthreads();    // h1 stores + w2 tiles visible to all warps

    #pragma unroll
    for (int c2 = 0; c2 < 4; ++c2)
        compute_chunk(stg + c2 * STAGE_BYTES, h1b + c2 * B_BYTES);

    // ---- epilogue: h2 = relu(acc + b2) -> fp16 gmem ----
    #pragma unroll
    for (int mt = 0; mt < 2; ++mt) {
        const int chl = wm + mt * 16 + g;
        const int chh = chl + 8;
        const float bl = bias2[chl];
        const float bh = bias2[chh];
        #pragma unroll
        for (int nt = 0; nt < 8; ++nt) {
            const int col = wn + nt * 8 + 2 * tq;
            float v0 = fmaxf(acc[mt][nt][0] + bl, 0.f);
            float v1 = fmaxf(acc[mt][nt][1] + bl, 0.f);
            float v2 = fmaxf(acc[mt][nt][2] + bh, 0.f);
            float v3 = fmaxf(acc[mt][nt][3] + bh, 0.f);
            *reinterpret_cast<__half2*>(h2out + ((size_t)b * HID + chl) * HW_ + pix0 + col) =
                __floats2half2_rn(v0, v1);
            *reinterpret_cast<__half2*>(h2out + ((size_t)b * HID + chh) * HW_ + pix0 + col) =
                __floats2half2_rn(v2, v3);
        }
    }
}

// ---------------- fp16 multistage GEMM conv (BK=32, 2 CTAs/SM) — conv3 ----------------
template<bool PAD3, bool RELU, int COUT, int CIN, int CLOG, int KPAD, bool HALF_OUT>
__global__ __launch_bounds__(256, 2)
void conv_gemm(const __half* __restrict__ in, const __half* __restrict__ wgt,
               const float* __restrict__ bias, void* __restrict__ outp)
{
    constexpr int NC = KPAD / 32;
    extern __shared__ char smemc[];
    const uint32_t stg = smem_u32(smemc);

    const int tid  = threadIdx.x;
    const int lane = tid & 31;
    const int wid  = tid >> 5;
    const int wm   = (wid & 3) * 32;
    const int wn   = (wid >> 2) * 64;

    const int b     = blockIdx.z;
    const int mbase = blockIdx.y * 128;
    const int h0    = blockIdx.x * 2;
    const int pix0  = blockIdx.x * 128;

    const int a_row0 = tid >> 1;
    const int a_kg0  = (tid & 1) * 2;
    const int b_krow = tid >> 3;
    const int b_g0   = (tid & 7) * 2;
    const int b_orow = b_g0 >> 3;

    auto issue_stage = [&](int c) {
        if (c < NC) {
            const uint32_t sA = stg + (c % NSTG) * STAGE_BYTES;
            const uint32_t sB = sA + A_BYTES;
            const __half* asrc = wgt + (size_t)(mbase + a_row0) * KPAD + c * 32 + a_kg0 * 8;
            cp_async16(a_addr(sA, a_row0, a_kg0), asrc);
            cp_async16(a_addr(sA, a_row0, a_kg0 + 1), asrc + 8);
            const int kk = c * 32 + b_krow;
            const __half* bsrc;
            if (PAD3) {
                int t9 = kk >> CLOG;
                if (t9 > 8) t9 = 8;
                const int ch = kk & (CIN - 1);
                const int dh = t9 / 3, dw = t9 - dh * 3;
                bsrc = in + (((size_t)(dw * BB + b) * CIN + ch) * PAREA)
                          + (size_t)(h0 + b_orow + dh) * 64 + (b_g0 & 7) * 8;
            } else {
                bsrc = in + ((size_t)b * CIN + kk) * HW_ + pix0 + b_g0 * 8;
            }
            cp_async16(b_addr(sB, b_krow, b_g0), bsrc);
            cp_async16(b_addr(sB, b_krow, b_g0 + 1), bsrc + 8);
        }
        cp_commit();
    };

    float acc[2][8][4];
    #pragma unroll
    for (int mt = 0; mt < 2; ++mt)
        #pragma unroll
        for (int nt = 0; nt < 8; ++nt)
            #pragma unroll
            for (int q = 0; q < 4; ++q) acc[mt][nt][q] = 0.f;

    #pragma unroll
    for (int s = 0; s < NSTG - 1; ++s) issue_stage(s);

    const int a_m  = (lane & 7) + ((lane >> 3) & 1) * 8;
    const int a_kg = lane >> 4;
    const int bl_k = ((lane >> 3) & 1) * 8 + (lane & 7);
    const int bl_g = lane >> 4;

    for (int c = 0; c < NC; ++c) {
        cp_wait<NSTG - 2>();
        __syncthreads();
        issue_stage(c + NSTG - 1);

        const uint32_t sA = stg + (c % NSTG) * STAGE_BYTES;
        const uint32_t sB = sA + A_BYTES;

        #pragma unroll
        for (int ks = 0; ks < 2; ++ks) {
            uint32_t af[2][4];
            uint32_t bf[4][4];
            #pragma unroll
            for (int mt = 0; mt < 2; ++mt)
                ldsm_x4(af[mt], a_addr(sA, wm + mt * 16 + a_m, 2 * ks + a_kg));
            #pragma unroll
            for (int nt2 = 0; nt2 < 4; ++nt2)
                ldsm_x4t(bf[nt2], b_addr(sB, 16 * ks + bl_k, (wn >> 3) + nt2 * 2 + bl_g));
            #pragma unroll
            for (int nt2 = 0; nt2 < 4; ++nt2) {
                #pragma unroll
                for (int mt = 0; mt < 2; ++mt) {
                    mma_f16(acc[mt][nt2 * 2 + 0], af[mt], bf[nt2][0], bf[nt2][1]);
                    mma_f16(acc[mt][nt2 * 2 + 1], af[mt], bf[nt2][2], bf[nt2][3]);
                }
            }
        }
    }

    // ---- epilogue ----
    const int g  = lane >> 2;
    const int tq = lane & 3;
    #pragma unroll
    for (int mt = 0; mt < 2; ++mt) {
        const int ocl = mbase + wm + mt * 16 + g;
        const int och = ocl + 8;
        const float bl = (ocl < COUT) ? bias[ocl] : 0.f;
        const float bh = (och < COUT) ? bias[och] : 0.f;
        #pragma unroll
        for (int nt = 0; nt < 8; ++nt) {
            const int col = wn + nt * 8 + 2 * tq;
            float v0 = acc[mt][nt][0] + bl, v1 = acc[mt][nt][1] + bl;
            float v2 = acc[mt][nt][2] + bh, v3 = acc[mt][nt][3] + bh;
            if (RELU) {
                v0 = fmaxf(v0, 0.f); v1 = fmaxf(v1, 0.f);
                v2 = fmaxf(v2, 0.f); v3 = fmaxf(v3, 0.f);
            }
            if constexpr (HALF_OUT) {
                __half* o = (__half*)outp;
                if (ocl < COUT)
                    *reinterpret_cast<__half2*>(o + ((size_t)b * COUT + ocl) * HW_ + pix0 + col) =
                        __floats2half2_rn(v0, v1);
                if (och < COUT)
                    *reinterpret_cast<__half2*>(o + ((size_t)b * COUT + och) * HW_ + pix0 + col) =
                        __floats2half2_rn(v2, v3);
            } else {
                float* o = (float*)outp;
                if (ocl < COUT)
                    *reinterpret_cast<float2*>(o + ((size_t)b * COUT + ocl) * HW_ + pix0 + col) =
                        make_float2(v0, v1);
                if (och < COUT)
                    *reinterpret_cast<float2*>(o + ((size_t)b * COUT + och) * HW_ + pix0 + col) =
                        make_float2(v2, v3);
            }
        }
    }
}

// ---------------- RQS pointwise transform + fused partial logdet ----------------
__device__ __forceinline__ float softplusf(float v) {
    return (v > 20.f) ? v : __logf(1.f + __expf(v));
}

__global__ void rqs_kernel(const float* __restrict__ x, float* __restrict__ y)
{
    const int b   = blockIdx.y;
    const int blk = blockIdx.x;                       // 0..PBLK-1
    const int i   = b * PERB + blk * 256 + threadIdx.x;
    const int hw  = i & (HW_ - 1);
    const int c   = (i >> 12) % CC;
    const float* pp = g_params + (((size_t)b * OUTS + c * 23) * HW_) + hw;

    float xv = x[i];
    bool inside = (xv >= -TAILF) && (xv <= TAILF);
    float xin = fminf(fmaxf(xv, -TAILF), TAILF);

    float u[NB];
    float mx = -1e30f;
    #pragma unroll
    for (int j = 0; j < NB; ++j) { u[j] = pp[(size_t)j * HW_]; mx = fmaxf(mx, u[j]); }
    float se = 0.f;
    #pragma unroll
    for (int j = 0; j < NB; ++j) { u[j] = __expf(u[j] - mx); se += u[j]; }
    float inv = 1.f / se;
    float cw[NB + 1];
    cw[0] = -TAILF;
    float cs = 0.f;
    #pragma unroll
    for (int k = 0; k < NB; ++k) {
        cs += MBWF + (1.f - MBWF * NB) * (u[k] * inv);
        cw[k + 1] = 2.f * TAILF * cs - TAILF;
    }
    cw[NB] = TAILF;

    int t = 0;
    #pragma unroll
    for (int k = 1; k < NB; ++k) t += (xin >= cw[k]) ? 1 : 0;
    float in_cw = cw[t];
    float in_w  = cw[t + 1] - cw[t];

    mx = -1e30f;
    #pragma unroll
    for (int j = 0; j < NB; ++j) { u[j] = pp[(size_t)(NB + j) * HW_]; mx = fmaxf(mx, u[j]); }
    se = 0.f;
    #pragma unroll
    for (int j = 0; j < NB; ++j) { u[j] = __expf(u[j] - mx); se += u[j]; }
    inv = 1.f / se;
    float ch[NB + 1];
    ch[0] = -TAILF;
    cs = 0.f;
    #pragma unroll
    for (int k = 0; k < NB; ++k) {
        cs += MBHF + (1.f - MBHF * NB) * (u[k] * inv);
        ch[k + 1] = 2.f * TAILF * cs - TAILF;
    }
    ch[NB] = TAILF;
    float in_ch = ch[t];
    float in_h  = ch[t + 1] - ch[t];

    float d0 = 1.0f, d1 = 1.0f;
    if (t > 0)      d0 = MDF + softplusf(pp[(size_t)(2*NB + t - 1) * HW_]);
    if (t < NB - 1) d1 = MDF + softplusf(pp[(size_t)(2*NB + t) * HW_]);

    float delta = in_h / in_w;
    float th  = (xin - in_cw) / in_w;
    float tom = th * (1.f - th);
    float numer = in_h * (delta * th * th + d0 * tom);
    float denom = delta + (d0 + d1 - 2.f * delta) * tom;
    float yv = in_ch + numer / denom;
    float omt = 1.f - th;
    float dnum = delta * delta * (d1 * th * th + 2.f * delta * tom + d0 * omt * omt);
    float lad = __logf(dnum) - 2.f * __logf(denom);

    y[i] = inside ? yv : xv;

    // fused deterministic block partial sum of lad
    __shared__ double sm[256];
    sm[threadIdx.x] = inside ? (double)lad : 0.0;
    __syncthreads();
    for (int st = 128; st > 0; st >>= 1) {
        if (threadIdx.x < st) sm[threadIdx.x] += sm[threadIdx.x + st];
        __syncthreads();
    }
    if (threadIdx.x == 0) g_psum[b * PBLK + blk] = sm[0];
}

__global__ void logdet_reduce(const float* __restrict__ logdet, float* __restrict__ out)
{
    int b = blockIdx.x;
    double s = (threadIdx.x < PBLK) ? g_psum[b * PBLK + threadIdx.x] : 0.0;
    __shared__ double sm[256];
    sm[threadIdx.x] = s;
    __syncthreads();
    for (int st = 128; st > 0; st >>= 1) {
        if (threadIdx.x < st) sm[threadIdx.x] += sm[threadIdx.x + st];
        __syncthreads();
    }
    if (threadIdx.x == 0) out[b] = logdet[b] + (float)sm[0];
}

// ---------------- launch ----------------
extern "C" void kernel_launch(void* const* d_in, const int* in_sizes, int n_in,
                              void* d_out, int out_size)
{
    const float* x    = (const float*)d_in[0];
    const float* ld   = (const float*)d_in[1];
    const float* cond = (const float*)d_in[2];
    const float* w1   = (const float*)d_in[3];
    const float* b1   = (const float*)d_in[4];
    const float* w2   = (const float*)d_in[5];
    const float* b2   = (const float*)d_in[6];
    const float* w3   = (const float*)d_in[7];
    const float* b3   = (const float*)d_in[8];
    float* out = (float*)d_out;

    __half *p_pad1, *p_pad3, *p_w1, *p_w2, *p_w3;
    float *p_params;
    cudaGetSymbolAddress((void**)&p_pad1, g_pad1);
    cudaGetSymbolAddress((void**)&p_pad3, g_pad3);
    cudaGetSymbolAddress((void**)&p_w1, g_w1h);
    cudaGetSymbolAddress((void**)&p_w2, g_w2h);
    cudaGetSymbolAddress((void**)&p_w3, g_w3h);
    cudaGetSymbolAddress((void**)&p_params, g_params);

    // h2 (fp16, 33MB) aliases the head of g_params (144MB): consumed by pad3
    // strictly before conv3 writes params. Safe ordering on one stream.
    __half* p_h2 = reinterpret_cast<__half*>(p_params);

    cudaFuncSetAttribute((const void*)fused_conv12,
                         cudaFuncAttributeMaxDynamicSharedMemorySize, FUSED_SMEM);
    cudaFuncSetAttribute((const void*)conv_gemm<true,  false, OUTS, 128, 7, 1152, false>,
                         cudaFuncAttributeMaxDynamicSharedMemorySize, CONV_SMEM);

    {
        const int NW = 128*192 + 128*128 + 384*1152;
        prep_weights<<<(NW + 255) / 256, 256>>>(w1, w2, w3);
    }
    {
        const int N = 3 * BB * 16 * 66 * 32;
        pad1_kernel<<<(N + 255) / 256, 256>>>(x, cond);
    }
    fused_conv12<<<dim3(32, 1, BB), 256, FUSED_SMEM>>>(p_pad1, p_w1, p_w2, b1, b2, p_h2);
    {
        const int N = 3 * BB * HID * 66 * 32;
        pad3_kernel<<<(N + 255) / 256, 256>>>(p_h2);
    }
    conv_gemm<true,  false, OUTS, 128, 7, 1152, false><<<dim3(32, 3, BB), 256, CONV_SMEM>>>(p_pad3, p_w3, b3, p_params);
    rqs_kernel<<<dim3(PBLK, BB), 256>>>(x, out);
    logdet_reduce<<<BB, 256>>>(ld, out + NTOT);
}

// round 14
// speedup vs baseline: 1.2246x; 1.0954x over previous
#include <cuda_runtime.h>
#include <cuda_fp16.h>
#include <math.h>
#include <cstdint>

// Problem constants
#define BB    32
#define CC    12
#define HH_   64
#define WW_   64
#define HW_   4096
#define HID   128
#define CONDC 4
#define OUTS  276          // 12 * 23
#define NB    8
#define TAILF 3.0f
#define MBWF  0.001f
#define MBHF  0.001f
#define MDF   0.001f
#define NTOT  (BB*CC*HW_)  // 1572864
#define PERB  (CC*HW_)     // 49152
#define PAREA (66*64)      // padded channel area (66 rows x 64 cols)
#define PBLK  192          // rqs partial-sum blocks per batch (PERB/256)

// ---------------- scratch (no cudaMalloc allowed) ----------------
__device__ __half g_pad1[(size_t)3*BB*16*PAREA];     // 13 MB
__device__ __half g_pad3[(size_t)3*BB*HID*PAREA];    // 104 MB
__device__ __half g_w1h[128 * 192];
__device__ __half g_w2h[128 * 128];
__device__ __half g_w3h[384 * 1152];
__device__ float  g_params[(size_t)BB*OUTS*HW_];      // 144 MB
__device__ double g_psum[BB * PBLK];

// ---------------- helpers ----------------
__device__ __forceinline__ uint32_t smem_u32(const void* p) {
    uint32_t a;
    asm("{ .reg .u64 t; cvta.to.shared.u64 t, %1; cvt.u32.u64 %0, t; }" : "=r"(a) : "l"(p));
    return a;
}
__device__ __forceinline__ uint32_t h2_bits(__half2 h) {
    uint32_t u;
    memcpy(&u, &h, 4);
    return u;
}
__device__ __forceinline__ void cp_async16(uint32_t dst, const void* src) {
    asm volatile("cp.async.cg.shared.global [%0], [%1], 16;"
                 :: "r"(dst), "l"(src) : "memory");
}
__device__ __forceinline__ void cp_commit() {
    asm volatile("cp.async.commit_group;" ::: "memory");
}
template<int N>
__device__ __forceinline__ void cp_wait() {
    asm volatile("cp.async.wait_group %0;" :: "n"(N) : "memory");
}
__device__ __forceinline__ void ldsm_x4(uint32_t r[4], uint32_t addr) {
    asm volatile("ldmatrix.sync.aligned.m8n8.x4.shared.b16 {%0,%1,%2,%3}, [%4];"
        : "=r"(r[0]), "=r"(r[1]), "=r"(r[2]), "=r"(r[3]) : "r"(addr));
}
__device__ __forceinline__ void ldsm_x4t(uint32_t r[4], uint32_t addr) {
    asm volatile("ldmatrix.sync.aligned.m8n8.x4.trans.shared.b16 {%0,%1,%2,%3}, [%4];"
        : "=r"(r[0]), "=r"(r[1]), "=r"(r[2]), "=r"(r[3]) : "r"(addr));
}
__device__ __forceinline__ void sts32(uint32_t addr, uint32_t v) {
    asm volatile("st.shared.u32 [%0], %1;" :: "r"(addr), "r"(v) : "memory");
}
__device__ __forceinline__ void mma_f16(float c[4], const uint32_t a[4],
                                        uint32_t b0, uint32_t b1) {
    asm volatile(
        "mma.sync.aligned.m16n8k16.row.col.f32.f16.f16.f32 "
        "{%0,%1,%2,%3}, {%4,%5,%6,%7}, {%8,%9}, {%0,%1,%2,%3};"
        : "+f"(c[0]), "+f"(c[1]), "+f"(c[2]), "+f"(c[3])
        : "r"(a[0]), "r"(a[1]), "r"(a[2]), "r"(a[3]), "r"(b0), "r"(b1));
}

// A tile: 128 rows x 32 k halves (64B rows), 16B granules XORed by (row>>1)&3
__device__ __forceinline__ uint32_t a_addr(uint32_t base, int row, int kg) {
    return base + row * 64 + ((kg ^ ((row >> 1) & 3)) << 4);
}
// B tile: 32 k-rows x 128 n halves (256B rows, 16 granules), granule XORed by (krow&7)
__device__ __forceinline__ uint32_t b_addr(uint32_t base, int krow, int g) {
    return base + krow * 256 + ((g ^ (krow & 7)) << 4);
}

#define A_BYTES     (128 * 64)            // 8 KB
#define B_BYTES     (32 * 256)            // 8 KB
#define STAGE_BYTES (A_BYTES + B_BYTES)   // 16 KB
#define NSTG        6
#define CONV_SMEM   (NSTG * STAGE_BYTES)  // 96 KB -> 2 CTAs/SM

// fused conv1+conv2 smem: 4-stage ring (64 KB) + h1 B-layout area (32 KB)
#define F_NSTG      4
#define F_RING      (F_NSTG * STAGE_BYTES)     // 64 KB
#define FUSED_SMEM  (F_RING + 4 * B_BYTES)     // 96 KB -> 2 CTAs/SM

// ---------------- weight reorder (tap-major, zero-padded, fp16) ----------------
__global__ void prep_weights(const float* __restrict__ w1, const float* __restrict__ w2,
                             const float* __restrict__ w3) {
    const int N1 = 128 * 192, N2 = 128 * 128, N3 = 384 * 1152;
    int i = blockIdx.x * blockDim.x + threadIdx.x;
    if (i < N1) {
        int oc = i / 192, k = i - oc * 192;
        int t = k >> 4, ch = k & 15;
        g_w1h[i] = __float2half((t < 9) ? w1[oc * 144 + ch * 9 + t] : 0.f);
    } else if (i < N1 + N2) {
        int j = i - N1;
        g_w2h[j] = __float2half(w2[j]);
    } else if (i < N1 + N2 + N3) {
        int j = i - N1 - N2;
        int oc = j / 1152, k = j - oc * 1152;
        int t = k >> 7, ch = k & 127;
        g_w3h[j] = __float2half((oc < OUTS) ? w3[oc * 1152 + ch * 9 + t] : 0.f);
    }
}

// ---------------- padded dw-replicated input builders ----------------
// P[dw][b][ch][r 0..65][w 0..63] = in[ch][r-1][w+dw-1] (0 if OOB)
__global__ void pad1_kernel(const float* __restrict__ x, const float* __restrict__ cond) {
    const int N = 3 * BB * 16 * 66 * 32;
    int i = blockIdx.x * blockDim.x + threadIdx.x;
    if (i >= N) return;
    int w2 = i & 31;           int tmp = i >> 5;
    int r  = tmp % 66;         tmp /= 66;
    int ch = tmp & 15;         tmp >>= 4;
    int b  = tmp & 31;         int dw = tmp >> 5;
    int rr = r - 1;
    const float* src = (ch < CC) ? (x    + ((size_t)b * CC    + ch)        * HW_)
                                 : (cond + ((size_t)b * CONDC + (ch - CC)) * HW_);
    float v0 = 0.f, v1 = 0.f;
    if ((unsigned)rr < 64u) {
        int w = w2 * 2;
        int ww0 = w + dw - 1, ww1 = ww0 + 1;
        if ((unsigned)ww0 < 64u) v0 = src[rr * 64 + ww0];
        if ((unsigned)ww1 < 64u) v1 = src[rr * 64 + ww1];
    }
    __half2* dst = reinterpret_cast<__half2*>(
        g_pad1 + (((size_t)(dw * BB + b) * 16 + ch) * PAREA) + r * 64);
    dst[w2] = __floats2half2_rn(v0, v1);
}

// Plane-parallel vectorized pad3: one block per (b,ch) plane.
// Reads h2 rows as uint4 (8 halves), emits 3 dw-shifted copies via 16-bit funnel
// shifts; zero borders written by the first 48 threads.
__global__ __launch_bounds__(256)
void pad3_kernel(const __half* __restrict__ h2) {
    const int plane = blockIdx.x;                  // b*HID + ch, 0..4095
    const __half* src = h2 + (size_t)plane * HW_;
    __half* dst0 = g_pad3 + (size_t)plane * PAREA;                       // dw=0
    __half* dst1 = dst0 + (size_t)BB * HID * PAREA;                      // dw=1
    __half* dst2 = dst1 + (size_t)BB * HID * PAREA;                      // dw=2
    const int tid = threadIdx.x;

    // zero border rows (r=0 and r=65) for all 3 copies: 3*2*8 = 48 uint4
    if (tid < 48) {
        int d = tid / 16;                 // dw
        int rq = tid & 15;                // row-sel(0/1) * 8 + quad
        int r = (rq >> 3) ? 65 : 0;
        int q = rq & 7;
        __half* dp = (d == 0) ? dst0 : (d == 1) ? dst1 : dst2;
        *reinterpret_cast<uint4*>(dp + r * 64 + q * 8) = make_uint4(0, 0, 0, 0);
    }

    // body: 64 rows x 8 quads = 512 units, 2 per thread
    #pragma unroll
    for (int u = tid; u < 512; u += 256) {
        const int r = u >> 3;             // src row 0..63
        const int q = u & 7;              // quad in row
        const __half* s = src + r * 64 + q * 8;
        uint4 v = *reinterpret_cast<const uint4*>(s);
        uint32_t left  = (q == 0) ? 0u : (uint32_t)__half_as_ushort(s[-1]);
        uint32_t right = (q == 7) ? 0u : (uint32_t)__half_as_ushort(s[8]);

        // dw=1: identity
        *reinterpret_cast<uint4*>(dst1 + (r + 1) * 64 + q * 8) = v;

        // dw=0: out[w] = src[w-1]  (shift right by one half, insert left)
        uint4 a;
        a.x = (v.x << 16) | left;
        a.y = (v.y << 16) | (v.x >> 16);
        a.z = (v.z << 16) | (v.y >> 16);
        a.w = (v.w << 16) | (v.z >> 16);
        *reinterpret_cast<uint4*>(dst0 + (r + 1) * 64 + q * 8) = a;

        // dw=2: out[w] = src[w+1]  (shift left by one half, insert right)
        uint4 c;
        c.x = (v.x >> 16) | (v.y << 16);
        c.y = (v.y >> 16) | (v.z << 16);
        c.z = (v.z >> 16) | (v.w << 16);
        c.w = (v.w >> 16) | (right << 16);
        *reinterpret_cast<uint4*>(dst2 + (r + 1) * 64 + q * 8) = c;
    }
}

// ---------------- fused conv1 (3x3, 16->128) + conv2 (1x1, 128->128) ----------------
// CTA: 256 threads (8 warps, 4(M) x 2(N)); M=128 (= all HID channels), N=128 pixels.
// Phase 1: K=192 (padded) over pad1 -> h1 in regs -> bias1+relu -> fp16 -> smem B-layout.
// Phase 2: K=128 over smem h1 with w2 A-tiles via cp.async -> bias2+relu -> h2 (fp16 gmem).
__global__ __launch_bounds__(256, 2)
void fused_conv12(const __half* __restrict__ in, const __half* __restrict__ w1,
                  const __half* __restrict__ w2, const float* __restrict__ bias1,
                  const float* __restrict__ bias2, __half* __restrict__ h2out)
{
    constexpr int NC1 = 6;      // K=192 / 32
    extern __shared__ char smemc[];
    const uint32_t stg  = smem_u32(smemc);
    const uint32_t h1b  = stg + F_RING;

    const int tid  = threadIdx.x;
    const int lane = tid & 31;
    const int wid  = tid >> 5;
    const int wm   = (wid & 3) * 32;
    const int wn   = (wid >> 2) * 64;

    const int b    = blockIdx.z;
    const int h0   = blockIdx.x * 2;
    const int pix0 = blockIdx.x * 128;

    const int a_row0 = tid >> 1;
    const int a_kg0  = (tid & 1) * 2;
    const int b_krow = tid >> 3;
    const int b_g0   = (tid & 7) * 2;
    const int b_orow = b_g0 >> 3;

    auto issue_stage1 = [&](int c) {
        if (c < NC1) {
            const uint32_t sA = stg + (c % F_NSTG) * STAGE_BYTES;
            const uint32_t sB = sA + A_BYTES;
            const __half* asrc = w1 + (size_t)a_row0 * 192 + c * 32 + a_kg0 * 8;
            cp_async16(a_addr(sA, a_row0, a_kg0), asrc);
            cp_async16(a_addr(sA, a_row0, a_kg0 + 1), asrc + 8);
            const int kk = c * 32 + b_krow;
            int t9 = kk >> 4;
            if (t9 > 8) t9 = 8;                  // pad region: weights are zero
            const int ch = kk & 15;
            const int dh = t9 / 3, dw = t9 - dh * 3;
            const __half* bsrc = in + (((size_t)(dw * BB + b) * 16 + ch) * PAREA)
                                    + (size_t)(h0 + b_orow + dh) * 64 + (b_g0 & 7) * 8;
            cp_async16(b_addr(sB, b_krow, b_g0), bsrc);
            cp_async16(b_addr(sB, b_krow, b_g0 + 1), bsrc + 8);
        }
        cp_commit();
    };

    float acc[2][8][4];
    #pragma unroll
    for (int mt = 0; mt < 2; ++mt)
        #pragma unroll
        for (int nt = 0; nt < 8; ++nt)
            #pragma unroll
            for (int q = 0; q < 4; ++q) acc[mt][nt][q] = 0.f;

    issue_stage1(0);
    issue_stage1(1);
    issue_stage1(2);

    const int a_m  = (lane & 7) + ((lane >> 3) & 1) * 8;
    const int a_kg = lane >> 4;
    const int bl_k = ((lane >> 3) & 1) * 8 + (lane & 7);
    const int bl_g = lane >> 4;

    auto compute_chunk = [&](uint32_t sA, uint32_t sB) {
        #pragma unroll
        for (int ks = 0; ks < 2; ++ks) {
            uint32_t af[2][4];
            uint32_t bf[4][4];
            #pragma unroll
            for (int mt = 0; mt < 2; ++mt)
                ldsm_x4(af[mt], a_addr(sA, wm + mt * 16 + a_m, 2 * ks + a_kg));
            #pragma unroll
            for (int nt2 = 0; nt2 < 4; ++nt2)
                ldsm_x4t(bf[nt2], b_addr(sB, 16 * ks + bl_k, (wn >> 3) + nt2 * 2 + bl_g));
            #pragma unroll
            for (int nt2 = 0; nt2 < 4; ++nt2) {
                #pragma unroll
                for (int mt = 0; mt < 2; ++mt) {
                    mma_f16(acc[mt][nt2 * 2 + 0], af[mt], bf[nt2][0], bf[nt2][1]);
                    mma_f16(acc[mt][nt2 * 2 + 1], af[mt], bf[nt2][2], bf[nt2][3]);
                }
            }
        }
    };

    // ---- phase 1: conv1 K-loop ----
    for (int c = 0; c < NC1; ++c) {
        cp_wait<F_NSTG - 2>();
        __syncthreads();
        issue_stage1(c + F_NSTG - 1);
        const uint32_t sA = stg + (c % F_NSTG) * STAGE_BYTES;
        compute_chunk(sA, sA + A_BYTES);
    }
    __syncthreads();    // all warps done reading ring before it is reused

    // ---- h1 = relu(acc + b1) -> fp16 -> smem (B-tile layout, 4 k-chunks) ----
    const int g  = lane >> 2;
    const int tq = lane & 3;
    #pragma unroll
    for (int mt = 0; mt < 2; ++mt) {
        const int chl = wm + mt * 16 + g;
        const int chh = chl + 8;
        const float bl = bias1[chl];
        const float bh = bias1[chh];
        #pragma unroll
        for (int nt = 0; nt < 8; ++nt) {
            const int col = wn + nt * 8 + 2 * tq;
            float v0 = fmaxf(acc[mt][nt][0] + bl, 0.f);
            float v1 = fmaxf(acc[mt][nt][1] + bl, 0.f);
            float v2 = fmaxf(acc[mt][nt][2] + bh, 0.f);
            float v3 = fmaxf(acc[mt][nt][3] + bh, 0.f);
            // addr(ch, col) in h1b: chunk = ch>>5, krow = ch&31, granule = col>>3
            uint32_t al = h1b + ((chl >> 5) << 13) + ((chl & 31) * 256)
                        + ((((col >> 3) ^ (chl & 7)) ) << 4) + ((col & 7) << 1);
            uint32_t ah = h1b + ((chh >> 5) << 13) + ((chh & 31) * 256)
                        + ((((col >> 3) ^ (chh & 7)) ) << 4) + ((col & 7) << 1);
            sts32(al, h2_bits(__floats2half2_rn(v0, v1)));
            sts32(ah, h2_bits(__floats2half2_rn(v2, v3)));
            acc[mt][nt][0] = 0.f; acc[mt][nt][1] = 0.f;
            acc[mt][nt][2] = 0.f; acc[mt][nt][3] = 0.f;
        }
    }

    // ---- phase 2: A = w2 tiles via cp.async into ring; B = h1 in smem ----
    #pragma unroll
    for (int s = 0; s < 4; ++s) {
        const uint32_t sA = stg + s * STAGE_BYTES;
        const __half* asrc = w2 + (size_t)a_row0 * 128 + s * 32 + a_kg0 * 8;
        cp_async16(a_addr(sA, a_row0, a_kg0), asrc);
        cp_async16(a_addr(sA, a_row0, a_kg0 + 1), asrc + 8);
        cp_commit();
    }
    cp_wait<0>();
    __syncthreads();    // h1 stores + w2 tiles visible to all warps

    #pragma unroll
    for (int c2 = 0; c2 < 4; ++c2)
        compute_chunk(stg + c2 * STAGE_BYTES, h1b + c2 * B_BYTES);

    // ---- epilogue: h2 = relu(acc + b2) -> fp16 gmem ----
    #pragma unroll
    for (int mt = 0; mt < 2; ++mt) {
        const int chl = wm + mt * 16 + g;
        const int chh = chl + 8;
        const float bl = bias2[chl];
        const float bh = bias2[chh];
        #pragma unroll
        for (int nt = 0; nt < 8; ++nt) {
            const int col = wn + nt * 8 + 2 * tq;
            float v0 = fmaxf(acc[mt][nt][0] + bl, 0.f);
            float v1 = fmaxf(acc[mt][nt][1] + bl, 0.f);
            float v2 = fmaxf(acc[mt][nt][2] + bh, 0.f);
            float v3 = fmaxf(acc[mt][nt][3] + bh, 0.f);
            *reinterpret_cast<__half2*>(h2out + ((size_t)b * HID + chl) * HW_ + pix0 + col) =
                __floats2half2_rn(v0, v1);
            *reinterpret_cast<__half2*>(h2out + ((size_t)b * HID + chh) * HW_ + pix0 + col) =
                __floats2half2_rn(v2, v3);
        }
    }
}

// ---------------- fp16 multistage GEMM conv (BK=32, 2 CTAs/SM) — conv3 ----------------
template<bool PAD3, bool RELU, int COUT, int CIN, int CLOG, int KPAD, bool HALF_OUT>
__global__ __launch_bounds__(256, 2)
void conv_gemm(const __half* __restrict__ in, const __half* __restrict__ wgt,
               const float* __restrict__ bias, void* __restrict__ outp)
{
    constexpr int NC = KPAD / 32;
    extern __shared__ char smemc[];
    const uint32_t stg = smem_u32(smemc);

    const int tid  = threadIdx.x;
    const int lane = tid & 31;
    const int wid  = tid >> 5;
    const int wm   = (wid & 3) * 32;
    const int wn   = (wid >> 2) * 64;

    const int b     = blockIdx.z;
    const int mbase = blockIdx.y * 128;
    const int h0    = blockIdx.x * 2;
    const int pix0  = blockIdx.x * 128;

    const int a_row0 = tid >> 1;
    const int a_kg0  = (tid & 1) * 2;
    const int b_krow = tid >> 3;
    const int b_g0   = (tid & 7) * 2;
    const int b_orow = b_g0 >> 3;

    auto issue_stage = [&](int c) {
        if (c < NC) {
            const uint32_t sA = stg + (c % NSTG) * STAGE_BYTES;
            const uint32_t sB = sA + A_BYTES;
            const __half* asrc = wgt + (size_t)(mbase + a_row0) * KPAD + c * 32 + a_kg0 * 8;
            cp_async16(a_addr(sA, a_row0, a_kg0), asrc);
            cp_async16(a_addr(sA, a_row0, a_kg0 + 1), asrc + 8);
            const int kk = c * 32 + b_krow;
            const __half* bsrc;
            if (PAD3) {
                int t9 = kk >> CLOG;
                if (t9 > 8) t9 = 8;
                const int ch = kk & (CIN - 1);
                const int dh = t9 / 3, dw = t9 - dh * 3;
                bsrc = in + (((size_t)(dw * BB + b) * CIN + ch) * PAREA)
                          + (size_t)(h0 + b_orow + dh) * 64 + (b_g0 & 7) * 8;
            } else {
                bsrc = in + ((size_t)b * CIN + kk) * HW_ + pix0 + b_g0 * 8;
            }
            cp_async16(b_addr(sB, b_krow, b_g0), bsrc);
            cp_async16(b_addr(sB, b_krow, b_g0 + 1), bsrc + 8);
        }
        cp_commit();
    };

    float acc[2][8][4];
    #pragma unroll
    for (int mt = 0; mt < 2; ++mt)
        #pragma unroll
        for (int nt = 0; nt < 8; ++nt)
            #pragma unroll
            for (int q = 0; q < 4; ++q) acc[mt][nt][q] = 0.f;

    #pragma unroll
    for (int s = 0; s < NSTG - 1; ++s) issue_stage(s);

    const int a_m  = (lane & 7) + ((lane >> 3) & 1) * 8;
    const int a_kg = lane >> 4;
    const int bl_k = ((lane >> 3) & 1) * 8 + (lane & 7);
    const int bl_g = lane >> 4;

    for (int c = 0; c < NC; ++c) {
        cp_wait<NSTG - 2>();
        __syncthreads();
        issue_stage(c + NSTG - 1);

        const uint32_t sA = stg + (c % NSTG) * STAGE_BYTES;
        const uint32_t sB = sA + A_BYTES;

        #pragma unroll
        for (int ks = 0; ks < 2; ++ks) {
            uint32_t af[2][4];
            uint32_t bf[4][4];
            #pragma unroll
            for (int mt = 0; mt < 2; ++mt)
                ldsm_x4(af[mt], a_addr(sA, wm + mt * 16 + a_m, 2 * ks + a_kg));
            #pragma unroll
            for (int nt2 = 0; nt2 < 4; ++nt2)
                ldsm_x4t(bf[nt2], b_addr(sB, 16 * ks + bl_k, (wn >> 3) + nt2 * 2 + bl_g));
            #pragma unroll
            for (int nt2 = 0; nt2 < 4; ++nt2) {
                #pragma unroll
                for (int mt = 0; mt < 2; ++mt) {
                    mma_f16(acc[mt][nt2 * 2 + 0], af[mt], bf[nt2][0], bf[nt2][1]);
                    mma_f16(acc[mt][nt2 * 2 + 1], af[mt], bf[nt2][2], bf[nt2][3]);
                }
            }
        }
    }

    // ---- epilogue ----
    const int g  = lane >> 2;
    const int tq = lane & 3;
    #pragma unroll
    for (int mt = 0; mt < 2; ++mt) {
        const int ocl = mbase + wm + mt * 16 + g;
        const int och = ocl + 8;
        const float bl = (ocl < COUT) ? bias[ocl] : 0.f;
        const float bh = (och < COUT) ? bias[och] : 0.f;
        #pragma unroll
        for (int nt = 0; nt < 8; ++nt) {
            const int col = wn + nt * 8 + 2 * tq;
            float v0 = acc[mt][nt][0] + bl, v1 = acc[mt][nt][1] + bl;
            float v2 = acc[mt][nt][2] + bh, v3 = acc[mt][nt][3] + bh;
            if (RELU) {
                v0 = fmaxf(v0, 0.f); v1 = fmaxf(v1, 0.f);
                v2 = fmaxf(v2, 0.f); v3 = fmaxf(v3, 0.f);
            }
            if constexpr (HALF_OUT) {
                __half* o = (__half*)outp;
                if (ocl < COUT)
                    *reinterpret_cast<__half2*>(o + ((size_t)b * COUT + ocl) * HW_ + pix0 + col) =
                        __floats2half2_rn(v0, v1);
                if (och < COUT)
                    *reinterpret_cast<__half2*>(o + ((size_t)b * COUT + och) * HW_ + pix0 + col) =
                        __floats2half2_rn(v2, v3);
            } else {
                float* o = (float*)outp;
                if (ocl < COUT)
                    *reinterpret_cast<float2*>(o + ((size_t)b * COUT + ocl) * HW_ + pix0 + col) =
                        make_float2(v0, v1);
                if (och < COUT)
                    *reinterpret_cast<float2*>(o + ((size_t)b * COUT + och) * HW_ + pix0 + col) =
                        make_float2(v2, v3);
            }
        }
    }
}

// ---------------- RQS pointwise transform + fused partial logdet ----------------
__device__ __forceinline__ float softplusf(float v) {
    return (v > 20.f) ? v : __logf(1.f + __expf(v));
}

__global__ void rqs_kernel(const float* __restrict__ x, float* __restrict__ y)
{
    const int b   = blockIdx.y;
    const int blk = blockIdx.x;                       // 0..PBLK-1
    const int i   = b * PERB + blk * 256 + threadIdx.x;
    const int hw  = i & (HW_ - 1);
    const int c   = (i >> 12) % CC;
    const float* pp = g_params + (((size_t)b * OUTS + c * 23) * HW_) + hw;

    float xv = x[i];
    bool inside = (xv >= -TAILF) && (xv <= TAILF);
    float xin = fminf(fmaxf(xv, -TAILF), TAILF);

    float u[NB];
    float mx = -1e30f;
    #pragma unroll
    for (int j = 0; j < NB; ++j) { u[j] = pp[(size_t)j * HW_]; mx = fmaxf(mx, u[j]); }
    float se = 0.f;
    #pragma unroll
    for (int j = 0; j < NB; ++j) { u[j] = __expf(u[j] - mx); se += u[j]; }
    float inv = 1.f / se;
    float cw[NB + 1];
    cw[0] = -TAILF;
    float cs = 0.f;
    #pragma unroll
    for (int k = 0; k < NB; ++k) {
        cs += MBWF + (1.f - MBWF * NB) * (u[k] * inv);
        cw[k + 1] = 2.f * TAILF * cs - TAILF;
    }
    cw[NB] = TAILF;

    int t = 0;
    #pragma unroll
    for (int k = 1; k < NB; ++k) t += (xin >= cw[k]) ? 1 : 0;
    float in_cw = cw[t];
    float in_w  = cw[t + 1] - cw[t];

    mx = -1e30f;
    #pragma unroll
    for (int j = 0; j < NB; ++j) { u[j] = pp[(size_t)(NB + j) * HW_]; mx = fmaxf(mx, u[j]); }
    se = 0.f;
    #pragma unroll
    for (int j = 0; j < NB; ++j) { u[j] = __expf(u[j] - mx); se += u[j]; }
    inv = 1.f / se;
    float ch[NB + 1];
    ch[0] = -TAILF;
    cs = 0.f;
    #pragma unroll
    for (int k = 0; k < NB; ++k) {
        cs += MBHF + (1.f - MBHF * NB) * (u[k] * inv);
        ch[k + 1] = 2.f * TAILF * cs - TAILF;
    }
    ch[NB] = TAILF;
    float in_ch = ch[t];
    float in_h  = ch[t + 1] - ch[t];

    float d0 = 1.0f, d1 = 1.0f;
    if (t > 0)      d0 = MDF + softplusf(pp[(size_t)(2*NB + t - 1) * HW_]);
    if (t < NB - 1) d1 = MDF + softplusf(pp[(size_t)(2*NB + t) * HW_]);

    float delta = in_h / in_w;
    float th  = (xin - in_cw) / in_w;
    float tom = th * (1.f - th);
    float numer = in_h * (delta * th * th + d0 * tom);
    float denom = delta + (d0 + d1 - 2.f * delta) * tom;
    float yv = in_ch + numer / denom;
    float omt = 1.f - th;
    float dnum = delta * delta * (d1 * th * th + 2.f * delta * tom + d0 * omt * omt);
    float lad = __logf(dnum) - 2.f * __logf(denom);

    y[i] = inside ? yv : xv;

    // fused deterministic block partial sum of lad
    __shared__ double sm[256];
    sm[threadIdx.x] = inside ? (double)lad : 0.0;
    __syncthreads();
    for (int st = 128; st > 0; st >>= 1) {
        if (threadIdx.x < st) sm[threadIdx.x] += sm[threadIdx.x + st];
        __syncthreads();
    }
    if (threadIdx.x == 0) g_psum[b * PBLK + blk] = sm[0];
}

__global__ void logdet_reduce(const float* __restrict__ logdet, float* __restrict__ out)
{
    int b = blockIdx.x;
    double s = (threadIdx.x < PBLK) ? g_psum[b * PBLK + threadIdx.x] : 0.0;
    __shared__ double sm[256];
    sm[threadIdx.x] = s;
    __syncthreads();
    for (int st = 128; st > 0; st >>= 1) {
        if (threadIdx.x < st) sm[threadIdx.x] += sm[threadIdx.x + st];
        __syncthreads();
    }
    if (threadIdx.x == 0) out[b] = logdet[b] + (float)sm[0];
}

// ---------------- launch ----------------
extern "C" void kernel_launch(void* const* d_in, const int* in_sizes, int n_in,
                              void* d_out, int out_size)
{
    const float* x    = (const float*)d_in[0];
    const float* ld   = (const float*)d_in[1];
    const float* cond = (const float*)d_in[2];
    const float* w1   = (const float*)d_in[3];
    const float* b1   = (const float*)d_in[4];
    const float* w2   = (const float*)d_in[5];
    const float* b2   = (const float*)d_in[6];
    const float* w3   = (const float*)d_in[7];
    const float* b3   = (const float*)d_in[8];
    float* out = (float*)d_out;

    __half *p_pad1, *p_pad3, *p_w1, *p_w2, *p_w3;
    float *p_params;
    cudaGetSymbolAddress((void**)&p_pad1, g_pad1);
    cudaGetSymbolAddress((void**)&p_pad3, g_pad3);
    cudaGetSymbolAddress((void**)&p_w1, g_w1h);
    cudaGetSymbolAddress((void**)&p_w2, g_w2h);
    cudaGetSymbolAddress((void**)&p_w3, g_w3h);
    cudaGetSymbolAddress((void**)&p_params, g_params);

    // h2 (fp16, 33MB) aliases the head of g_params (144MB): consumed by pad3
    // strictly before conv3 writes params. Safe ordering on one stream.
    __half* p_h2 = reinterpret_cast<__half*>(p_params);

    cudaFuncSetAttribute((const void*)fused_conv12,
                         cudaFuncAttributeMaxDynamicSharedMemorySize, FUSED_SMEM);
    cudaFuncSetAttribute((const void*)conv_gemm<true,  false, OUTS, 128, 7, 1152, false>,
                         cudaFuncAttributeMaxDynamicSharedMemorySize, CONV_SMEM);

    {
        const int NW = 128*192 + 128*128 + 384*1152;
        prep_weights<<<(NW + 255) / 256, 256>>>(w1, w2, w3);
    }
    {
        const int N = 3 * BB * 16 * 66 * 32;
        pad1_kernel<<<(N + 255) / 256, 256>>>(x, cond);
    }
    fused_conv12<<<dim3(32, 1, BB), 256, FUSED_SMEM>>>(p_pad1, p_w1, p_w2, b1, b2, p_h2);
    pad3_kernel<<<BB * HID, 256>>>(p_h2);
    conv_gemm<true,  false, OUTS, 128, 7, 1152, false><<<dim3(32, 3, BB), 256, CONV_SMEM>>>(p_pad3, p_w3, b3, p_params);
    rqs_kernel<<<dim3(PBLK, BB), 256>>>(x, out);
    logdet_reduce<<<BB, 256>>>(ld, out + NTOT);
}

// round 15
// speedup vs baseline: 1.2510x; 1.0216x over previous
#include <cuda_runtime.h>
#include <cuda_fp16.h>
#include <math.h>
#include <cstdint>

// Problem constants
#define BB    32
#define CC    12
#define HH_   64
#define WW_   64
#define HW_   4096
#define HID   128
#define CONDC 4
#define OUTS  276          // 12 * 23
#define NB    8
#define TAILF 3.0f
#define MBWF  0.001f
#define MBHF  0.001f
#define MDF   0.001f
#define NTOT  (BB*CC*HW_)  // 1572864
#define PERB  (CC*HW_)     // 49152
#define PAREA (66*64)      // padded channel area (66 rows x 64 cols)
#define PBLK  192          // rqs partial-sum blocks per batch (PERB/256)

// ---------------- scratch (no cudaMalloc allowed) ----------------
__device__ __half g_pad1[(size_t)3*BB*16*PAREA];     // 13 MB
__device__ __half g_pad3[(size_t)3*BB*HID*PAREA];    // 104 MB
__device__ __half g_w1h[128 * 192];
__device__ __half g_w2h[128 * 128];
__device__ __half g_w3h[384 * 1152];
__device__ __half g_params[(size_t)BB*OUTS*HW_];      // 72 MB (fp16 logits)
__device__ double g_psum[BB * PBLK];

// ---------------- helpers ----------------
__device__ __forceinline__ uint32_t smem_u32(const void* p) {
    uint32_t a;
    asm("{ .reg .u64 t; cvta.to.shared.u64 t, %1; cvt.u32.u64 %0, t; }" : "=r"(a) : "l"(p));
    return a;
}
__device__ __forceinline__ uint32_t h2_bits(__half2 h) {
    uint32_t u;
    memcpy(&u, &h, 4);
    return u;
}
__device__ __forceinline__ void cp_async16(uint32_t dst, const void* src) {
    asm volatile("cp.async.cg.shared.global [%0], [%1], 16;"
                 :: "r"(dst), "l"(src) : "memory");
}
__device__ __forceinline__ void cp_commit() {
    asm volatile("cp.async.commit_group;" ::: "memory");
}
template<int N>
__device__ __forceinline__ void cp_wait() {
    asm volatile("cp.async.wait_group %0;" :: "n"(N) : "memory");
}
__device__ __forceinline__ void ldsm_x4(uint32_t r[4], uint32_t addr) {
    asm volatile("ldmatrix.sync.aligned.m8n8.x4.shared.b16 {%0,%1,%2,%3}, [%4];"
        : "=r"(r[0]), "=r"(r[1]), "=r"(r[2]), "=r"(r[3]) : "r"(addr));
}
__device__ __forceinline__ void ldsm_x4t(uint32_t r[4], uint32_t addr) {
    asm volatile("ldmatrix.sync.aligned.m8n8.x4.trans.shared.b16 {%0,%1,%2,%3}, [%4];"
        : "=r"(r[0]), "=r"(r[1]), "=r"(r[2]), "=r"(r[3]) : "r"(addr));
}
__device__ __forceinline__ void sts32(uint32_t addr, uint32_t v) {
    asm volatile("st.shared.u32 [%0], %1;" :: "r"(addr), "r"(v) : "memory");
}
__device__ __forceinline__ void mma_f16(float c[4], const uint32_t a[4],
                                        uint32_t b0, uint32_t b1) {
    asm volatile(
        "mma.sync.aligned.m16n8k16.row.col.f32.f16.f16.f32 "
        "{%0,%1,%2,%3}, {%4,%5,%6,%7}, {%8,%9}, {%0,%1,%2,%3};"
        : "+f"(c[0]), "+f"(c[1]), "+f"(c[2]), "+f"(c[3])
        : "r"(a[0]), "r"(a[1]), "r"(a[2]), "r"(a[3]), "r"(b0), "r"(b1));
}

// A tile: 128 rows x 32 k halves (64B rows), 16B granules XORed by (row>>1)&3
__device__ __forceinline__ uint32_t a_addr(uint32_t base, int row, int kg) {
    return base + row * 64 + ((kg ^ ((row >> 1) & 3)) << 4);
}
// B tile: 32 k-rows x 128 n halves (256B rows, 16 granules), granule XORed by (krow&7)
__device__ __forceinline__ uint32_t b_addr(uint32_t base, int krow, int g) {
    return base + krow * 256 + ((g ^ (krow & 7)) << 4);
}

#define A_BYTES     (128 * 64)            // 8 KB
#define B_BYTES     (32 * 256)            // 8 KB
#define STAGE_BYTES (A_BYTES + B_BYTES)   // 16 KB
#define NSTG        6
#define CONV_SMEM   (NSTG * STAGE_BYTES)  // 96 KB -> 2 CTAs/SM

// fused conv1+conv2 smem: 4-stage ring (64 KB) + h1 B-layout area (32 KB)
#define F_NSTG      4
#define F_RING      (F_NSTG * STAGE_BYTES)     // 64 KB
#define FUSED_SMEM  (F_RING + 4 * B_BYTES)     // 96 KB -> 2 CTAs/SM

// ---------------- weight reorder (tap-major, zero-padded, fp16) ----------------
__global__ void prep_weights(const float* __restrict__ w1, const float* __restrict__ w2,
                             const float* __restrict__ w3) {
    const int N1 = 128 * 192, N2 = 128 * 128, N3 = 384 * 1152;
    int i = blockIdx.x * blockDim.x + threadIdx.x;
    if (i < N1) {
        int oc = i / 192, k = i - oc * 192;
        int t = k >> 4, ch = k & 15;
        g_w1h[i] = __float2half((t < 9) ? w1[oc * 144 + ch * 9 + t] : 0.f);
    } else if (i < N1 + N2) {
        int j = i - N1;
        g_w2h[j] = __float2half(w2[j]);
    } else if (i < N1 + N2 + N3) {
        int j = i - N1 - N2;
        int oc = j / 1152, k = j - oc * 1152;
        int t = k >> 7, ch = k & 127;
        g_w3h[j] = __float2half((oc < OUTS) ? w3[oc * 1152 + ch * 9 + t] : 0.f);
    }
}

// ---------------- padded dw-replicated input builders ----------------
// P[dw][b][ch][r 0..65][w 0..63] = in[ch][r-1][w+dw-1] (0 if OOB)
__global__ void pad1_kernel(const float* __restrict__ x, const float* __restrict__ cond) {
    const int N = 3 * BB * 16 * 66 * 32;
    int i = blockIdx.x * blockDim.x + threadIdx.x;
    if (i >= N) return;
    int w2 = i & 31;           int tmp = i >> 5;
    int r  = tmp % 66;         tmp /= 66;
    int ch = tmp & 15;         tmp >>= 4;
    int b  = tmp & 31;         int dw = tmp >> 5;
    int rr = r - 1;
    const float* src = (ch < CC) ? (x    + ((size_t)b * CC    + ch)        * HW_)
                                 : (cond + ((size_t)b * CONDC + (ch - CC)) * HW_);
    float v0 = 0.f, v1 = 0.f;
    if ((unsigned)rr < 64u) {
        int w = w2 * 2;
        int ww0 = w + dw - 1, ww1 = ww0 + 1;
        if ((unsigned)ww0 < 64u) v0 = src[rr * 64 + ww0];
        if ((unsigned)ww1 < 64u) v1 = src[rr * 64 + ww1];
    }
    __half2* dst = reinterpret_cast<__half2*>(
        g_pad1 + (((size_t)(dw * BB + b) * 16 + ch) * PAREA) + r * 64);
    dst[w2] = __floats2half2_rn(v0, v1);
}

// Plane-parallel vectorized pad3: one block per (b,ch) plane.
__global__ __launch_bounds__(256)
void pad3_kernel(const __half* __restrict__ h2) {
    const int plane = blockIdx.x;                  // b*HID + ch, 0..4095
    const __half* src = h2 + (size_t)plane * HW_;
    __half* dst0 = g_pad3 + (size_t)plane * PAREA;                       // dw=0
    __half* dst1 = dst0 + (size_t)BB * HID * PAREA;                      // dw=1
    __half* dst2 = dst1 + (size_t)BB * HID * PAREA;                      // dw=2
    const int tid = threadIdx.x;

    if (tid < 48) {
        int d = tid / 16;
        int rq = tid & 15;
        int r = (rq >> 3) ? 65 : 0;
        int q = rq & 7;
        __half* dp = (d == 0) ? dst0 : (d == 1) ? dst1 : dst2;
        *reinterpret_cast<uint4*>(dp + r * 64 + q * 8) = make_uint4(0, 0, 0, 0);
    }

    #pragma unroll
    for (int u = tid; u < 512; u += 256) {
        const int r = u >> 3;
        const int q = u & 7;
        const __half* s = src + r * 64 + q * 8;
        uint4 v = *reinterpret_cast<const uint4*>(s);
        uint32_t left  = (q == 0) ? 0u : (uint32_t)__half_as_ushort(s[-1]);
        uint32_t right = (q == 7) ? 0u : (uint32_t)__half_as_ushort(s[8]);

        *reinterpret_cast<uint4*>(dst1 + (r + 1) * 64 + q * 8) = v;

        uint4 a;
        a.x = (v.x << 16) | left;
        a.y = (v.y << 16) | (v.x >> 16);
        a.z = (v.z << 16) | (v.y >> 16);
        a.w = (v.w << 16) | (v.z >> 16);
        *reinterpret_cast<uint4*>(dst0 + (r + 1) * 64 + q * 8) = a;

        uint4 c;
        c.x = (v.x >> 16) | (v.y << 16);
        c.y = (v.y >> 16) | (v.z << 16);
        c.z = (v.z >> 16) | (v.w << 16);
        c.w = (v.w >> 16) | (right << 16);
        *reinterpret_cast<uint4*>(dst2 + (r + 1) * 64 + q * 8) = c;
    }
}

// ---------------- fused conv1 (3x3, 16->128) + conv2 (1x1, 128->128) ----------------
__global__ __launch_bounds__(256, 2)
void fused_conv12(const __half* __restrict__ in, const __half* __restrict__ w1,
                  const __half* __restrict__ w2, const float* __restrict__ bias1,
                  const float* __restrict__ bias2, __half* __restrict__ h2out)
{
    constexpr int NC1 = 6;      // K=192 / 32
    extern __shared__ char smemc[];
    const uint32_t stg  = smem_u32(smemc);
    const uint32_t h1b  = stg + F_RING;

    const int tid  = threadIdx.x;
    const int lane = tid & 31;
    const int wid  = tid >> 5;
    const int wm   = (wid & 3) * 32;
    const int wn   = (wid >> 2) * 64;

    const int b    = blockIdx.z;
    const int h0   = blockIdx.x * 2;
    const int pix0 = blockIdx.x * 128;

    const int a_row0 = tid >> 1;
    const int a_kg0  = (tid & 1) * 2;
    const int b_krow = tid >> 3;
    const int b_g0   = (tid & 7) * 2;
    const int b_orow = b_g0 >> 3;

    auto issue_stage1 = [&](int c) {
        if (c < NC1) {
            const uint32_t sA = stg + (c % F_NSTG) * STAGE_BYTES;
            const uint32_t sB = sA + A_BYTES;
            const __half* asrc = w1 + (size_t)a_row0 * 192 + c * 32 + a_kg0 * 8;
            cp_async16(a_addr(sA, a_row0, a_kg0), asrc);
            cp_async16(a_addr(sA, a_row0, a_kg0 + 1), asrc + 8);
            const int kk = c * 32 + b_krow;
            int t9 = kk >> 4;
            if (t9 > 8) t9 = 8;                  // pad region: weights are zero
            const int ch = kk & 15;
            const int dh = t9 / 3, dw = t9 - dh * 3;
            const __half* bsrc = in + (((size_t)(dw * BB + b) * 16 + ch) * PAREA)
                                    + (size_t)(h0 + b_orow + dh) * 64 + (b_g0 & 7) * 8;
            cp_async16(b_addr(sB, b_krow, b_g0), bsrc);
            cp_async16(b_addr(sB, b_krow, b_g0 + 1), bsrc + 8);
        }
        cp_commit();
    };

    float acc[2][8][4];
    #pragma unroll
    for (int mt = 0; mt < 2; ++mt)
        #pragma unroll
        for (int nt = 0; nt < 8; ++nt)
            #pragma unroll
            for (int q = 0; q < 4; ++q) acc[mt][nt][q] = 0.f;

    issue_stage1(0);
    issue_stage1(1);
    issue_stage1(2);

    const int a_m  = (lane & 7) + ((lane >> 3) & 1) * 8;
    const int a_kg = lane >> 4;
    const int bl_k = ((lane >> 3) & 1) * 8 + (lane & 7);
    const int bl_g = lane >> 4;

    auto compute_chunk = [&](uint32_t sA, uint32_t sB) {
        #pragma unroll
        for (int ks = 0; ks < 2; ++ks) {
            uint32_t af[2][4];
            uint32_t bf[4][4];
            #pragma unroll
            for (int mt = 0; mt < 2; ++mt)
                ldsm_x4(af[mt], a_addr(sA, wm + mt * 16 + a_m, 2 * ks + a_kg));
            #pragma unroll
            for (int nt2 = 0; nt2 < 4; ++nt2)
                ldsm_x4t(bf[nt2], b_addr(sB, 16 * ks + bl_k, (wn >> 3) + nt2 * 2 + bl_g));
            #pragma unroll
            for (int nt2 = 0; nt2 < 4; ++nt2) {
                #pragma unroll
                for (int mt = 0; mt < 2; ++mt) {
                    mma_f16(acc[mt][nt2 * 2 + 0], af[mt], bf[nt2][0], bf[nt2][1]);
                    mma_f16(acc[mt][nt2 * 2 + 1], af[mt], bf[nt2][2], bf[nt2][3]);
                }
            }
        }
    };

    // ---- phase 1: conv1 K-loop ----
    for (int c = 0; c < NC1; ++c) {
        cp_wait<F_NSTG - 2>();
        __syncthreads();
        issue_stage1(c + F_NSTG - 1);
        const uint32_t sA = stg + (c % F_NSTG) * STAGE_BYTES;
        compute_chunk(sA, sA + A_BYTES);
    }
    __syncthreads();    // all warps done reading ring before it is reused

    // ---- h1 = relu(acc + b1) -> fp16 -> smem (B-tile layout, 4 k-chunks) ----
    const int g  = lane >> 2;
    const int tq = lane & 3;
    #pragma unroll
    for (int mt = 0; mt < 2; ++mt) {
        const int chl = wm + mt * 16 + g;
        const int chh = chl + 8;
        const float bl = bias1[chl];
        const float bh = bias1[chh];
        #pragma unroll
        for (int nt = 0; nt < 8; ++nt) {
            const int col = wn + nt * 8 + 2 * tq;
            float v0 = fmaxf(acc[mt][nt][0] + bl, 0.f);
            float v1 = fmaxf(acc[mt][nt][1] + bl, 0.f);
            float v2 = fmaxf(acc[mt][nt][2] + bh, 0.f);
            float v3 = fmaxf(acc[mt][nt][3] + bh, 0.f);
            uint32_t al = h1b + ((chl >> 5) << 13) + ((chl & 31) * 256)
                        + ((((col >> 3) ^ (chl & 7)) ) << 4) + ((col & 7) << 1);
            uint32_t ah = h1b + ((chh >> 5) << 13) + ((chh & 31) * 256)
                        + ((((col >> 3) ^ (chh & 7)) ) << 4) + ((col & 7) << 1);
            sts32(al, h2_bits(__floats2half2_rn(v0, v1)));
            sts32(ah, h2_bits(__floats2half2_rn(v2, v3)));
            acc[mt][nt][0] = 0.f; acc[mt][nt][1] = 0.f;
            acc[mt][nt][2] = 0.f; acc[mt][nt][3] = 0.f;
        }
    }

    // ---- phase 2: A = w2 tiles via cp.async into ring; B = h1 in smem ----
    #pragma unroll
    for (int s = 0; s < 4; ++s) {
        const uint32_t sA = stg + s * STAGE_BYTES;
        const __half* asrc = w2 + (size_t)a_row0 * 128 + s * 32 + a_kg0 * 8;
        cp_async16(a_addr(sA, a_row0, a_kg0), asrc);
        cp_async16(a_addr(sA, a_row0, a_kg0 + 1), asrc + 8);
        cp_commit();
    }
    cp_wait<0>();
    __syncthreads();    // h1 stores + w2 tiles visible to all warps

    #pragma unroll
    for (int c2 = 0; c2 < 4; ++c2)
        compute_chunk(stg + c2 * STAGE_BYTES, h1b + c2 * B_BYTES);

    // ---- epilogue: h2 = relu(acc + b2) -> fp16 gmem ----
    #pragma unroll
    for (int mt = 0; mt < 2; ++mt) {
        const int chl = wm + mt * 16 + g;
        const int chh = chl + 8;
        const float bl = bias2[chl];
        const float bh = bias2[chh];
        #pragma unroll
        for (int nt = 0; nt < 8; ++nt) {
            const int col = wn + nt * 8 + 2 * tq;
            float v0 = fmaxf(acc[mt][nt][0] + bl, 0.f);
            float v1 = fmaxf(acc[mt][nt][1] + bl, 0.f);
            float v2 = fmaxf(acc[mt][nt][2] + bh, 0.f);
            float v3 = fmaxf(acc[mt][nt][3] + bh, 0.f);
            *reinterpret_cast<__half2*>(h2out + ((size_t)b * HID + chl) * HW_ + pix0 + col) =
                __floats2half2_rn(v0, v1);
            *reinterpret_cast<__half2*>(h2out + ((size_t)b * HID + chh) * HW_ + pix0 + col) =
                __floats2half2_rn(v2, v3);
        }
    }
}

// ---------------- fp16 multistage GEMM conv (BK=32, 2 CTAs/SM) — conv3 ----------------
// Output: fp16 params (halved epilogue traffic).
template<int COUT, int CIN, int CLOG, int KPAD>
__global__ __launch_bounds__(256, 2)
void conv_gemm(const __half* __restrict__ in, const __half* __restrict__ wgt,
               const float* __restrict__ bias, __half* __restrict__ outp)
{
    constexpr int NC = KPAD / 32;
    extern __shared__ char smemc[];
    const uint32_t stg = smem_u32(smemc);

    const int tid  = threadIdx.x;
    const int lane = tid & 31;
    const int wid  = tid >> 5;
    const int wm   = (wid & 3) * 32;
    const int wn   = (wid >> 2) * 64;

    const int b     = blockIdx.z;
    const int mbase = blockIdx.y * 128;
    const int h0    = blockIdx.x * 2;
    const int pix0  = blockIdx.x * 128;

    const int a_row0 = tid >> 1;
    const int a_kg0  = (tid & 1) * 2;
    const int b_krow = tid >> 3;
    const int b_g0   = (tid & 7) * 2;
    const int b_orow = b_g0 >> 3;

    auto issue_stage = [&](int c) {
        if (c < NC) {
            const uint32_t sA = stg + (c % NSTG) * STAGE_BYTES;
            const uint32_t sB = sA + A_BYTES;
            const __half* asrc = wgt + (size_t)(mbase + a_row0) * KPAD + c * 32 + a_kg0 * 8;
            cp_async16(a_addr(sA, a_row0, a_kg0), asrc);
            cp_async16(a_addr(sA, a_row0, a_kg0 + 1), asrc + 8);
            const int kk = c * 32 + b_krow;
            int t9 = kk >> CLOG;
            if (t9 > 8) t9 = 8;
            const int ch = kk & (CIN - 1);
            const int dh = t9 / 3, dw = t9 - dh * 3;
            const __half* bsrc = in + (((size_t)(dw * BB + b) * CIN + ch) * PAREA)
                                    + (size_t)(h0 + b_orow + dh) * 64 + (b_g0 & 7) * 8;
            cp_async16(b_addr(sB, b_krow, b_g0), bsrc);
            cp_async16(b_addr(sB, b_krow, b_g0 + 1), bsrc + 8);
        }
        cp_commit();
    };

    float acc[2][8][4];
    #pragma unroll
    for (int mt = 0; mt < 2; ++mt)
        #pragma unroll
        for (int nt = 0; nt < 8; ++nt)
            #pragma unroll
            for (int q = 0; q < 4; ++q) acc[mt][nt][q] = 0.f;

    #pragma unroll
    for (int s = 0; s < NSTG - 1; ++s) issue_stage(s);

    const int a_m  = (lane & 7) + ((lane >> 3) & 1) * 8;
    const int a_kg = lane >> 4;
    const int bl_k = ((lane >> 3) & 1) * 8 + (lane & 7);
    const int bl_g = lane >> 4;

    for (int c = 0; c < NC; ++c) {
        cp_wait<NSTG - 2>();
        __syncthreads();
        issue_stage(c + NSTG - 1);

        const uint32_t sA = stg + (c % NSTG) * STAGE_BYTES;
        const uint32_t sB = sA + A_BYTES;

        #pragma unroll
        for (int ks = 0; ks < 2; ++ks) {
            uint32_t af[2][4];
            uint32_t bf[4][4];
            #pragma unroll
            for (int mt = 0; mt < 2; ++mt)
                ldsm_x4(af[mt], a_addr(sA, wm + mt * 16 + a_m, 2 * ks + a_kg));
            #pragma unroll
            for (int nt2 = 0; nt2 < 4; ++nt2)
                ldsm_x4t(bf[nt2], b_addr(sB, 16 * ks + bl_k, (wn >> 3) + nt2 * 2 + bl_g));
            #pragma unroll
            for (int nt2 = 0; nt2 < 4; ++nt2) {
                #pragma unroll
                for (int mt = 0; mt < 2; ++mt) {
                    mma_f16(acc[mt][nt2 * 2 + 0], af[mt], bf[nt2][0], bf[nt2][1]);
                    mma_f16(acc[mt][nt2 * 2 + 1], af[mt], bf[nt2][2], bf[nt2][3]);
                }
            }
        }
    }

    // ---- epilogue (fp16 out) ----
    const int g  = lane >> 2;
    const int tq = lane & 3;
    #pragma unroll
    for (int mt = 0; mt < 2; ++mt) {
        const int ocl = mbase + wm + mt * 16 + g;
        const int och = ocl + 8;
        const float bl = (ocl < COUT) ? bias[ocl] : 0.f;
        const float bh = (och < COUT) ? bias[och] : 0.f;
        #pragma unroll
        for (int nt = 0; nt < 8; ++nt) {
            const int col = wn + nt * 8 + 2 * tq;
            float v0 = acc[mt][nt][0] + bl, v1 = acc[mt][nt][1] + bl;
            float v2 = acc[mt][nt][2] + bh, v3 = acc[mt][nt][3] + bh;
            if (ocl < COUT)
                *reinterpret_cast<__half2*>(outp + ((size_t)b * COUT + ocl) * HW_ + pix0 + col) =
                    __floats2half2_rn(v0, v1);
            if (och < COUT)
                *reinterpret_cast<__half2*>(outp + ((size_t)b * COUT + och) * HW_ + pix0 + col) =
                    __floats2half2_rn(v2, v3);
        }
    }
}

// ---------------- RQS pointwise transform + fused partial logdet ----------------
__device__ __forceinline__ float softplusf(float v) {
    return (v > 20.f) ? v : __logf(1.f + __expf(v));
}

__global__ void rqs_kernel(const float* __restrict__ x, float* __restrict__ y)
{
    const int b   = blockIdx.y;
    const int blk = blockIdx.x;                       // 0..PBLK-1
    const int i   = b * PERB + blk * 256 + threadIdx.x;
    const int hw  = i & (HW_ - 1);
    const int c   = (i >> 12) % CC;
    const __half* pp = g_params + (((size_t)b * OUTS + c * 23) * HW_) + hw;

    float xv = x[i];
    bool inside = (xv >= -TAILF) && (xv <= TAILF);
    float xin = fminf(fmaxf(xv, -TAILF), TAILF);

    float u[NB];
    float mx = -1e30f;
    #pragma unroll
    for (int j = 0; j < NB; ++j) { u[j] = __half2float(pp[(size_t)j * HW_]); mx = fmaxf(mx, u[j]); }
    float se = 0.f;
    #pragma unroll
    for (int j = 0; j < NB; ++j) { u[j] = __expf(u[j] - mx); se += u[j]; }
    float inv = 1.f / se;
    float cw[NB + 1];
    cw[0] = -TAILF;
    float cs = 0.f;
    #pragma unroll
    for (int k = 0; k < NB; ++k) {
        cs += MBWF + (1.f - MBWF * NB) * (u[k] * inv);
        cw[k + 1] = 2.f * TAILF * cs - TAILF;
    }
    cw[NB] = TAILF;

    int t = 0;
    #pragma unroll
    for (int k = 1; k < NB; ++k) t += (xin >= cw[k]) ? 1 : 0;
    float in_cw = cw[t];
    float in_w  = cw[t + 1] - cw[t];

    mx = -1e30f;
    #pragma unroll
    for (int j = 0; j < NB; ++j) { u[j] = __half2float(pp[(size_t)(NB + j) * HW_]); mx = fmaxf(mx, u[j]); }
    se = 0.f;
    #pragma unroll
    for (int j = 0; j < NB; ++j) { u[j] = __expf(u[j] - mx); se += u[j]; }
    inv = 1.f / se;
    float ch[NB + 1];
    ch[0] = -TAILF;
    cs = 0.f;
    #pragma unroll
    for (int k = 0; k < NB; ++k) {
        cs += MBHF + (1.f - MBHF * NB) * (u[k] * inv);
        ch[k + 1] = 2.f * TAILF * cs - TAILF;
    }
    ch[NB] = TAILF;
    float in_ch = ch[t];
    float in_h  = ch[t + 1] - ch[t];

    float d0 = 1.0f, d1 = 1.0f;
    if (t > 0)      d0 = MDF + softplusf(__half2float(pp[(size_t)(2*NB + t - 1) * HW_]));
    if (t < NB - 1) d1 = MDF + softplusf(__half2float(pp[(size_t)(2*NB + t) * HW_]));

    float delta = in_h / in_w;
    float th  = (xin - in_cw) / in_w;
    float tom = th * (1.f - th);
    float numer = in_h * (delta * th * th + d0 * tom);
    float denom = delta + (d0 + d1 - 2.f * delta) * tom;
    float yv = in_ch + numer / denom;
    float omt = 1.f - th;
    float dnum = delta * delta * (d1 * th * th + 2.f * delta * tom + d0 * omt * omt);
    float lad = __logf(dnum) - 2.f * __logf(denom);

    y[i] = inside ? yv : xv;

    // fused deterministic block partial sum of lad
    __shared__ double sm[256];
    sm[threadIdx.x] = inside ? (double)lad : 0.0;
    __syncthreads();
    for (int st = 128; st > 0; st >>= 1) {
        if (threadIdx.x < st) sm[threadIdx.x] += sm[threadIdx.x + st];
        __syncthreads();
    }
    if (threadIdx.x == 0) g_psum[b * PBLK + blk] = sm[0];
}

__global__ void logdet_reduce(const float* __restrict__ logdet, float* __restrict__ out)
{
    int b = blockIdx.x;
    double s = (threadIdx.x < PBLK) ? g_psum[b * PBLK + threadIdx.x] : 0.0;
    __shared__ double sm[256];
    sm[threadIdx.x] = s;
    __syncthreads();
    for (int st = 128; st > 0; st >>= 1) {
        if (threadIdx.x < st) sm[threadIdx.x] += sm[threadIdx.x + st];
        __syncthreads();
    }
    if (threadIdx.x == 0) out[b] = logdet[b] + (float)sm[0];
}

// ---------------- launch ----------------
extern "C" void kernel_launch(void* const* d_in, const int* in_sizes, int n_in,
                              void* d_out, int out_size)
{
    const float* x    = (const float*)d_in[0];
    const float* ld   = (const float*)d_in[1];
    const float* cond = (const float*)d_in[2];
    const float* w1   = (const float*)d_in[3];
    const float* b1   = (const float*)d_in[4];
    const float* w2   = (const float*)d_in[5];
    const float* b2   = (const float*)d_in[6];
    const float* w3   = (const float*)d_in[7];
    const float* b3   = (const float*)d_in[8];
    float* out = (float*)d_out;

    __half *p_pad1, *p_pad3, *p_w1, *p_w2, *p_w3, *p_params;
    cudaGetSymbolAddress((void**)&p_pad1, g_pad1);
    cudaGetSymbolAddress((void**)&p_pad3, g_pad3);
    cudaGetSymbolAddress((void**)&p_w1, g_w1h);
    cudaGetSymbolAddress((void**)&p_w2, g_w2h);
    cudaGetSymbolAddress((void**)&p_w3, g_w3h);
    cudaGetSymbolAddress((void**)&p_params, g_params);

    // h2 (fp16, 33MB) aliases the head of g_params (72MB): consumed by pad3
    // strictly before conv3 writes params. Safe ordering on one stream.
    __half* p_h2 = p_params;

    cudaFuncSetAttribute((const void*)fused_conv12,
                         cudaFuncAttributeMaxDynamicSharedMemorySize, FUSED_SMEM);
    cudaFuncSetAttribute((const void*)conv_gemm<OUTS, 128, 7, 1152>,
                         cudaFuncAttributeMaxDynamicSharedMemorySize, CONV_SMEM);

    {
        const int NW = 128*192 + 128*128 + 384*1152;
        prep_weights<<<(NW + 255) / 256, 256>>>(w1, w2, w3);
    }
    {
        const int N = 3 * BB * 16 * 66 * 32;
        pad1_kernel<<<(N + 255) / 256, 256>>>(x, cond);
    }
    fused_conv12<<<dim3(32, 1, BB), 256, FUSED_SMEM>>>(p_pad1, p_w1, p_w2, b1, b2, p_h2);
    pad3_kernel<<<BB * HID, 256>>>(p_h2);
    conv_gemm<OUTS, 128, 7, 1152><<<dim3(32, 3, BB), 256, CONV_SMEM>>>(p_pad3, p_w3, b3, p_params);
    rqs_kernel<<<dim3(PBLK, BB), 256>>>(x, out);
    logdet_reduce<<<BB, 256>>>(ld, out + NTOT);
}

// round 16
// speedup vs baseline: 1.3108x; 1.0478x over previous
#include <cuda_runtime.h>
#include <cuda_fp16.h>
#include <math.h>
#include <cstdint>

// Problem constants
#define BB    32
#define CC    12
#define HH_   64
#define WW_   64
#define HW_   4096
#define HID   128
#define CONDC 4
#define OUTS  276          // 12 * 23
#define NB    8
#define TAILF 3.0f
#define MBWF  0.001f
#define MBHF  0.001f
#define MDF   0.001f
#define NTOT  (BB*CC*HW_)  // 1572864
#define PERB  (CC*HW_)     // 49152
#define PAREA (66*64)      // padded channel area (66 rows x 64 cols)
#define PBLK  192          // rqs partial-sum blocks per batch (PERB/256)

// ---------------- scratch (no cudaMalloc allowed) ----------------
__device__ __half g_pad1[(size_t)3*BB*16*PAREA];     // 13 MB
__device__ __half g_pad3[(size_t)3*BB*HID*PAREA];    // 104 MB
__device__ __half g_w1h[128 * 192];
__device__ __half g_w2h[128 * 128];
__device__ __half g_w3h[384 * 1152];
__device__ __half g_params[(size_t)BB*OUTS*HW_];      // 72 MB (fp16 logits)
__device__ double g_psum[BB * PBLK];

// ---------------- helpers ----------------
__device__ __forceinline__ uint32_t smem_u32(const void* p) {
    uint32_t a;
    asm("{ .reg .u64 t; cvta.to.shared.u64 t, %1; cvt.u32.u64 %0, t; }" : "=r"(a) : "l"(p));
    return a;
}
__device__ __forceinline__ uint32_t h2_bits(__half2 h) {
    uint32_t u;
    memcpy(&u, &h, 4);
    return u;
}
__device__ __forceinline__ void cp_async16(uint32_t dst, const void* src) {
    asm volatile("cp.async.cg.shared.global [%0], [%1], 16;"
                 :: "r"(dst), "l"(src) : "memory");
}
__device__ __forceinline__ void cp_commit() {
    asm volatile("cp.async.commit_group;" ::: "memory");
}
template<int N>
__device__ __forceinline__ void cp_wait() {
    asm volatile("cp.async.wait_group %0;" :: "n"(N) : "memory");
}
__device__ __forceinline__ void ldsm_x4(uint32_t r[4], uint32_t addr) {
    asm volatile("ldmatrix.sync.aligned.m8n8.x4.shared.b16 {%0,%1,%2,%3}, [%4];"
        : "=r"(r[0]), "=r"(r[1]), "=r"(r[2]), "=r"(r[3]) : "r"(addr));
}
__device__ __forceinline__ void ldsm_x4t(uint32_t r[4], uint32_t addr) {
    asm volatile("ldmatrix.sync.aligned.m8n8.x4.trans.shared.b16 {%0,%1,%2,%3}, [%4];"
        : "=r"(r[0]), "=r"(r[1]), "=r"(r[2]), "=r"(r[3]) : "r"(addr));
}
__device__ __forceinline__ void sts32(uint32_t addr, uint32_t v) {
    asm volatile("st.shared.u32 [%0], %1;" :: "r"(addr), "r"(v) : "memory");
}
__device__ __forceinline__ void mma_f16(float c[4], const uint32_t a[4],
                                        uint32_t b0, uint32_t b1) {
    asm volatile(
        "mma.sync.aligned.m16n8k16.row.col.f32.f16.f16.f32 "
        "{%0,%1,%2,%3}, {%4,%5,%6,%7}, {%8,%9}, {%0,%1,%2,%3};"
        : "+f"(c[0]), "+f"(c[1]), "+f"(c[2]), "+f"(c[3])
        : "r"(a[0]), "r"(a[1]), "r"(a[2]), "r"(a[3]), "r"(b0), "r"(b1));
}

// A tile: 128 rows x 32 k halves (64B rows), 16B granules XORed by (row>>1)&3
__device__ __forceinline__ uint32_t a_addr(uint32_t base, int row, int kg) {
    return base + row * 64 + ((kg ^ ((row >> 1) & 3)) << 4);
}
// B tile: 32 k-rows x 128 n halves (256B rows, 16 granules), granule XORed by (krow&7)
__device__ __forceinline__ uint32_t b_addr(uint32_t base, int krow, int g) {
    return base + krow * 256 + ((g ^ (krow & 7)) << 4);
}

#define A_BYTES     (128 * 64)            // 8 KB
#define B_BYTES     (32 * 256)            // 8 KB
#define STAGE_BYTES (A_BYTES + B_BYTES)   // 16 KB
#define NSTG        6
#define CONV_SMEM   (NSTG * STAGE_BYTES)  // 96 KB -> 2 CTAs/SM

// fused conv1+conv2 smem: 4-stage ring (64 KB) + h1 B-layout area (32 KB)
#define F_NSTG      4
#define F_RING      (F_NSTG * STAGE_BYTES)     // 64 KB
#define FUSED_SMEM  (F_RING + 4 * B_BYTES)     // 96 KB -> 2 CTAs/SM

// ---------------- weight reorder (tap-major, zero-padded, fp16) ----------------
__global__ void prep_weights(const float* __restrict__ w1, const float* __restrict__ w2,
                             const float* __restrict__ w3) {
    const int N1 = 128 * 192, N2 = 128 * 128, N3 = 384 * 1152;
    int i = blockIdx.x * blockDim.x + threadIdx.x;
    if (i < N1) {
        int oc = i / 192, k = i - oc * 192;
        int t = k >> 4, ch = k & 15;
        g_w1h[i] = __float2half((t < 9) ? w1[oc * 144 + ch * 9 + t] : 0.f);
    } else if (i < N1 + N2) {
        int j = i - N1;
        g_w2h[j] = __float2half(w2[j]);
    } else if (i < N1 + N2 + N3) {
        int j = i - N1 - N2;
        int oc = j / 1152, k = j - oc * 1152;
        int t = k >> 7, ch = k & 127;
        g_w3h[j] = __float2half((oc < OUTS) ? w3[oc * 1152 + ch * 9 + t] : 0.f);
    }
}

// ---------------- padded dw-replicated input builders ----------------
// P[dw][b][ch][r 0..65][w 0..63] = in[ch][r-1][w+dw-1] (0 if OOB)
__global__ void pad1_kernel(const float* __restrict__ x, const float* __restrict__ cond) {
    const int N = 3 * BB * 16 * 66 * 32;
    int i = blockIdx.x * blockDim.x + threadIdx.x;
    if (i >= N) return;
    int w2 = i & 31;           int tmp = i >> 5;
    int r  = tmp % 66;         tmp /= 66;
    int ch = tmp & 15;         tmp >>= 4;
    int b  = tmp & 31;         int dw = tmp >> 5;
    int rr = r - 1;
    const float* src = (ch < CC) ? (x    + ((size_t)b * CC    + ch)        * HW_)
                                 : (cond + ((size_t)b * CONDC + (ch - CC)) * HW_);
    float v0 = 0.f, v1 = 0.f;
    if ((unsigned)rr < 64u) {
        int w = w2 * 2;
        int ww0 = w + dw - 1, ww1 = ww0 + 1;
        if ((unsigned)ww0 < 64u) v0 = src[rr * 64 + ww0];
        if ((unsigned)ww1 < 64u) v1 = src[rr * 64 + ww1];
    }
    __half2* dst = reinterpret_cast<__half2*>(
        g_pad1 + (((size_t)(dw * BB + b) * 16 + ch) * PAREA) + r * 64);
    dst[w2] = __floats2half2_rn(v0, v1);
}

// Plane-parallel vectorized pad3: one block per (b,ch) plane.
__global__ __launch_bounds__(256)
void pad3_kernel(const __half* __restrict__ h2) {
    const int plane = blockIdx.x;                  // b*HID + ch, 0..4095
    const __half* src = h2 + (size_t)plane * HW_;
    __half* dst0 = g_pad3 + (size_t)plane * PAREA;                       // dw=0
    __half* dst1 = dst0 + (size_t)BB * HID * PAREA;                      // dw=1
    __half* dst2 = dst1 + (size_t)BB * HID * PAREA;                      // dw=2
    const int tid = threadIdx.x;

    if (tid < 48) {
        int d = tid / 16;
        int rq = tid & 15;
        int r = (rq >> 3) ? 65 : 0;
        int q = rq & 7;
        __half* dp = (d == 0) ? dst0 : (d == 1) ? dst1 : dst2;
        *reinterpret_cast<uint4*>(dp + r * 64 + q * 8) = make_uint4(0, 0, 0, 0);
    }

    #pragma unroll
    for (int u = tid; u < 512; u += 256) {
        const int r = u >> 3;
        const int q = u & 7;
        const __half* s = src + r * 64 + q * 8;
        uint4 v = *reinterpret_cast<const uint4*>(s);
        uint32_t left  = (q == 0) ? 0u : (uint32_t)__half_as_ushort(s[-1]);
        uint32_t right = (q == 7) ? 0u : (uint32_t)__half_as_ushort(s[8]);

        *reinterpret_cast<uint4*>(dst1 + (r + 1) * 64 + q * 8) = v;

        uint4 a;
        a.x = (v.x << 16) | left;
        a.y = (v.y << 16) | (v.x >> 16);
        a.z = (v.z << 16) | (v.y >> 16);
        a.w = (v.w << 16) | (v.z >> 16);
        *reinterpret_cast<uint4*>(dst0 + (r + 1) * 64 + q * 8) = a;

        uint4 c;
        c.x = (v.x >> 16) | (v.y << 16);
        c.y = (v.y >> 16) | (v.z << 16);
        c.z = (v.z >> 16) | (v.w << 16);
        c.w = (v.w >> 16) | (right << 16);
        *reinterpret_cast<uint4*>(dst2 + (r + 1) * 64 + q * 8) = c;
    }
}

// ---------------- fused conv1 (3x3, 16->128) + conv2 (1x1, 128->128) ----------------
__global__ __launch_bounds__(256, 2)
void fused_conv12(const __half* __restrict__ in, const __half* __restrict__ w1,
                  const __half* __restrict__ w2, const float* __restrict__ bias1,
                  const float* __restrict__ bias2, __half* __restrict__ h2out)
{
    constexpr int NC1 = 6;      // K=192 / 32
    extern __shared__ char smemc[];
    const uint32_t stg  = smem_u32(smemc);
    const uint32_t h1b  = stg + F_RING;

    const int tid  = threadIdx.x;
    const int lane = tid & 31;
    const int wid  = tid >> 5;
    const int wm   = (wid & 3) * 32;
    const int wn   = (wid >> 2) * 64;

    const int b    = blockIdx.z;
    const int h0   = blockIdx.x * 2;
    const int pix0 = blockIdx.x * 128;

    const int a_row0 = tid >> 1;
    const int a_kg0  = (tid & 1) * 2;
    const int b_krow = tid >> 3;
    const int b_g0   = (tid & 7) * 2;
    const int b_orow = b_g0 >> 3;

    auto issue_stage1 = [&](int c) {
        if (c < NC1) {
            const uint32_t sA = stg + (c % F_NSTG) * STAGE_BYTES;
            const uint32_t sB = sA + A_BYTES;
            const __half* asrc = w1 + (size_t)a_row0 * 192 + c * 32 + a_kg0 * 8;
            cp_async16(a_addr(sA, a_row0, a_kg0), asrc);
            cp_async16(a_addr(sA, a_row0, a_kg0 + 1), asrc + 8);
            const int kk = c * 32 + b_krow;
            int t9 = kk >> 4;
            if (t9 > 8) t9 = 8;                  // pad region: weights are zero
            const int ch = kk & 15;
            const int dh = t9 / 3, dw = t9 - dh * 3;
            const __half* bsrc = in + (((size_t)(dw * BB + b) * 16 + ch) * PAREA)
                                    + (size_t)(h0 + b_orow + dh) * 64 + (b_g0 & 7) * 8;
            cp_async16(b_addr(sB, b_krow, b_g0), bsrc);
            cp_async16(b_addr(sB, b_krow, b_g0 + 1), bsrc + 8);
        }
        cp_commit();
    };

    float acc[2][8][4];
    #pragma unroll
    for (int mt = 0; mt < 2; ++mt)
        #pragma unroll
        for (int nt = 0; nt < 8; ++nt)
            #pragma unroll
            for (int q = 0; q < 4; ++q) acc[mt][nt][q] = 0.f;

    issue_stage1(0);
    issue_stage1(1);
    issue_stage1(2);

    const int a_m  = (lane & 7) + ((lane >> 3) & 1) * 8;
    const int a_kg = lane >> 4;
    const int bl_k = ((lane >> 3) & 1) * 8 + (lane & 7);
    const int bl_g = lane >> 4;

    auto compute_chunk = [&](uint32_t sA, uint32_t sB) {
        #pragma unroll
        for (int ks = 0; ks < 2; ++ks) {
            uint32_t af[2][4];
            uint32_t bf[4][4];
            #pragma unroll
            for (int mt = 0; mt < 2; ++mt)
                ldsm_x4(af[mt], a_addr(sA, wm + mt * 16 + a_m, 2 * ks + a_kg));
            #pragma unroll
            for (int nt2 = 0; nt2 < 4; ++nt2)
                ldsm_x4t(bf[nt2], b_addr(sB, 16 * ks + bl_k, (wn >> 3) + nt2 * 2 + bl_g));
            #pragma unroll
            for (int nt2 = 0; nt2 < 4; ++nt2) {
                #pragma unroll
                for (int mt = 0; mt < 2; ++mt) {
                    mma_f16(acc[mt][nt2 * 2 + 0], af[mt], bf[nt2][0], bf[nt2][1]);
                    mma_f16(acc[mt][nt2 * 2 + 1], af[mt], bf[nt2][2], bf[nt2][3]);
                }
            }
        }
    };

    // ---- phase 1: conv1 K-loop ----
    for (int c = 0; c < NC1; ++c) {
        cp_wait<F_NSTG - 2>();
        __syncthreads();
        issue_stage1(c + F_NSTG - 1);
        const uint32_t sA = stg + (c % F_NSTG) * STAGE_BYTES;
        compute_chunk(sA, sA + A_BYTES);
    }
    __syncthreads();    // all warps done reading ring before it is reused

    // ---- h1 = relu(acc + b1) -> fp16 -> smem (B-tile layout, 4 k-chunks) ----
    const int g  = lane >> 2;
    const int tq = lane & 3;
    #pragma unroll
    for (int mt = 0; mt < 2; ++mt) {
        const int chl = wm + mt * 16 + g;
        const int chh = chl + 8;
        const float bl = bias1[chl];
        const float bh = bias1[chh];
        #pragma unroll
        for (int nt = 0; nt < 8; ++nt) {
            const int col = wn + nt * 8 + 2 * tq;
            float v0 = fmaxf(acc[mt][nt][0] + bl, 0.f);
            float v1 = fmaxf(acc[mt][nt][1] + bl, 0.f);
            float v2 = fmaxf(acc[mt][nt][2] + bh, 0.f);
            float v3 = fmaxf(acc[mt][nt][3] + bh, 0.f);
            uint32_t al = h1b + ((chl >> 5) << 13) + ((chl & 31) * 256)
                        + ((((col >> 3) ^ (chl & 7)) ) << 4) + ((col & 7) << 1);
            uint32_t ah = h1b + ((chh >> 5) << 13) + ((chh & 31) * 256)
                        + ((((col >> 3) ^ (chh & 7)) ) << 4) + ((col & 7) << 1);
            sts32(al, h2_bits(__floats2half2_rn(v0, v1)));
            sts32(ah, h2_bits(__floats2half2_rn(v2, v3)));
            acc[mt][nt][0] = 0.f; acc[mt][nt][1] = 0.f;
            acc[mt][nt][2] = 0.f; acc[mt][nt][3] = 0.f;
        }
    }

    // ---- phase 2: A = w2 tiles via cp.async into ring; B = h1 in smem ----
    #pragma unroll
    for (int s = 0; s < 4; ++s) {
        const uint32_t sA = stg + s * STAGE_BYTES;
        const __half* asrc = w2 + (size_t)a_row0 * 128 + s * 32 + a_kg0 * 8;
        cp_async16(a_addr(sA, a_row0, a_kg0), asrc);
        cp_async16(a_addr(sA, a_row0, a_kg0 + 1), asrc + 8);
        cp_commit();
    }
    cp_wait<0>();
    __syncthreads();    // h1 stores + w2 tiles visible to all warps

    #pragma unroll
    for (int c2 = 0; c2 < 4; ++c2)
        compute_chunk(stg + c2 * STAGE_BYTES, h1b + c2 * B_BYTES);

    // ---- epilogue: h2 = relu(acc + b2) -> fp16 gmem ----
    #pragma unroll
    for (int mt = 0; mt < 2; ++mt) {
        const int chl = wm + mt * 16 + g;
        const int chh = chl + 8;
        const float bl = bias2[chl];
        const float bh = bias2[chh];
        #pragma unroll
        for (int nt = 0; nt < 8; ++nt) {
            const int col = wn + nt * 8 + 2 * tq;
            float v0 = fmaxf(acc[mt][nt][0] + bl, 0.f);
            float v1 = fmaxf(acc[mt][nt][1] + bl, 0.f);
            float v2 = fmaxf(acc[mt][nt][2] + bh, 0.f);
            float v3 = fmaxf(acc[mt][nt][3] + bh, 0.f);
            *reinterpret_cast<__half2*>(h2out + ((size_t)b * HID + chl) * HW_ + pix0 + col) =
                __floats2half2_rn(v0, v1);
            *reinterpret_cast<__half2*>(h2out + ((size_t)b * HID + chh) * HW_ + pix0 + col) =
                __floats2half2_rn(v2, v3);
        }
    }
}

// ---------------- fp16 multistage GEMM conv3 (BK=32), M-tile = MROWS*64 ----------------
// MROWS=2: M=128 tile (4 warp-rows x 2x16). MROWS=1: M=64 tile (4 warp-rows x 1x16).
// moff = output-channel base for this launch.
template<int MROWS, int COUT, int CIN, int CLOG, int KPAD>
__global__ __launch_bounds__(256, 2)
void conv_gemm(const __half* __restrict__ in, const __half* __restrict__ wgt,
               const float* __restrict__ bias, __half* __restrict__ outp, int moff)
{
    constexpr int NC = KPAD / 32;
    constexpr int MT = MROWS * 64;      // tile M
    extern __shared__ char smemc[];
    const uint32_t stg = smem_u32(smemc);

    const int tid  = threadIdx.x;
    const int lane = tid & 31;
    const int wid  = tid >> 5;
    const int wm   = (wid & 3) * (MROWS * 16);
    const int wn   = (wid >> 2) * 64;

    const int b     = blockIdx.z;
    const int mbase = moff + blockIdx.y * MT;
    const int h0    = blockIdx.x * 2;
    const int pix0  = blockIdx.x * 128;

    const int a_row0 = tid >> 1;
    const int a_kg0  = (tid & 1) * 2;
    const int b_krow = tid >> 3;
    const int b_g0   = (tid & 7) * 2;
    const int b_orow = b_g0 >> 3;

    auto issue_stage = [&](int c) {
        if (c < NC) {
            const uint32_t sA = stg + (c % NSTG) * STAGE_BYTES;
            const uint32_t sB = sA + A_BYTES;
            if (MROWS == 2 || a_row0 < MT) {
                const __half* asrc = wgt + (size_t)(mbase + a_row0) * KPAD + c * 32 + a_kg0 * 8;
                cp_async16(a_addr(sA, a_row0, a_kg0), asrc);
                cp_async16(a_addr(sA, a_row0, a_kg0 + 1), asrc + 8);
            }
            const int kk = c * 32 + b_krow;
            int t9 = kk >> CLOG;
            if (t9 > 8) t9 = 8;
            const int ch = kk & (CIN - 1);
            const int dh = t9 / 3, dw = t9 - dh * 3;
            const __half* bsrc = in + (((size_t)(dw * BB + b) * CIN + ch) * PAREA)
                                    + (size_t)(h0 + b_orow + dh) * 64 + (b_g0 & 7) * 8;
            cp_async16(b_addr(sB, b_krow, b_g0), bsrc);
            cp_async16(b_addr(sB, b_krow, b_g0 + 1), bsrc + 8);
        }
        cp_commit();
    };

    float acc[MROWS][8][4];
    #pragma unroll
    for (int mt = 0; mt < MROWS; ++mt)
        #pragma unroll
        for (int nt = 0; nt < 8; ++nt)
            #pragma unroll
            for (int q = 0; q < 4; ++q) acc[mt][nt][q] = 0.f;

    #pragma unroll
    for (int s = 0; s < NSTG - 1; ++s) issue_stage(s);

    const int a_m  = (lane & 7) + ((lane >> 3) & 1) * 8;
    const int a_kg = lane >> 4;
    const int bl_k = ((lane >> 3) & 1) * 8 + (lane & 7);
    const int bl_g = lane >> 4;

    for (int c = 0; c < NC; ++c) {
        cp_wait<NSTG - 2>();
        __syncthreads();
        issue_stage(c + NSTG - 1);

        const uint32_t sA = stg + (c % NSTG) * STAGE_BYTES;
        const uint32_t sB = sA + A_BYTES;

        #pragma unroll
        for (int ks = 0; ks < 2; ++ks) {
            uint32_t af[MROWS][4];
            uint32_t bf[4][4];
            #pragma unroll
            for (int mt = 0; mt < MROWS; ++mt)
                ldsm_x4(af[mt], a_addr(sA, wm + mt * 16 + a_m, 2 * ks + a_kg));
            #pragma unroll
            for (int nt2 = 0; nt2 < 4; ++nt2)
                ldsm_x4t(bf[nt2], b_addr(sB, 16 * ks + bl_k, (wn >> 3) + nt2 * 2 + bl_g));
            #pragma unroll
            for (int nt2 = 0; nt2 < 4; ++nt2) {
                #pragma unroll
                for (int mt = 0; mt < MROWS; ++mt) {
                    mma_f16(acc[mt][nt2 * 2 + 0], af[mt], bf[nt2][0], bf[nt2][1]);
                    mma_f16(acc[mt][nt2 * 2 + 1], af[mt], bf[nt2][2], bf[nt2][3]);
                }
            }
        }
    }

    // ---- epilogue (fp16 out) ----
    const int g  = lane >> 2;
    const int tq = lane & 3;
    #pragma unroll
    for (int mt = 0; mt < MROWS; ++mt) {
        const int ocl = mbase + wm + mt * 16 + g;
        const int och = ocl + 8;
        const float bl = (ocl < COUT) ? bias[ocl] : 0.f;
        const float bh = (och < COUT) ? bias[och] : 0.f;
        #pragma unroll
        for (int nt = 0; nt < 8; ++nt) {
            const int col = wn + nt * 8 + 2 * tq;
            float v0 = acc[mt][nt][0] + bl, v1 = acc[mt][nt][1] + bl;
            float v2 = acc[mt][nt][2] + bh, v3 = acc[mt][nt][3] + bh;
            if (ocl < COUT)
                *reinterpret_cast<__half2*>(outp + ((size_t)b * COUT + ocl) * HW_ + pix0 + col) =
                    __floats2half2_rn(v0, v1);
            if (och < COUT)
                *reinterpret_cast<__half2*>(outp + ((size_t)b * COUT + och) * HW_ + pix0 + col) =
                    __floats2half2_rn(v2, v3);
        }
    }
}

// ---------------- RQS pointwise transform + fused partial logdet ----------------
__device__ __forceinline__ float softplusf(float v) {
    return (v > 20.f) ? v : __logf(1.f + __expf(v));
}

__global__ void rqs_kernel(const float* __restrict__ x, float* __restrict__ y)
{
    const int b   = blockIdx.y;
    const int blk = blockIdx.x;                       // 0..PBLK-1
    const int i   = b * PERB + blk * 256 + threadIdx.x;
    const int hw  = i & (HW_ - 1);
    const int c   = (i >> 12) % CC;
    const __half* pp = g_params + (((size_t)b * OUTS + c * 23) * HW_) + hw;

    float xv = x[i];
    bool inside = (xv >= -TAILF) && (xv <= TAILF);
    float xin = fminf(fmaxf(xv, -TAILF), TAILF);

    float u[NB];
    float mx = -1e30f;
    #pragma unroll
    for (int j = 0; j < NB; ++j) { u[j] = __half2float(pp[(size_t)j * HW_]); mx = fmaxf(mx, u[j]); }
    float se = 0.f;
    #pragma unroll
    for (int j = 0; j < NB; ++j) { u[j] = __expf(u[j] - mx); se += u[j]; }
    float inv = 1.f / se;
    float cw[NB + 1];
    cw[0] = -TAILF;
    float cs = 0.f;
    #pragma unroll
    for (int k = 0; k < NB; ++k) {
        cs += MBWF + (1.f - MBWF * NB) * (u[k] * inv);
        cw[k + 1] = 2.f * TAILF * cs - TAILF;
    }
    cw[NB] = TAILF;

    int t = 0;
    #pragma unroll
    for (int k = 1; k < NB; ++k) t += (xin >= cw[k]) ? 1 : 0;
    float in_cw = cw[t];
    float in_w  = cw[t + 1] - cw[t];

    mx = -1e30f;
    #pragma unroll
    for (int j = 0; j < NB; ++j) { u[j] = __half2float(pp[(size_t)(NB + j) * HW_]); mx = fmaxf(mx, u[j]); }
    se = 0.f;
    #pragma unroll
    for (int j = 0; j < NB; ++j) { u[j] = __expf(u[j] - mx); se += u[j]; }
    inv = 1.f / se;
    float ch[NB + 1];
    ch[0] = -TAILF;
    cs = 0.f;
    #pragma unroll
    for (int k = 0; k < NB; ++k) {
        cs += MBHF + (1.f - MBHF * NB) * (u[k] * inv);
        ch[k + 1] = 2.f * TAILF * cs - TAILF;
    }
    ch[NB] = TAILF;
    float in_ch = ch[t];
    float in_h  = ch[t + 1] - ch[t];

    float d0 = 1.0f, d1 = 1.0f;
    if (t > 0)      d0 = MDF + softplusf(__half2float(pp[(size_t)(2*NB + t - 1) * HW_]));
    if (t < NB - 1) d1 = MDF + softplusf(__half2float(pp[(size_t)(2*NB + t) * HW_]));

    float delta = in_h / in_w;
    float th  = (xin - in_cw) / in_w;
    float tom = th * (1.f - th);
    float numer = in_h * (delta * th * th + d0 * tom);
    float denom = delta + (d0 + d1 - 2.f * delta) * tom;
    float yv = in_ch + numer / denom;
    float omt = 1.f - th;
    float dnum = delta * delta * (d1 * th * th + 2.f * delta * tom + d0 * omt * omt);
    float lad = __logf(dnum) - 2.f * __logf(denom);

    y[i] = inside ? yv : xv;

    // fused deterministic block partial sum of lad
    __shared__ double sm[256];
    sm[threadIdx.x] = inside ? (double)lad : 0.0;
    __syncthreads();
    for (int st = 128; st > 0; st >>= 1) {
        if (threadIdx.x < st) sm[threadIdx.x] += sm[threadIdx.x + st];
        __syncthreads();
    }
    if (threadIdx.x == 0) g_psum[b * PBLK + blk] = sm[0];
}

__global__ void logdet_reduce(const float* __restrict__ logdet, float* __restrict__ out)
{
    int b = blockIdx.x;
    double s = (threadIdx.x < PBLK) ? g_psum[b * PBLK + threadIdx.x] : 0.0;
    __shared__ double sm[256];
    sm[threadIdx.x] = s;
    __syncthreads();
    for (int st = 128; st > 0; st >>= 1) {
        if (threadIdx.x < st) sm[threadIdx.x] += sm[threadIdx.x + st];
        __syncthreads();
    }
    if (threadIdx.x == 0) out[b] = logdet[b] + (float)sm[0];
}

// ---------------- launch ----------------
extern "C" void kernel_launch(void* const* d_in, const int* in_sizes, int n_in,
                              void* d_out, int out_size)
{
    const float* x    = (const float*)d_in[0];
    const float* ld   = (const float*)d_in[1];
    const float* cond = (const float*)d_in[2];
    const float* w1   = (const float*)d_in[3];
    const float* b1   = (const float*)d_in[4];
    const float* w2   = (const float*)d_in[5];
    const float* b2   = (const float*)d_in[6];
    const float* w3   = (const float*)d_in[7];
    const float* b3   = (const float*)d_in[8];
    float* out = (float*)d_out;

    __half *p_pad1, *p_pad3, *p_w1, *p_w2, *p_w3, *p_params;
    cudaGetSymbolAddress((void**)&p_pad1, g_pad1);
    cudaGetSymbolAddress((void**)&p_pad3, g_pad3);
    cudaGetSymbolAddress((void**)&p_w1, g_w1h);
    cudaGetSymbolAddress((void**)&p_w2, g_w2h);
    cudaGetSymbolAddress((void**)&p_w3, g_w3h);
    cudaGetSymbolAddress((void**)&p_params, g_params);

    // h2 (fp16, 33MB) aliases the head of g_params (72MB): consumed by pad3
    // strictly before conv3 writes params. Safe ordering on one stream.
    __half* p_h2 = p_params;

    cudaFuncSetAttribute((const void*)fused_conv12,
                         cudaFuncAttributeMaxDynamicSharedMemorySize, FUSED_SMEM);
    cudaFuncSetAttribute((const void*)conv_gemm<2, OUTS, 128, 7, 1152>,
                         cudaFuncAttributeMaxDynamicSharedMemorySize, CONV_SMEM);
    cudaFuncSetAttribute((const void*)conv_gemm<1, OUTS, 128, 7, 1152>,
                         cudaFuncAttributeMaxDynamicSharedMemorySize, CONV_SMEM);

    {
        const int NW = 128*192 + 128*128 + 384*1152;
        prep_weights<<<(NW + 255) / 256, 256>>>(w1, w2, w3);
    }
    {
        const int N = 3 * BB * 16 * 66 * 32;
        pad1_kernel<<<(N + 255) / 256, 256>>>(x, cond);
    }
    fused_conv12<<<dim3(32, 1, BB), 256, FUSED_SMEM>>>(p_pad1, p_w1, p_w2, b1, b2, p_h2);
    pad3_kernel<<<BB * HID, 256>>>(p_h2);
    // main: oc 0..255 with M=128 tiles; tail: oc 256..275 with one M=64 tile row
    conv_gemm<2, OUTS, 128, 7, 1152><<<dim3(32, 2, BB), 256, CONV_SMEM>>>(p_pad3, p_w3, b3, p_params, 0);
    conv_gemm<1, OUTS, 128, 7, 1152><<<dim3(32, 1, BB), 256, CONV_SMEM>>>(p_pad3, p_w3, b3, p_params, 256);
    rqs_kernel<<<dim3(PBLK, BB), 256>>>(x, out);
    logdet_reduce<<<BB, 256>>>(ld, out + NTOT);
}

// round 17
// speedup vs baseline: 1.3159x; 1.0038x over previous
#include <cuda_runtime.h>
#include <cuda_fp16.h>
#include <math.h>
#include <cstdint>

// Problem constants
#define BB    32
#define CC    12
#define HH_   64
#define WW_   64
#define HW_   4096
#define HID   128
#define CONDC 4
#define OUTS  276          // 12 * 23
#define NB    8
#define TAILF 3.0f
#define MBWF  0.001f
#define MBHF  0.001f
#define MDF   0.001f
#define NTOT  (BB*CC*HW_)  // 1572864
#define PERB  (CC*HW_)     // 49152
#define PAREA (66*64)      // padded channel area (66 rows x 64 cols)
#define PBLK  192          // rqs partial-sum blocks per batch (PERB/256)

// ---------------- scratch (no cudaMalloc allowed) ----------------
__device__ __half g_pad1[(size_t)3*BB*16*PAREA];     // 13 MB
__device__ __half g_pad3[(size_t)3*BB*HID*PAREA];    // 104 MB
__device__ __half g_w1h[128 * 192];
__device__ __half g_w2h[128 * 128];
__device__ __half g_w3h[384 * 1152];
__device__ __half g_params[(size_t)BB*OUTS*HW_];      // 72 MB (fp16 logits)
__device__ double g_psum[BB * PBLK];

// ---------------- helpers ----------------
__device__ __forceinline__ uint32_t smem_u32(const void* p) {
    uint32_t a;
    asm("{ .reg .u64 t; cvta.to.shared.u64 t, %1; cvt.u32.u64 %0, t; }" : "=r"(a) : "l"(p));
    return a;
}
__device__ __forceinline__ uint32_t h2_bits(__half2 h) {
    uint32_t u;
    memcpy(&u, &h, 4);
    return u;
}
__device__ __forceinline__ void cp_async16(uint32_t dst, const void* src) {
    asm volatile("cp.async.cg.shared.global [%0], [%1], 16;"
                 :: "r"(dst), "l"(src) : "memory");
}
__device__ __forceinline__ void cp_commit() {
    asm volatile("cp.async.commit_group;" ::: "memory");
}
template<int N>
__device__ __forceinline__ void cp_wait() {
    asm volatile("cp.async.wait_group %0;" :: "n"(N) : "memory");
}
__device__ __forceinline__ void ldsm_x4(uint32_t r[4], uint32_t addr) {
    asm volatile("ldmatrix.sync.aligned.m8n8.x4.shared.b16 {%0,%1,%2,%3}, [%4];"
        : "=r"(r[0]), "=r"(r[1]), "=r"(r[2]), "=r"(r[3]) : "r"(addr));
}
__device__ __forceinline__ void ldsm_x4t(uint32_t r[4], uint32_t addr) {
    asm volatile("ldmatrix.sync.aligned.m8n8.x4.trans.shared.b16 {%0,%1,%2,%3}, [%4];"
        : "=r"(r[0]), "=r"(r[1]), "=r"(r[2]), "=r"(r[3]) : "r"(addr));
}
__device__ __forceinline__ void sts32(uint32_t addr, uint32_t v) {
    asm volatile("st.shared.u32 [%0], %1;" :: "r"(addr), "r"(v) : "memory");
}
__device__ __forceinline__ void mma_f16(float c[4], const uint32_t a[4],
                                        uint32_t b0, uint32_t b1) {
    asm volatile(
        "mma.sync.aligned.m16n8k16.row.col.f32.f16.f16.f32 "
        "{%0,%1,%2,%3}, {%4,%5,%6,%7}, {%8,%9}, {%0,%1,%2,%3};"
        : "+f"(c[0]), "+f"(c[1]), "+f"(c[2]), "+f"(c[3])
        : "r"(a[0]), "r"(a[1]), "r"(a[2]), "r"(a[3]), "r"(b0), "r"(b1));
}

// A tile: rows x 32 k halves (64B rows), 16B granules XORed by (row>>1)&3
__device__ __forceinline__ uint32_t a_addr(uint32_t base, int row, int kg) {
    return base + row * 64 + ((kg ^ ((row >> 1) & 3)) << 4);
}
// B tile (N=128): 32 k-rows x 128 n halves (256B rows, 16 granules), XOR (krow&7)
__device__ __forceinline__ uint32_t b_addr(uint32_t base, int krow, int g) {
    return base + krow * 256 + ((g ^ (krow & 7)) << 4);
}
// B tile (N=256): 32 k-rows x 256 n halves (512B rows, 32 granules), XOR (krow&7)
__device__ __forceinline__ uint32_t b2_addr(uint32_t base, int krow, int g) {
    return base + krow * 512 + ((g ^ (krow & 7)) << 4);
}

#define A_BYTES     (128 * 64)            // 8 KB
#define B_BYTES     (32 * 256)            // 8 KB
#define STAGE_BYTES (A_BYTES + B_BYTES)   // 16 KB
#define NSTG        6
#define CONV_SMEM   (NSTG * STAGE_BYTES)  // 96 KB -> 2 CTAs/SM

// tail conv: M=64 x N=256. stage = A(64x64B=4KB) + B(32x512B=16KB) = 20 KB; 4 stages.
#define T_A_BYTES   (64 * 64)
#define T_B_BYTES   (32 * 512)
#define T_STAGE     (T_A_BYTES + T_B_BYTES)
#define T_NSTG      4
#define TAIL_SMEM   (T_NSTG * T_STAGE)    // 80 KB -> 2 CTAs/SM

// fused conv1+conv2 smem: 4-stage ring (64 KB) + h1 B-layout area (32 KB)
#define F_NSTG      4
#define F_RING      (F_NSTG * STAGE_BYTES)     // 64 KB
#define FUSED_SMEM  (F_RING + 4 * B_BYTES)     // 96 KB -> 2 CTAs/SM

// ---------------- weight reorder (tap-major, zero-padded, fp16) ----------------
__global__ void prep_weights(const float* __restrict__ w1, const float* __restrict__ w2,
                             const float* __restrict__ w3) {
    const int N1 = 128 * 192, N2 = 128 * 128, N3 = 384 * 1152;
    int i = blockIdx.x * blockDim.x + threadIdx.x;
    if (i < N1) {
        int oc = i / 192, k = i - oc * 192;
        int t = k >> 4, ch = k & 15;
        g_w1h[i] = __float2half((t < 9) ? w1[oc * 144 + ch * 9 + t] : 0.f);
    } else if (i < N1 + N2) {
        int j = i - N1;
        g_w2h[j] = __float2half(w2[j]);
    } else if (i < N1 + N2 + N3) {
        int j = i - N1 - N2;
        int oc = j / 1152, k = j - oc * 1152;
        int t = k >> 7, ch = k & 127;
        g_w3h[j] = __float2half((oc < OUTS) ? w3[oc * 1152 + ch * 9 + t] : 0.f);
    }
}

// ---------------- padded dw-replicated input builders ----------------
// P[dw][b][ch][r 0..65][w 0..63] = in[ch][r-1][w+dw-1] (0 if OOB)
__global__ void pad1_kernel(const float* __restrict__ x, const float* __restrict__ cond) {
    const int N = 3 * BB * 16 * 66 * 32;
    int i = blockIdx.x * blockDim.x + threadIdx.x;
    if (i >= N) return;
    int w2 = i & 31;           int tmp = i >> 5;
    int r  = tmp % 66;         tmp /= 66;
    int ch = tmp & 15;         tmp >>= 4;
    int b  = tmp & 31;         int dw = tmp >> 5;
    int rr = r - 1;
    const float* src = (ch < CC) ? (x    + ((size_t)b * CC    + ch)        * HW_)
                                 : (cond + ((size_t)b * CONDC + (ch - CC)) * HW_);
    float v0 = 0.f, v1 = 0.f;
    if ((unsigned)rr < 64u) {
        int w = w2 * 2;
        int ww0 = w + dw - 1, ww1 = ww0 + 1;
        if ((unsigned)ww0 < 64u) v0 = src[rr * 64 + ww0];
        if ((unsigned)ww1 < 64u) v1 = src[rr * 64 + ww1];
    }
    __half2* dst = reinterpret_cast<__half2*>(
        g_pad1 + (((size_t)(dw * BB + b) * 16 + ch) * PAREA) + r * 64);
    dst[w2] = __floats2half2_rn(v0, v1);
}

// Plane-parallel vectorized pad3: one block per (b,ch) plane.
__global__ __launch_bounds__(256)
void pad3_kernel(const __half* __restrict__ h2) {
    const int plane = blockIdx.x;                  // b*HID + ch, 0..4095
    const __half* src = h2 + (size_t)plane * HW_;
    __half* dst0 = g_pad3 + (size_t)plane * PAREA;                       // dw=0
    __half* dst1 = dst0 + (size_t)BB * HID * PAREA;                      // dw=1
    __half* dst2 = dst1 + (size_t)BB * HID * PAREA;                      // dw=2
    const int tid = threadIdx.x;

    if (tid < 48) {
        int d = tid / 16;
        int rq = tid & 15;
        int r = (rq >> 3) ? 65 : 0;
        int q = rq & 7;
        __half* dp = (d == 0) ? dst0 : (d == 1) ? dst1 : dst2;
        *reinterpret_cast<uint4*>(dp + r * 64 + q * 8) = make_uint4(0, 0, 0, 0);
    }

    #pragma unroll
    for (int u = tid; u < 512; u += 256) {
        const int r = u >> 3;
        const int q = u & 7;
        const __half* s = src + r * 64 + q * 8;
        uint4 v = *reinterpret_cast<const uint4*>(s);
        uint32_t left  = (q == 0) ? 0u : (uint32_t)__half_as_ushort(s[-1]);
        uint32_t right = (q == 7) ? 0u : (uint32_t)__half_as_ushort(s[8]);

        *reinterpret_cast<uint4*>(dst1 + (r + 1) * 64 + q * 8) = v;

        uint4 a;
        a.x = (v.x << 16) | left;
        a.y = (v.y << 16) | (v.x >> 16);
        a.z = (v.z << 16) | (v.y >> 16);
        a.w = (v.w << 16) | (v.z >> 16);
        *reinterpret_cast<uint4*>(dst0 + (r + 1) * 64 + q * 8) = a;

        uint4 c;
        c.x = (v.x >> 16) | (v.y << 16);
        c.y = (v.y >> 16) | (v.z << 16);
        c.z = (v.z >> 16) | (v.w << 16);
        c.w = (v.w >> 16) | (right << 16);
        *reinterpret_cast<uint4*>(dst2 + (r + 1) * 64 + q * 8) = c;
    }
}

// ---------------- fused conv1 (3x3, 16->128) + conv2 (1x1, 128->128) ----------------
__global__ __launch_bounds__(256, 2)
void fused_conv12(const __half* __restrict__ in, const __half* __restrict__ w1,
                  const __half* __restrict__ w2, const float* __restrict__ bias1,
                  const float* __restrict__ bias2, __half* __restrict__ h2out)
{
    constexpr int NC1 = 6;      // K=192 / 32
    extern __shared__ char smemc[];
    const uint32_t stg  = smem_u32(smemc);
    const uint32_t h1b  = stg + F_RING;

    const int tid  = threadIdx.x;
    const int lane = tid & 31;
    const int wid  = tid >> 5;
    const int wm   = (wid & 3) * 32;
    const int wn   = (wid >> 2) * 64;

    const int b    = blockIdx.z;
    const int h0   = blockIdx.x * 2;
    const int pix0 = blockIdx.x * 128;

    const int a_row0 = tid >> 1;
    const int a_kg0  = (tid & 1) * 2;
    const int b_krow = tid >> 3;
    const int b_g0   = (tid & 7) * 2;
    const int b_orow = b_g0 >> 3;

    auto issue_stage1 = [&](int c) {
        if (c < NC1) {
            const uint32_t sA = stg + (c % F_NSTG) * STAGE_BYTES;
            const uint32_t sB = sA + A_BYTES;
            const __half* asrc = w1 + (size_t)a_row0 * 192 + c * 32 + a_kg0 * 8;
            cp_async16(a_addr(sA, a_row0, a_kg0), asrc);
            cp_async16(a_addr(sA, a_row0, a_kg0 + 1), asrc + 8);
            const int kk = c * 32 + b_krow;
            int t9 = kk >> 4;
            if (t9 > 8) t9 = 8;                  // pad region: weights are zero
            const int ch = kk & 15;
            const int dh = t9 / 3, dw = t9 - dh * 3;
            const __half* bsrc = in + (((size_t)(dw * BB + b) * 16 + ch) * PAREA)
                                    + (size_t)(h0 + b_orow + dh) * 64 + (b_g0 & 7) * 8;
            cp_async16(b_addr(sB, b_krow, b_g0), bsrc);
            cp_async16(b_addr(sB, b_krow, b_g0 + 1), bsrc + 8);
        }
        cp_commit();
    };

    float acc[2][8][4];
    #pragma unroll
    for (int mt = 0; mt < 2; ++mt)
        #pragma unroll
        for (int nt = 0; nt < 8; ++nt)
            #pragma unroll
            for (int q = 0; q < 4; ++q) acc[mt][nt][q] = 0.f;

    issue_stage1(0);
    issue_stage1(1);
    issue_stage1(2);

    const int a_m  = (lane & 7) + ((lane >> 3) & 1) * 8;
    const int a_kg = lane >> 4;
    const int bl_k = ((lane >> 3) & 1) * 8 + (lane & 7);
    const int bl_g = lane >> 4;

    auto compute_chunk = [&](uint32_t sA, uint32_t sB) {
        #pragma unroll
        for (int ks = 0; ks < 2; ++ks) {
            uint32_t af[2][4];
            uint32_t bf[4][4];
            #pragma unroll
            for (int mt = 0; mt < 2; ++mt)
                ldsm_x4(af[mt], a_addr(sA, wm + mt * 16 + a_m, 2 * ks + a_kg));
            #pragma unroll
            for (int nt2 = 0; nt2 < 4; ++nt2)
                ldsm_x4t(bf[nt2], b_addr(sB, 16 * ks + bl_k, (wn >> 3) + nt2 * 2 + bl_g));
            #pragma unroll
            for (int nt2 = 0; nt2 < 4; ++nt2) {
                #pragma unroll
                for (int mt = 0; mt < 2; ++mt) {
                    mma_f16(acc[mt][nt2 * 2 + 0], af[mt], bf[nt2][0], bf[nt2][1]);
                    mma_f16(acc[mt][nt2 * 2 + 1], af[mt], bf[nt2][2], bf[nt2][3]);
                }
            }
        }
    };

    // ---- phase 1: conv1 K-loop ----
    for (int c = 0; c < NC1; ++c) {
        cp_wait<F_NSTG - 2>();
        __syncthreads();
        issue_stage1(c + F_NSTG - 1);
        const uint32_t sA = stg + (c % F_NSTG) * STAGE_BYTES;
        compute_chunk(sA, sA + A_BYTES);
    }
    __syncthreads();    // all warps done reading ring before it is reused

    // ---- h1 = relu(acc + b1) -> fp16 -> smem (B-tile layout, 4 k-chunks) ----
    const int g  = lane >> 2;
    const int tq = lane & 3;
    #pragma unroll
    for (int mt = 0; mt < 2; ++mt) {
        const int chl = wm + mt * 16 + g;
        const int chh = chl + 8;
        const float bl = bias1[chl];
        const float bh = bias1[chh];
        #pragma unroll
        for (int nt = 0; nt < 8; ++nt) {
            const int col = wn + nt * 8 + 2 * tq;
            float v0 = fmaxf(acc[mt][nt][0] + bl, 0.f);
            float v1 = fmaxf(acc[mt][nt][1] + bl, 0.f);
            float v2 = fmaxf(acc[mt][nt][2] + bh, 0.f);
            float v3 = fmaxf(acc[mt][nt][3] + bh, 0.f);
            uint32_t al = h1b + ((chl >> 5) << 13) + ((chl & 31) * 256)
                        + ((((col >> 3) ^ (chl & 7)) ) << 4) + ((col & 7) << 1);
            uint32_t ah = h1b + ((chh >> 5) << 13) + ((chh & 31) * 256)
                        + ((((col >> 3) ^ (chh & 7)) ) << 4) + ((col & 7) << 1);
            sts32(al, h2_bits(__floats2half2_rn(v0, v1)));
            sts32(ah, h2_bits(__floats2half2_rn(v2, v3)));
            acc[mt][nt][0] = 0.f; acc[mt][nt][1] = 0.f;
            acc[mt][nt][2] = 0.f; acc[mt][nt][3] = 0.f;
        }
    }

    // ---- phase 2: A = w2 tiles via cp.async into ring; B = h1 in smem ----
    #pragma unroll
    for (int s = 0; s < 4; ++s) {
        const uint32_t sA = stg + s * STAGE_BYTES;
        const __half* asrc = w2 + (size_t)a_row0 * 128 + s * 32 + a_kg0 * 8;
        cp_async16(a_addr(sA, a_row0, a_kg0), asrc);
        cp_async16(a_addr(sA, a_row0, a_kg0 + 1), asrc + 8);
        cp_commit();
    }
    cp_wait<0>();
    __syncthreads();    // h1 stores + w2 tiles visible to all warps

    #pragma unroll
    for (int c2 = 0; c2 < 4; ++c2)
        compute_chunk(stg + c2 * STAGE_BYTES, h1b + c2 * B_BYTES);

    // ---- epilogue: h2 = relu(acc + b2) -> fp16 gmem ----
    #pragma unroll
    for (int mt = 0; mt < 2; ++mt) {
        const int chl = wm + mt * 16 + g;
        const int chh = chl + 8;
        const float bl = bias2[chl];
        const float bh = bias2[chh];
        #pragma unroll
        for (int nt = 0; nt < 8; ++nt) {
            const int col = wn + nt * 8 + 2 * tq;
            float v0 = fmaxf(acc[mt][nt][0] + bl, 0.f);
            float v1 = fmaxf(acc[mt][nt][1] + bl, 0.f);
            float v2 = fmaxf(acc[mt][nt][2] + bh, 0.f);
            float v3 = fmaxf(acc[mt][nt][3] + bh, 0.f);
            *reinterpret_cast<__half2*>(h2out + ((size_t)b * HID + chl) * HW_ + pix0 + col) =
                __floats2half2_rn(v0, v1);
            *reinterpret_cast<__half2*>(h2out + ((size_t)b * HID + chh) * HW_ + pix0 + col) =
                __floats2half2_rn(v2, v3);
        }
    }
}

// ---------------- conv3 main: M=128 x N=128 (oc 0..255) ----------------
template<int COUT, int CIN, int CLOG, int KPAD>
__global__ __launch_bounds__(256, 2)
void conv_gemm(const __half* __restrict__ in, const __half* __restrict__ wgt,
               const float* __restrict__ bias, __half* __restrict__ outp)
{
    constexpr int NC = KPAD / 32;
    extern __shared__ char smemc[];
    const uint32_t stg = smem_u32(smemc);

    const int tid  = threadIdx.x;
    const int lane = tid & 31;
    const int wid  = tid >> 5;
    const int wm   = (wid & 3) * 32;
    const int wn   = (wid >> 2) * 64;

    const int b     = blockIdx.z;
    const int mbase = blockIdx.y * 128;
    const int h0    = blockIdx.x * 2;
    const int pix0  = blockIdx.x * 128;

    const int a_row0 = tid >> 1;
    const int a_kg0  = (tid & 1) * 2;
    const int b_krow = tid >> 3;
    const int b_g0   = (tid & 7) * 2;
    const int b_orow = b_g0 >> 3;

    auto issue_stage = [&](int c) {
        if (c < NC) {
            const uint32_t sA = stg + (c % NSTG) * STAGE_BYTES;
            const uint32_t sB = sA + A_BYTES;
            const __half* asrc = wgt + (size_t)(mbase + a_row0) * KPAD + c * 32 + a_kg0 * 8;
            cp_async16(a_addr(sA, a_row0, a_kg0), asrc);
            cp_async16(a_addr(sA, a_row0, a_kg0 + 1), asrc + 8);
            const int kk = c * 32 + b_krow;
            int t9 = kk >> CLOG;
            if (t9 > 8) t9 = 8;
            const int ch = kk & (CIN - 1);
            const int dh = t9 / 3, dw = t9 - dh * 3;
            const __half* bsrc = in + (((size_t)(dw * BB + b) * CIN + ch) * PAREA)
                                    + (size_t)(h0 + b_orow + dh) * 64 + (b_g0 & 7) * 8;
            cp_async16(b_addr(sB, b_krow, b_g0), bsrc);
            cp_async16(b_addr(sB, b_krow, b_g0 + 1), bsrc + 8);
        }
        cp_commit();
    };

    float acc[2][8][4];
    #pragma unroll
    for (int mt = 0; mt < 2; ++mt)
        #pragma unroll
        for (int nt = 0; nt < 8; ++nt)
            #pragma unroll
            for (int q = 0; q < 4; ++q) acc[mt][nt][q] = 0.f;

    #pragma unroll
    for (int s = 0; s < NSTG - 1; ++s) issue_stage(s);

    const int a_m  = (lane & 7) + ((lane >> 3) & 1) * 8;
    const int a_kg = lane >> 4;
    const int bl_k = ((lane >> 3) & 1) * 8 + (lane & 7);
    const int bl_g = lane >> 4;

    for (int c = 0; c < NC; ++c) {
        cp_wait<NSTG - 2>();
        __syncthreads();
        issue_stage(c + NSTG - 1);

        const uint32_t sA = stg + (c % NSTG) * STAGE_BYTES;
        const uint32_t sB = sA + A_BYTES;

        #pragma unroll
        for (int ks = 0; ks < 2; ++ks) {
            uint32_t af[2][4];
            uint32_t bf[4][4];
            #pragma unroll
            for (int mt = 0; mt < 2; ++mt)
                ldsm_x4(af[mt], a_addr(sA, wm + mt * 16 + a_m, 2 * ks + a_kg));
            #pragma unroll
            for (int nt2 = 0; nt2 < 4; ++nt2)
                ldsm_x4t(bf[nt2], b_addr(sB, 16 * ks + bl_k, (wn >> 3) + nt2 * 2 + bl_g));
            #pragma unroll
            for (int nt2 = 0; nt2 < 4; ++nt2) {
                #pragma unroll
                for (int mt = 0; mt < 2; ++mt) {
                    mma_f16(acc[mt][nt2 * 2 + 0], af[mt], bf[nt2][0], bf[nt2][1]);
                    mma_f16(acc[mt][nt2 * 2 + 1], af[mt], bf[nt2][2], bf[nt2][3]);
                }
            }
        }
    }

    // ---- epilogue (fp16 out) ----
    const int g  = lane >> 2;
    const int tq = lane & 3;
    #pragma unroll
    for (int mt = 0; mt < 2; ++mt) {
        const int ocl = mbase + wm + mt * 16 + g;
        const int och = ocl + 8;
        const float bl = bias[ocl];
        const float bh = bias[och];
        #pragma unroll
        for (int nt = 0; nt < 8; ++nt) {
            const int col = wn + nt * 8 + 2 * tq;
            float v0 = acc[mt][nt][0] + bl, v1 = acc[mt][nt][1] + bl;
            float v2 = acc[mt][nt][2] + bh, v3 = acc[mt][nt][3] + bh;
            *reinterpret_cast<__half2*>(outp + ((size_t)b * COUT + ocl) * HW_ + pix0 + col) =
                __floats2half2_rn(v0, v1);
            *reinterpret_cast<__half2*>(outp + ((size_t)b * COUT + och) * HW_ + pix0 + col) =
                __floats2half2_rn(v2, v3);
        }
    }
}

// ---------------- conv3 tail: M=64 x N=256 (oc 256..275 live) ----------------
template<int COUT, int CIN, int CLOG, int KPAD, int MOFF>
__global__ __launch_bounds__(256, 2)
void conv_tail(const __half* __restrict__ in, const __half* __restrict__ wgt,
               const float* __restrict__ bias, __half* __restrict__ outp)
{
    constexpr int NC = KPAD / 32;
    extern __shared__ char smemc[];
    const uint32_t stg = smem_u32(smemc);

    const int tid  = threadIdx.x;
    const int lane = tid & 31;
    const int wid  = tid >> 5;
    const int wm   = (wid & 3) * 16;          // 4 M-quarters of 16 rows
    const int wn   = (wid >> 2) * 128;        // 2 N-halves of 128 px

    const int b    = blockIdx.z;
    const int h0   = blockIdx.x * 4;          // 4 image rows = 256 px
    const int pix0 = blockIdx.x * 256;

    // A loader: 64 rows x 4 granules = 256, 1/thread
    const int a_row0 = tid >> 2;
    const int a_kg0  = tid & 3;
    // B loader: 32 krows x 32 granules = 1024, 4/thread (64B contiguous)
    const int b_krow = tid >> 3;
    const int b_q    = tid & 7;               // quarter-run: granules q*4..q*4+3
    const int b_orow = b_q >> 1;              // image row within tile (0..3)

    auto issue_stage = [&](int c) {
        if (c < NC) {
            const uint32_t sA = stg + (c % T_NSTG) * T_STAGE;
            const uint32_t sB = sA + T_A_BYTES;
            const __half* asrc = wgt + (size_t)(MOFF + a_row0) * KPAD + c * 32 + a_kg0 * 8;
            cp_async16(a_addr(sA, a_row0, a_kg0), asrc);
            const int kk = c * 32 + b_krow;
            int t9 = kk >> CLOG;
            if (t9 > 8) t9 = 8;
            const int ch = kk & (CIN - 1);
            const int dh = t9 / 3, dw = t9 - dh * 3;
            const __half* bsrc = in + (((size_t)(dw * BB + b) * CIN + ch) * PAREA)
                                    + (size_t)(h0 + b_orow + dh) * 64 + (b_q & 1) * 32;
            #pragma unroll
            for (int q = 0; q < 4; ++q)
                cp_async16(b2_addr(sB, b_krow, b_q * 4 + q), bsrc + q * 8);
        }
        cp_commit();
    };

    float acc[16][4];
    #pragma unroll
    for (int nt = 0; nt < 16; ++nt)
        #pragma unroll
        for (int q = 0; q < 4; ++q) acc[nt][q] = 0.f;

    #pragma unroll
    for (int s = 0; s < T_NSTG - 1; ++s) issue_stage(s);

    const int a_m  = (lane & 7) + ((lane >> 3) & 1) * 8;
    const int a_kg = lane >> 4;
    const int bl_k = ((lane >> 3) & 1) * 8 + (lane & 7);
    const int bl_g = lane >> 4;

    for (int c = 0; c < NC; ++c) {
        cp_wait<T_NSTG - 2>();
        __syncthreads();
        issue_stage(c + T_NSTG - 1);

        const uint32_t sA = stg + (c % T_NSTG) * T_STAGE;
        const uint32_t sB = sA + T_A_BYTES;

        #pragma unroll
        for (int ks = 0; ks < 2; ++ks) {
            uint32_t af[4];
            ldsm_x4(af, a_addr(sA, wm + a_m, 2 * ks + a_kg));
            #pragma unroll
            for (int grp = 0; grp < 2; ++grp) {
                uint32_t bf[4][4];
                #pragma unroll
                for (int j = 0; j < 4; ++j) {
                    const int nt2 = grp * 4 + j;
                    ldsm_x4t(bf[j], b2_addr(sB, 16 * ks + bl_k, (wn >> 3) + nt2 * 2 + bl_g));
                }
                #pragma unroll
                for (int j = 0; j < 4; ++j) {
                    const int nt2 = grp * 4 + j;
                    mma_f16(acc[nt2 * 2 + 0], af, bf[j][0], bf[j][1]);
                    mma_f16(acc[nt2 * 2 + 1], af, bf[j][2], bf[j][3]);
                }
            }
        }
    }

    // ---- epilogue (fp16 out, guarded: oc 256..319 but COUT=276) ----
    const int g  = lane >> 2;
    const int tq = lane & 3;
    const int ocl = MOFF + wm + g;
    const int och = ocl + 8;
    const float bl = (ocl < COUT) ? bias[ocl] : 0.f;
    const float bh = (och < COUT) ? bias[och] : 0.f;
    #pragma unroll
    for (int nt = 0; nt < 16; ++nt) {
        const int col = wn + nt * 8 + 2 * tq;
        float v0 = acc[nt][0] + bl, v1 = acc[nt][1] + bl;
        float v2 = acc[nt][2] + bh, v3 = acc[nt][3] + bh;
        if (ocl < COUT)
            *reinterpret_cast<__half2*>(outp + ((size_t)b * COUT + ocl) * HW_ + pix0 + col) =
                __floats2half2_rn(v0, v1);
        if (och < COUT)
            *reinterpret_cast<__half2*>(outp + ((size_t)b * COUT + och) * HW_ + pix0 + col) =
                __floats2half2_rn(v2, v3);
    }
}

// ---------------- RQS pointwise transform + fused partial logdet ----------------
__device__ __forceinline__ float softplusf(float v) {
    return (v > 20.f) ? v : __logf(1.f + __expf(v));
}

__global__ void rqs_kernel(const float* __restrict__ x, float* __restrict__ y)
{
    const int b   = blockIdx.y;
    const int blk = blockIdx.x;                       // 0..PBLK-1
    const int i   = b * PERB + blk * 256 + threadIdx.x;
    const int hw  = i & (HW_ - 1);
    const int c   = (i >> 12) % CC;
    const __half* pp = g_params + (((size_t)b * OUTS + c * 23) * HW_) + hw;

    float xv = x[i];
    bool inside = (xv >= -TAILF) && (xv <= TAILF);
    float xin = fminf(fmaxf(xv, -TAILF), TAILF);

    float u[NB];
    float mx = -1e30f;
    #pragma unroll
    for (int j = 0; j < NB; ++j) { u[j] = __half2float(pp[(size_t)j * HW_]); mx = fmaxf(mx, u[j]); }
    float se = 0.f;
    #pragma unroll
    for (int j = 0; j < NB; ++j) { u[j] = __expf(u[j] - mx); se += u[j]; }
    float inv = 1.f / se;
    float cw[NB + 1];
    cw[0] = -TAILF;
    float cs = 0.f;
    #pragma unroll
    for (int k = 0; k < NB; ++k) {
        cs += MBWF + (1.f - MBWF * NB) * (u[k] * inv);
        cw[k + 1] = 2.f * TAILF * cs - TAILF;
    }
    cw[NB] = TAILF;

    int t = 0;
    #pragma unroll
    for (int k = 1; k < NB; ++k) t += (xin >= cw[k]) ? 1 : 0;
    float in_cw = cw[t];
    float in_w  = cw[t + 1] - cw[t];

    mx = -1e30f;
    #pragma unroll
    for (int j = 0; j < NB; ++j) { u[j] = __half2float(pp[(size_t)(NB + j) * HW_]); mx = fmaxf(mx, u[j]); }
    se = 0.f;
    #pragma unroll
    for (int j = 0; j < NB; ++j) { u[j] = __expf(u[j] - mx); se += u[j]; }
    inv = 1.f / se;
    float ch[NB + 1];
    ch[0] = -TAILF;
    cs = 0.f;
    #pragma unroll
    for (int k = 0; k < NB; ++k) {
        cs += MBHF + (1.f - MBHF * NB) * (u[k] * inv);
        ch[k + 1] = 2.f * TAILF * cs - TAILF;
    }
    ch[NB] = TAILF;
    float in_ch = ch[t];
    float in_h  = ch[t + 1] - ch[t];

    float d0 = 1.0f, d1 = 1.0f;
    if (t > 0)      d0 = MDF + softplusf(__half2float(pp[(size_t)(2*NB + t - 1) * HW_]));
    if (t < NB - 1) d1 = MDF + softplusf(__half2float(pp[(size_t)(2*NB + t) * HW_]));

    float delta = in_h / in_w;
    float th  = (xin - in_cw) / in_w;
    float tom = th * (1.f - th);
    float numer = in_h * (delta * th * th + d0 * tom);
    float denom = delta + (d0 + d1 - 2.f * delta) * tom;
    float yv = in_ch + numer / denom;
    float omt = 1.f - th;
    float dnum = delta * delta * (d1 * th * th + 2.f * delta * tom + d0 * omt * omt);
    float lad = __logf(dnum) - 2.f * __logf(denom);

    y[i] = inside ? yv : xv;

    // fused deterministic block partial sum of lad
    __shared__ double sm[256];
    sm[threadIdx.x] = inside ? (double)lad : 0.0;
    __syncthreads();
    for (int st = 128; st > 0; st >>= 1) {
        if (threadIdx.x < st) sm[threadIdx.x] += sm[threadIdx.x + st];
        __syncthreads();
    }
    if (threadIdx.x == 0) g_psum[b * PBLK + blk] = sm[0];
}

__global__ void logdet_reduce(const float* __restrict__ logdet, float* __restrict__ out)
{
    int b = blockIdx.x;
    double s = (threadIdx.x < PBLK) ? g_psum[b * PBLK + threadIdx.x] : 0.0;
    __shared__ double sm[256];
    sm[threadIdx.x] = s;
    __syncthreads();
    for (int st = 128; st > 0; st >>= 1) {
        if (threadIdx.x < st) sm[threadIdx.x] += sm[threadIdx.x + st];
        __syncthreads();
    }
    if (threadIdx.x == 0) out[b] = logdet[b] + (float)sm[0];
}

// ---------------- launch ----------------
extern "C" void kernel_launch(void* const* d_in, const int* in_sizes, int n_in,
                              void* d_out, int out_size)
{
    const float* x    = (const float*)d_in[0];
    const float* ld   = (const float*)d_in[1];
    const float* cond = (const float*)d_in[2];
    const float* w1   = (const float*)d_in[3];
    const float* b1   = (const float*)d_in[4];
    const float* w2   = (const float*)d_in[5];
    const float* b2   = (const float*)d_in[6];
    const float* w3   = (const float*)d_in[7];
    const float* b3   = (const float*)d_in[8];
    float* out = (float*)d_out;

    __half *p_pad1, *p_pad3, *p_w1, *p_w2, *p_w3, *p_params;
    cudaGetSymbolAddress((void**)&p_pad1, g_pad1);
    cudaGetSymbolAddress((void**)&p_pad3, g_pad3);
    cudaGetSymbolAddress((void**)&p_w1, g_w1h);
    cudaGetSymbolAddress((void**)&p_w2, g_w2h);
    cudaGetSymbolAddress((void**)&p_w3, g_w3h);
    cudaGetSymbolAddress((void**)&p_params, g_params);

    // h2 (fp16, 33MB) aliases the head of g_params (72MB): consumed by pad3
    // strictly before conv3 writes params. Safe ordering on one stream.
    __half* p_h2 = p_params;

    cudaFuncSetAttribute((const void*)fused_conv12,
                         cudaFuncAttributeMaxDynamicSharedMemorySize, FUSED_SMEM);
    cudaFuncSetAttribute((const void*)conv_gemm<OUTS, 128, 7, 1152>,
                         cudaFuncAttributeMaxDynamicSharedMemorySize, CONV_SMEM);
    cudaFuncSetAttribute((const void*)conv_tail<OUTS, 128, 7, 1152, 256>,
                         cudaFuncAttributeMaxDynamicSharedMemorySize, TAIL_SMEM);

    {
        const int NW = 128*192 + 128*128 + 384*1152;
        prep_weights<<<(NW + 255) / 256, 256>>>(w1, w2, w3);
    }
    {
        const int N = 3 * BB * 16 * 66 * 32;
        pad1_kernel<<<(N + 255) / 256, 256>>>(x, cond);
    }
    fused_conv12<<<dim3(32, 1, BB), 256, FUSED_SMEM>>>(p_pad1, p_w1, p_w2, b1, b2, p_h2);
    pad3_kernel<<<BB * HID, 256>>>(p_h2);
    // main: oc 0..255 with M=128 x N=128 tiles; tail: oc 256..319 with M=64 x N=256
    conv_gemm<OUTS, 128, 7, 1152><<<dim3(32, 2, BB), 256, CONV_SMEM>>>(p_pad3, p_w3, b3, p_params);
    conv_tail<OUTS, 128, 7, 1152, 256><<<dim3(16, 1, BB), 256, TAIL_SMEM>>>(p_pad3, p_w3, b3, p_params);
    rqs_kernel<<<dim3(PBLK, BB), 256>>>(x, out);
    logdet_reduce<<<BB, 256>>>(ld, out + NTOT);
}